// round 2
// baseline (speedup 1.0000x reference)
#include <cuda_runtime.h>
#include <math.h>

#define D 512
#define NROWS 65536
#define MATN (D*D)
#define NS_ITERS 5
#define BARY_ITERS 50
#define SPLITS 32
#define CHUNK (NROWS/SPLITS)
#define NCTA 144

// ---------------- matrix buffer ids ----------------
enum {
  COVC=0, COVS, SIGB, BYA, BZA, BYB, BZB, BW0,
  BP0, BP1, BM0, BM1,
  YJ0A, YJ1A, ZJ0A, ZJ1A, YJ0B, YJ1B, ZJ0B, ZJ1B, WJ0, WJ1,
  BR0, BR1, BT0, BT1, NBUF
};

__device__ float g_mat[NBUF][MATN];
__device__ float g_covpart[SPLITS][MATN];
__device__ float g_meanpart[256][D];
__device__ float g_mean[3][D];              // 0: mu_c, 1: mu_s, 2: mu_bary
__device__ float g_scal[16];

// ---------------- grid-wide barrier (persistent kernel) ----------------
__device__ unsigned g_bar_cnt;
__device__ volatile unsigned g_bar_gen;

__device__ __forceinline__ void gridsync() {
    __syncthreads();
    if (threadIdx.x == 0) {
        __threadfence();
        unsigned gen = g_bar_gen;
        if (atomicAdd(&g_bar_cnt, 1u) == NCTA - 1u) {
            g_bar_cnt = 0u;
            __threadfence();
            g_bar_gen = gen + 1u;
        } else {
            while (g_bar_gen == gen) { }
        }
        __threadfence();
    }
    __syncthreads();
}

// ---------------- column means ----------------
__global__ void colsum1_k(const float* __restrict__ x) {
    int cta = blockIdx.x, t = threadIdx.x;
    const float* base = x + (size_t)cta * 256 * D;
    float s0 = 0.f, s1 = 0.f;
    for (int r = 0; r < 256; r++) {
        s0 += base[(size_t)r * D + t];
        s1 += base[(size_t)r * D + t + 256];
    }
    g_meanpart[cta][t] = s0;
    g_meanpart[cta][t + 256] = s1;
}

__global__ void colsum2_k(int which) {
    int t = threadIdx.x;
    float s = 0.f;
    for (int i = 0; i < 256; i++) s += g_meanpart[i][t];
    g_mean[which][t] = s * (1.0f / NROWS);
}

__global__ void mub_k() {
    int t = threadIdx.x;
    g_mean[2][t] = 0.5f * (g_mean[0][t] + g_mean[1][t]);
}

// ---------------- x^T x split-K partials (upper tile triangle) ----------
__global__ __launch_bounds__(256) void xtx_k(const float* __restrict__ x) {
    if (blockIdx.y > blockIdx.x) return;
    __shared__ float As[16][68];
    __shared__ float Bs[16][68];
    int tid = threadIdx.x;
    int tx = tid & 15, ty = tid >> 4;
    int j1 = blockIdx.y * 64, j2 = blockIdx.x * 64;
    int lc = (tid & 15) * 4, lr = tid >> 4;
    size_t r0 = (size_t)blockIdx.z * CHUNK;
    float acc[4][4] = {};
    for (int k0 = 0; k0 < CHUNK; k0 += 16) {
        const float* xr = x + (r0 + k0 + lr) * D;
        *(float4*)&As[lr][lc] = *(const float4*)&xr[j1 + lc];
        *(float4*)&Bs[lr][lc] = *(const float4*)&xr[j2 + lc];
        __syncthreads();
        #pragma unroll
        for (int k = 0; k < 16; k++) {
            float4 a = *(const float4*)&As[k][ty * 4];
            float4 b = *(const float4*)&Bs[k][tx * 4];
            float av[4] = {a.x, a.y, a.z, a.w};
            float bv[4] = {b.x, b.y, b.z, b.w};
            #pragma unroll
            for (int i = 0; i < 4; i++)
                #pragma unroll
                for (int j = 0; j < 4; j++)
                    acc[i][j] += av[i] * bv[j];
        }
        __syncthreads();
    }
    float* Cp = g_covpart[blockIdx.z];
    #pragma unroll
    for (int i = 0; i < 4; i++) {
        int m = j1 + ty * 4 + i, n = j2 + tx * 4;
        float4 o = make_float4(acc[i][0], acc[i][1], acc[i][2], acc[i][3]);
        *(float4*)&Cp[m * D + n] = o;
    }
}

__global__ void covfin_k(int covIdx, int meanIdx) {
    int idx = blockIdx.x * 256 + threadIdx.x;
    int m = idx >> 9, n = idx & 511;
    int ms = m, ns = n;
    if ((m >> 6) > (n >> 6)) { ms = n; ns = m; }
    float s = 0.f;
    #pragma unroll 8
    for (int p = 0; p < SPLITS; p++) s += g_covpart[p][ms * D + ns];
    float v = (s - (float)NROWS * g_mean[meanIdx][m] * g_mean[meanIdx][n])
              * (1.0f / (NROWS - 1));
    g_mat[covIdx][idx] = v;
}

// ---------------- tile GEMM (device fn, 64x64 tile, optional mirror) -----
__device__ __noinline__ void tile_gemm(const float* __restrict__ A,
                                       const float* __restrict__ B,
                                       float* __restrict__ C,
                                       int m0, int n0,
                                       float alpha, float betaI, int mirror) {
    __shared__ float As[32 * 68];
    __shared__ float Bs[32 * 68];
    int tid = threadIdx.x;
    int tx = tid & 15, ty = tid >> 4;
    int acol = (tid & 7) * 4, arow = tid >> 3;
    int bcol = (tid & 15) * 4, brow = tid >> 4;
    float acc[4][4] = {};
    for (int k0 = 0; k0 < D; k0 += 32) {
        __syncthreads();
        #pragma unroll
        for (int p = 0; p < 2; p++) {
            int m = arow + p * 32;
            float4 v = *(const float4*)&A[(size_t)(m0 + m) * D + k0 + acol];
            As[(acol + 0) * 68 + m] = v.x; As[(acol + 1) * 68 + m] = v.y;
            As[(acol + 2) * 68 + m] = v.z; As[(acol + 3) * 68 + m] = v.w;
        }
        #pragma unroll
        for (int p = 0; p < 2; p++) {
            int k = brow + p * 16;
            *(float4*)&Bs[k * 68 + bcol] = *(const float4*)&B[(size_t)(k0 + k) * D + n0 + bcol];
        }
        __syncthreads();
        #pragma unroll
        for (int k = 0; k < 32; k++) {
            float4 a = *(const float4*)&As[k * 68 + ty * 4];
            float4 b = *(const float4*)&Bs[k * 68 + tx * 4];
            float av[4] = {a.x, a.y, a.z, a.w};
            float bv[4] = {b.x, b.y, b.z, b.w};
            #pragma unroll
            for (int i = 0; i < 4; i++)
                #pragma unroll
                for (int j = 0; j < 4; j++)
                    acc[i][j] += av[i] * bv[j];
        }
    }
    float val[4][4];
    #pragma unroll
    for (int i = 0; i < 4; i++)
        #pragma unroll
        for (int j = 0; j < 4; j++)
            val[i][j] = alpha * acc[i][j];
    #pragma unroll
    for (int i = 0; i < 4; i++) {
        int m = m0 + ty * 4 + i, n = n0 + tx * 4;
        float4 o;
        o.x = val[i][0] + (m == n + 0 ? betaI : 0.f);
        o.y = val[i][1] + (m == n + 1 ? betaI : 0.f);
        o.z = val[i][2] + (m == n + 2 ? betaI : 0.f);
        o.w = val[i][3] + (m == n + 3 ? betaI : 0.f);
        *(float4*)&C[(size_t)m * D + n] = o;
    }
    if (mirror) {
        // stage transposed tile through smem, write to C[nTile, mTile]
        __syncthreads();
        #pragma unroll
        for (int i = 0; i < 4; i++)
            #pragma unroll
            for (int j = 0; j < 4; j++) {
                int r = ty * 4 + i, c2 = tx * 4 + j;
                if (r < 32) As[r * 68 + c2] = val[i][j];
                else        Bs[(r - 32) * 68 + c2] = val[i][j];
            }
        __syncthreads();
        #pragma unroll
        for (int i = 0; i < 4; i++) {
            int cc = ty * 4 + i;
            int r0 = tx * 4;
            float4 o;
            if (r0 < 32) {
                o.x = As[(r0 + 0) * 68 + cc]; o.y = As[(r0 + 1) * 68 + cc];
                o.z = As[(r0 + 2) * 68 + cc]; o.w = As[(r0 + 3) * 68 + cc];
            } else {
                o.x = Bs[(r0 - 32 + 0) * 68 + cc]; o.y = Bs[(r0 - 32 + 1) * 68 + cc];
                o.z = Bs[(r0 - 32 + 2) * 68 + cc]; o.w = Bs[(r0 - 32 + 3) * 68 + cc];
            }
            *(float4*)&C[(size_t)(n0 + ty * 4 + i) * D + m0 + tx * 4] = o;
        }
    }
}

// ---------------- phase runner: nj jobs, sym=upper-tri tiles + mirror ----
__device__ __noinline__ void phase_gemm(int nj, const float* const* Aj,
                                        const float* const* Bj, float* const* Cj,
                                        const float* al, float betaI, int sym) {
    int tpj = sym ? 36 : 64;
    int total = nj * tpj;
    for (int t = blockIdx.x; t < total; t += NCTA) {
        int j = t / tpj, tt = t - j * tpj;
        int mt, nt;
        if (sym) {
            int m = 0, r = tt;
            while (r >= 8 - m) { r -= 8 - m; m++; }
            mt = m; nt = m + r;
        } else { mt = tt >> 3; nt = tt & 7; }
        tile_gemm(Aj[j], Bj[j], Cj[j], mt * 64, nt * 64, al[j], betaI,
                  sym && (mt != nt));
    }
}

// ---------------- small device helpers ----------------
__device__ __noinline__ void trace_prep(const float* __restrict__ A, int base,
                                        int withAlpha) {
    __shared__ float red[256];
    int t = threadIdx.x;
    red[t] = A[(size_t)t * (D + 1)] + A[(size_t)(t + 256) * (D + 1)];
    __syncthreads();
    for (int off = 128; off > 0; off >>= 1) {
        if (t < off) red[t] += red[t + off];
        __syncthreads();
    }
    if (t == 0) {
        float c = red[0] * (1.25f / 512.0f);
        g_scal[base] = c;
        g_scal[base + 1] = 1.0f / c;
        if (withAlpha) g_scal[base + 2] = sqrtf(c) / g_scal[0];
    }
}

__device__ __forceinline__ void ew_copy(float* dst, const float* src) {
    for (int i = blockIdx.x * 256 + threadIdx.x; i < MATN / 4; i += NCTA * 256)
        ((float4*)dst)[i] = ((const float4*)src)[i];
}

__device__ __forceinline__ void ew_add(float* dst, const float* a, const float* b) {
    for (int i = blockIdx.x * 256 + threadIdx.x; i < MATN; i += NCTA * 256)
        dst[i] = a[i] + b[i];
}

__device__ __forceinline__ void ew_nsinit(float* Y, float* Z, const float* S,
                                          float invc) {
    for (int i = blockIdx.x * 256 + threadIdx.x; i < MATN; i += NCTA * 256) {
        Y[i] = S[i] * invc;
        Z[i] = ((i >> 9) == (i & 511)) ? 1.0f : 0.0f;
    }
}

// coupled Newton-Schulz for nb matrices (all symmetric; upper tiles + mirror)
__device__ __noinline__ void ns_run(float* y[], float* z[], float* yb[],
                                    float* zb[], float* const w[], int nb) {
    const float* Aj[4]; const float* Bj[4]; float* Cj[4]; float al[4];
    for (int s = 0; s < NS_ITERS; s++) {
        for (int j = 0; j < nb; j++) {
            Aj[j] = z[j]; Bj[j] = y[j]; Cj[j] = w[j]; al[j] = -0.5f;
        }
        phase_gemm(nb, Aj, Bj, Cj, al, 1.5f, 1);
        gridsync();
        for (int j = 0; j < nb; j++) {
            Aj[2*j]   = y[j]; Bj[2*j]   = w[j]; Cj[2*j]   = yb[j]; al[2*j]   = 1.f;
            Aj[2*j+1] = w[j]; Bj[2*j+1] = z[j]; Cj[2*j+1] = zb[j]; al[2*j+1] = 1.f;
        }
        phase_gemm(2 * nb, Aj, Bj, Cj, al, 0.f, 1);
        gridsync();
        for (int j = 0; j < nb; j++) {
            float* t = y[j]; y[j] = yb[j]; yb[j] = t;
            t = z[j]; z[j] = zb[j]; zb[j] = t;
        }
    }
}

// ---------------- persistent barycenter kernel ----------------
__global__ __launch_bounds__(256, 1) void persist_k() {
    float* Yp[2]; float* Zp[2]; float* Ybp[2]; float* Zbp[2]; float* Wp[2];
    const float* Aj[4]; const float* Bj[4]; float* Cj[4]; float al[4];

    // Sigma init = cov_c
    ew_copy(g_mat[SIGB], g_mat[COVC]);
    gridsync();

    for (int it = 0; it < BARY_ITERS; it++) {
        if (blockIdx.x == 0) trace_prep(g_mat[SIGB], 0, 0);
        gridsync();
        ew_nsinit(g_mat[BYA], g_mat[BZA], g_mat[SIGB], g_scal[1]);
        gridsync();
        Yp[0] = g_mat[BYA]; Zp[0] = g_mat[BZA];
        Ybp[0] = g_mat[BYB]; Zbp[0] = g_mat[BZB]; Wp[0] = g_mat[BW0];
        ns_run(Yp, Zp, Ybp, Zbp, Wp, 1);
        float* y = Yp[0]; float* z = Zp[0];

        // P_j = Y @ cov_j (full)
        Aj[0] = y; Bj[0] = g_mat[COVC]; Cj[0] = g_mat[BP0]; al[0] = 1.f;
        Aj[1] = y; Bj[1] = g_mat[COVS]; Cj[1] = g_mat[BP1]; al[1] = 1.f;
        phase_gemm(2, Aj, Bj, Cj, al, 0.f, 0);
        gridsync();
        // M_j = c * (P_j @ Y) (sym)  [= S_sqrt cov_j S_sqrt]
        float csig = g_scal[0];
        Aj[0] = g_mat[BP0]; Bj[0] = y; Cj[0] = g_mat[BM0]; al[0] = csig;
        Aj[1] = g_mat[BP1]; Bj[1] = y; Cj[1] = g_mat[BM1]; al[1] = csig;
        phase_gemm(2, Aj, Bj, Cj, al, 0.f, 1);
        gridsync();

        if (blockIdx.x < 2) trace_prep(g_mat[BM0 + blockIdx.x], 4 + 4 * blockIdx.x, 1);
        gridsync();
        ew_nsinit(g_mat[YJ0A], g_mat[ZJ0A], g_mat[BM0], g_scal[5]);
        ew_nsinit(g_mat[YJ1A], g_mat[ZJ1A], g_mat[BM1], g_scal[9]);
        gridsync();
        Yp[0] = g_mat[YJ0A]; Zp[0] = g_mat[ZJ0A];
        Ybp[0] = g_mat[YJ0B]; Zbp[0] = g_mat[ZJ0B]; Wp[0] = g_mat[WJ0];
        Yp[1] = g_mat[YJ1A]; Zp[1] = g_mat[ZJ1A];
        Ybp[1] = g_mat[YJ1B]; Zbp[1] = g_mat[ZJ1B]; Wp[1] = g_mat[WJ1];
        ns_run(Yp, Zp, Ybp, Zbp, Wp, 2);

        // R_j = Z @ Ym_j (full)
        Aj[0] = z; Bj[0] = Yp[0]; Cj[0] = g_mat[BR0]; al[0] = 1.f;
        Aj[1] = z; Bj[1] = Yp[1]; Cj[1] = g_mat[BR1]; al[1] = 1.f;
        phase_gemm(2, Aj, Bj, Cj, al, 0.f, 0);
        gridsync();
        // T_j = (0.5 * sqrt(c_j) / c) * (R_j @ Z) (sym)
        Aj[0] = g_mat[BR0]; Bj[0] = z; Cj[0] = g_mat[BT0]; al[0] = 0.5f * g_scal[6];
        Aj[1] = g_mat[BR1]; Bj[1] = z; Cj[1] = g_mat[BT1]; al[1] = 0.5f * g_scal[10];
        phase_gemm(2, Aj, Bj, Cj, al, 0.f, 1);
        gridsync();
        // Sigma = T0 + T1 (already symmetric via mirroring)
        ew_add(g_mat[SIGB], g_mat[BT0], g_mat[BT1]);
        gridsync();
    }

    // ---- final transform M = Sc^-1/2 (Sc^1/2 Sigma Sc^1/2)^1/2 Sc^-1/2 ----
    if (blockIdx.x == 0) trace_prep(g_mat[COVC], 0, 0);
    gridsync();
    ew_nsinit(g_mat[BYA], g_mat[BZA], g_mat[COVC], g_scal[1]);
    gridsync();
    Yp[0] = g_mat[BYA]; Zp[0] = g_mat[BZA];
    Ybp[0] = g_mat[BYB]; Zbp[0] = g_mat[BZB]; Wp[0] = g_mat[BW0];
    ns_run(Yp, Zp, Ybp, Zbp, Wp, 1);
    float* y = Yp[0]; float* z = Zp[0];

    Aj[0] = y; Bj[0] = g_mat[SIGB]; Cj[0] = g_mat[BP0]; al[0] = 1.f;
    phase_gemm(1, Aj, Bj, Cj, al, 0.f, 0);
    gridsync();
    Aj[0] = g_mat[BP0]; Bj[0] = y; Cj[0] = g_mat[BM0]; al[0] = g_scal[0];
    phase_gemm(1, Aj, Bj, Cj, al, 0.f, 1);
    gridsync();
    if (blockIdx.x == 0) trace_prep(g_mat[BM0], 4, 1);
    gridsync();
    ew_nsinit(g_mat[YJ0A], g_mat[ZJ0A], g_mat[BM0], g_scal[5]);
    gridsync();
    Yp[0] = g_mat[YJ0A]; Zp[0] = g_mat[ZJ0A];
    Ybp[0] = g_mat[YJ0B]; Zbp[0] = g_mat[ZJ0B]; Wp[0] = g_mat[WJ0];
    ns_run(Yp, Zp, Ybp, Zbp, Wp, 1);

    // R = Z @ Ym (full); M = (sqrt(cm)/cc) * (R @ Z) (sym) -> BT0
    Aj[0] = z; Bj[0] = Yp[0]; Cj[0] = g_mat[BR0]; al[0] = 1.f;
    phase_gemm(1, Aj, Bj, Cj, al, 0.f, 0);
    gridsync();
    Aj[0] = g_mat[BR0]; Bj[0] = z; Cj[0] = g_mat[BT0]; al[0] = g_scal[6];
    phase_gemm(1, Aj, Bj, Cj, al, 0.f, 1);
}

// ---------------- output GEMM: out = (x - mu_c) @ M^T + mu_b (NT) --------
__global__ __launch_bounds__(256) void outgemm_k(const float* __restrict__ x,
                                                 float* __restrict__ out) {
    __shared__ float As[32 * 68];
    __shared__ float Bs[32 * 68];
    const float* __restrict__ Mt = g_mat[BT0];
    int tid = threadIdx.x, tx = tid & 15, ty = tid >> 4;
    size_t m0 = (size_t)blockIdx.y * 64;
    int n0 = blockIdx.x * 64;
    int acol = (tid & 7) * 4, arow = tid >> 3;
    float acc[4][4] = {};
    for (int k0 = 0; k0 < D; k0 += 32) {
        __syncthreads();
        #pragma unroll
        for (int p = 0; p < 2; p++) {
            int m = arow + p * 32;
            float4 v = *(const float4*)&x[(m0 + m) * D + k0 + acol];
            As[(acol + 0) * 68 + m] = v.x - g_mean[0][k0 + acol + 0];
            As[(acol + 1) * 68 + m] = v.y - g_mean[0][k0 + acol + 1];
            As[(acol + 2) * 68 + m] = v.z - g_mean[0][k0 + acol + 2];
            As[(acol + 3) * 68 + m] = v.w - g_mean[0][k0 + acol + 3];
        }
        #pragma unroll
        for (int p = 0; p < 2; p++) {
            int n = arow + p * 32;
            float4 v = *(const float4*)&Mt[(size_t)(n0 + n) * D + k0 + acol];
            Bs[(acol + 0) * 68 + n] = v.x; Bs[(acol + 1) * 68 + n] = v.y;
            Bs[(acol + 2) * 68 + n] = v.z; Bs[(acol + 3) * 68 + n] = v.w;
        }
        __syncthreads();
        #pragma unroll
        for (int k = 0; k < 32; k++) {
            float4 a = *(const float4*)&As[k * 68 + ty * 4];
            float4 b = *(const float4*)&Bs[k * 68 + tx * 4];
            float av[4] = {a.x, a.y, a.z, a.w};
            float bv[4] = {b.x, b.y, b.z, b.w};
            #pragma unroll
            for (int i = 0; i < 4; i++)
                #pragma unroll
                for (int j = 0; j < 4; j++)
                    acc[i][j] += av[i] * bv[j];
        }
    }
    #pragma unroll
    for (int i = 0; i < 4; i++) {
        size_t m = m0 + ty * 4 + i;
        int n = n0 + tx * 4;
        float4 o;
        o.x = acc[i][0] + g_mean[2][n + 0];
        o.y = acc[i][1] + g_mean[2][n + 1];
        o.z = acc[i][2] + g_mean[2][n + 2];
        o.w = acc[i][3] + g_mean[2][n + 3];
        *(float4*)&out[m * D + n] = o;
    }
}

// ---------------- host orchestration (11 graph nodes) ----------------
extern "C" void kernel_launch(void* const* d_in, const int* in_sizes, int n_in,
                              void* d_out, int out_size) {
    const float* content = (const float*)d_in[0];
    const float* style   = (const float*)d_in[1];
    float* out = (float*)d_out;

    colsum1_k<<<256, 256>>>(content);
    colsum2_k<<<1, D>>>(0);
    colsum1_k<<<256, 256>>>(style);
    colsum2_k<<<1, D>>>(1);
    mub_k<<<1, D>>>();

    xtx_k<<<dim3(8, 8, SPLITS), 256>>>(content);
    covfin_k<<<MATN / 256, 256>>>(COVC, 0);
    xtx_k<<<dim3(8, 8, SPLITS), 256>>>(style);
    covfin_k<<<MATN / 256, 256>>>(COVS, 1);

    persist_k<<<NCTA, 256>>>();

    outgemm_k<<<dim3(8, 1024), 256>>>(content, out);

    (void)in_sizes; (void)n_in; (void)out_size;
}

// round 4
// speedup vs baseline: 4.0401x; 4.0401x over previous
#include <cuda_runtime.h>
#include <cuda_bf16.h>
#include <math.h>

#define D 512
#define NROWS 65536
#define MATN (D*D)
#define NS_ITERS 5
#define BARY_ITERS 16
#define SPLITS 32
#define CHUNK (NROWS/SPLITS)
#define NCTA 144
#define KC 64
#define PK 72
#define PC 68
#define SMEM_SZ (4*64*PK*2)   // 36,864 B: Ah/Al/Bh/Bl bf16 staging (Cs fp32 overlays)

// ---------------- matrix buffer ids ----------------
enum {
  COVC=0, COVS, SIGB, BYA, BZA, BYB, BZB, BW0,
  BP0, BP1, BM0, BM1,
  YJ0A, YJ1A, ZJ0A, ZJ1A, YJ0B, YJ1B, ZJ0B, ZJ1B, WJ0, WJ1,
  BR0, BR1, BT0, BT1, NBUF
};

__device__ float g_mat[NBUF][MATN];
__device__ float g_covpart[SPLITS][MATN];
__device__ float g_meanpart[256][D];
__device__ float g_mean[3][D];              // 0: mu_c, 1: mu_s, 2: mu_bary
__device__ float g_scal[16];

// ---------------- grid-wide barrier ----------------
__device__ unsigned g_bar_cnt;
__device__ volatile unsigned g_bar_gen;

__device__ __forceinline__ void gridsync() {
    __syncthreads();
    if (threadIdx.x == 0) {
        __threadfence();
        unsigned gen = g_bar_gen;
        if (atomicAdd(&g_bar_cnt, 1u) == NCTA - 1u) {
            g_bar_cnt = 0u;
            __threadfence();
            g_bar_gen = gen + 1u;
        } else {
            while (g_bar_gen == gen) { }
        }
        __threadfence();
    }
    __syncthreads();
}

// ---------------- bf16 split helpers ----------------
__device__ __forceinline__ void split2(float x0, float x1, unsigned &h, unsigned &l) {
    __nv_bfloat162 hh = __floats2bfloat162_rn(x0, x1);
    float r0 = x0 - __low2float(hh);
    float r1 = x1 - __high2float(hh);
    __nv_bfloat162 ll = __floats2bfloat162_rn(r0, r1);
    h = *reinterpret_cast<unsigned*>(&hh);
    l = *reinterpret_cast<unsigned*>(&ll);
}

__device__ __forceinline__ void split1(float x, unsigned short &h, unsigned short &l) {
    __nv_bfloat16 hb = __float2bfloat16_rn(x);
    float r = x - __bfloat162float(hb);
    __nv_bfloat16 lb = __float2bfloat16_rn(r);
    h = *reinterpret_cast<unsigned short*>(&hb);
    l = *reinterpret_cast<unsigned short*>(&lb);
}

// ---------------- smem staging ----------------
// rows: dst[m][k] <- src[row0+m][k0+k], 64x64, src row stride D
__device__ __forceinline__ void stage_rows(unsigned short* sh, unsigned short* sl,
                                           const float* src, size_t row0, int k0) {
    int r = threadIdx.x >> 2, q4 = threadIdx.x & 3;
    const float* p = src + (row0 + (size_t)r) * D + k0;
    #pragma unroll
    for (int q = 0; q < 4; q++) {
        int kk = (q4 + 4 * q) * 4;
        float4 v = __ldcg((const float4*)(p + kk));
        unsigned h0, l0, h1, l1;
        split2(v.x, v.y, h0, l0);
        split2(v.z, v.w, h1, l1);
        *(unsigned*)&sh[r * PK + kk] = h0;  *(unsigned*)&sh[r * PK + kk + 2] = h1;
        *(unsigned*)&sl[r * PK + kk] = l0;  *(unsigned*)&sl[r * PK + kk + 2] = l1;
    }
}

// rows minus mean: dst[m][k] <- src[row0+m][k0+k] - mean[k0+k]
__device__ __forceinline__ void stage_rows_sub(unsigned short* sh, unsigned short* sl,
                                               const float* src, size_t row0, int k0,
                                               const float* mean) {
    int r = threadIdx.x >> 2, q4 = threadIdx.x & 3;
    const float* p = src + (row0 + (size_t)r) * D + k0;
    #pragma unroll
    for (int q = 0; q < 4; q++) {
        int kk = (q4 + 4 * q) * 4;
        float4 v = __ldcg((const float4*)(p + kk));
        float4 mu = *(const float4*)&mean[k0 + kk];
        unsigned h0, l0, h1, l1;
        split2(v.x - mu.x, v.y - mu.y, h0, l0);
        split2(v.z - mu.z, v.w - mu.w, h1, l1);
        *(unsigned*)&sh[r * PK + kk] = h0;  *(unsigned*)&sh[r * PK + kk + 2] = h1;
        *(unsigned*)&sl[r * PK + kk] = l0;  *(unsigned*)&sl[r * PK + kk + 2] = l1;
    }
}

// transposed: dst[m][k] <- src[krow0+k][c0+m]  (for X^T X)
__device__ __forceinline__ void stage_cols(unsigned short* sh, unsigned short* sl,
                                           const float* src, size_t krow0, int c0) {
    int kr = threadIdx.x >> 2, q4 = threadIdx.x & 3;
    const float* p = src + (krow0 + (size_t)kr) * D + c0;
    #pragma unroll
    for (int q = 0; q < 4; q++) {
        int col4 = (q4 + 4 * q) * 4;
        float4 v = __ldcg((const float4*)(p + col4));
        unsigned short h, l;
        split1(v.x, h, l); sh[(col4 + 0) * PK + kr] = h; sl[(col4 + 0) * PK + kr] = l;
        split1(v.y, h, l); sh[(col4 + 1) * PK + kr] = h; sl[(col4 + 1) * PK + kr] = l;
        split1(v.z, h, l); sh[(col4 + 2) * PK + kr] = h; sl[(col4 + 2) * PK + kr] = l;
        split1(v.w, h, l); sh[(col4 + 3) * PK + kr] = h; sl[(col4 + 3) * PK + kr] = l;
    }
}

// ---------------- mma fragments ----------------
__device__ __forceinline__ void lda(unsigned a[4], const unsigned short* s, int rb, int kb) {
    int l = threadIdx.x & 31;
    int r = rb + (l >> 2), c = kb + (l & 3) * 2;
    a[0] = *(const unsigned*)&s[r * PK + c];
    a[1] = *(const unsigned*)&s[(r + 8) * PK + c];
    a[2] = *(const unsigned*)&s[r * PK + c + 8];
    a[3] = *(const unsigned*)&s[(r + 8) * PK + c + 8];
}

__device__ __forceinline__ void ldb(unsigned b[2], const unsigned short* s, int nb, int kb) {
    int l = threadIdx.x & 31;
    int n = nb + (l >> 2), c = kb + (l & 3) * 2;
    b[0] = *(const unsigned*)&s[n * PK + c];
    b[1] = *(const unsigned*)&s[n * PK + c + 8];
}

__device__ __forceinline__ void mma16816(float c[4], const unsigned a[4], const unsigned b[2]) {
    asm volatile(
        "mma.sync.aligned.m16n8k16.row.col.f32.bf16.bf16.f32 "
        "{%0,%1,%2,%3}, {%4,%5,%6,%7}, {%8,%9}, {%0,%1,%2,%3};\n"
        : "+f"(c[0]), "+f"(c[1]), "+f"(c[2]), "+f"(c[3])
        : "r"(a[0]), "r"(a[1]), "r"(a[2]), "r"(a[3]), "r"(b[0]), "r"(b[1]));
}

// one KC-chunk of mma work (split-precision: hh + hl + lh)
__device__ __forceinline__ void mma_chunk(float c[2][2][4],
                                          const unsigned short* Ah, const unsigned short* Al,
                                          const unsigned short* Bh, const unsigned short* Bl,
                                          int wm, int wn) {
    #pragma unroll
    for (int kb = 0; kb < KC; kb += 16) {
        unsigned ah0[4], ah1[4], al0[4], al1[4], bh0[2], bh1[2], bl0[2], bl1[2];
        lda(ah0, Ah, wm, kb);      lda(ah1, Ah, wm + 16, kb);
        lda(al0, Al, wm, kb);      lda(al1, Al, wm + 16, kb);
        ldb(bh0, Bh, wn, kb);      ldb(bh1, Bh, wn + 8, kb);
        ldb(bl0, Bl, wn, kb);      ldb(bl1, Bl, wn + 8, kb);
        mma16816(c[0][0], ah0, bh0);  mma16816(c[0][1], ah0, bh1);
        mma16816(c[1][0], ah1, bh0);  mma16816(c[1][1], ah1, bh1);
        mma16816(c[0][0], ah0, bl0);  mma16816(c[0][1], ah0, bl1);
        mma16816(c[1][0], ah1, bl0);  mma16816(c[1][1], ah1, bl1);
        mma16816(c[0][0], al0, bh0);  mma16816(c[0][1], al0, bh1);
        mma16816(c[1][0], al1, bh0);  mma16816(c[1][1], al1, bh1);
    }
}

__device__ __forceinline__ void frags_to_Cs(float c[2][2][4], float* Cs, int wm, int wn) {
    int l = threadIdx.x & 31;
    int rr = l >> 2, cc2 = (l & 3) * 2;
    #pragma unroll
    for (int mf = 0; mf < 2; mf++)
        #pragma unroll
        for (int nf = 0; nf < 2; nf++) {
            int r = wm + mf * 16 + rr, cc = wn + nf * 8 + cc2;
            *(float2*)&Cs[r * PC + cc]       = make_float2(c[mf][nf][0], c[mf][nf][1]);
            *(float2*)&Cs[(r + 8) * PC + cc] = make_float2(c[mf][nf][2], c[mf][nf][3]);
        }
}

// ---------------- 64x64 tile GEMM over K=512 (row-major A, SYMMETRIC B) --
__device__ __noinline__ void tile_gemm(const float* __restrict__ A,
                                       const float* __restrict__ B,
                                       float* __restrict__ C,
                                       int m0, int n0,
                                       float alpha, float betaI, int mirror) {
    extern __shared__ char sm_[];
    unsigned short* Ah = (unsigned short*)sm_;
    unsigned short* Al = Ah + 64 * PK;
    unsigned short* Bh = Al + 64 * PK;
    unsigned short* Bl = Bh + 64 * PK;
    float* Cs = (float*)sm_;
    int tid = threadIdx.x, wid = tid >> 5;
    int wm = (wid >> 2) * 32, wn = (wid & 3) * 16;
    float c[2][2][4] = {};
    for (int k0 = 0; k0 < D; k0 += KC) {
        __syncthreads();
        stage_rows(Ah, Al, A, (size_t)m0, k0);
        stage_rows(Bh, Bl, B, (size_t)n0, k0);   // B symmetric: row n == col n
        __syncthreads();
        mma_chunk(c, Ah, Al, Bh, Bl, wm, wn);
    }
    __syncthreads();
    frags_to_Cs(c, Cs, wm, wn);
    __syncthreads();
    int r = tid >> 2;
    #pragma unroll
    for (int q = 0; q < 4; q++) {
        int cc = (tid & 3) * 4 + q * 16;
        float4 v = *(float4*)&Cs[r * PC + cc];
        int m = m0 + r, n = n0 + cc;
        float o0 = v.x * alpha, o1 = v.y * alpha, o2 = v.z * alpha, o3 = v.w * alpha;
        if (betaI != 0.f) {
            if (m == n + 0) o0 += betaI;
            if (m == n + 1) o1 += betaI;
            if (m == n + 2) o2 += betaI;
            if (m == n + 3) o3 += betaI;
        }
        *(float4*)&C[(size_t)m * D + n] = make_float4(o0, o1, o2, o3);
        if (mirror) {
            C[(size_t)(n + 0) * D + m] = o0;
            C[(size_t)(n + 1) * D + m] = o1;
            C[(size_t)(n + 2) * D + m] = o2;
            C[(size_t)(n + 3) * D + m] = o3;
        }
    }
}

// ---------------- phase runner ----------------
__device__ __noinline__ void phase_gemm(int nj, const float* const* Aj,
                                        const float* const* Bj, float* const* Cj,
                                        const float* al, float betaI, int sym) {
    int tpj = sym ? 36 : 64;
    int total = nj * tpj;
    for (int t = blockIdx.x; t < total; t += NCTA) {
        int j = t / tpj, tt = t - j * tpj;
        int mt, nt;
        if (sym) {
            int m = 0, r = tt;
            while (r >= 8 - m) { r -= 8 - m; m++; }
            mt = m; nt = m + r;
        } else { mt = tt >> 3; nt = tt & 7; }
        tile_gemm(Aj[j], Bj[j], Cj[j], mt * 64, nt * 64, al[j], betaI,
                  sym && (mt != nt));
    }
}

// ---------------- small device helpers ----------------
__device__ __noinline__ void trace_prep(const float* __restrict__ A, int base,
                                        int withAlpha) {
    __shared__ float red[256];
    int t = threadIdx.x;
    red[t] = __ldcg(&A[(size_t)t * (D + 1)]) + __ldcg(&A[(size_t)(t + 256) * (D + 1)]);
    __syncthreads();
    for (int off = 128; off > 0; off >>= 1) {
        if (t < off) red[t] += red[t + off];
        __syncthreads();
    }
    if (t == 0) {
        float c = red[0] * (1.25f / 512.0f);
        g_scal[base] = c;
        g_scal[base + 1] = 1.0f / c;
        if (withAlpha) g_scal[base + 2] = sqrtf(c) / g_scal[0];
    }
}

__device__ __forceinline__ void ew_copy(float* dst, const float* src) {
    for (int i = blockIdx.x * 256 + threadIdx.x; i < MATN / 4; i += NCTA * 256)
        ((float4*)dst)[i] = __ldcg((const float4*)src + i);
}

__device__ __forceinline__ void ew_add(float* dst, const float* a, const float* b) {
    for (int i = blockIdx.x * 256 + threadIdx.x; i < MATN; i += NCTA * 256)
        dst[i] = __ldcg(a + i) + __ldcg(b + i);
}

__device__ __forceinline__ void ew_nsinit(float* Y, float* Z, const float* S,
                                          float invc) {
    for (int i = blockIdx.x * 256 + threadIdx.x; i < MATN; i += NCTA * 256) {
        Y[i] = __ldcg(S + i) * invc;
        Z[i] = ((i >> 9) == (i & 511)) ? 1.0f : 0.0f;
    }
}

// coupled Newton-Schulz for nb symmetric matrices
__device__ __noinline__ void ns_run(float* y[], float* z[], float* yb[],
                                    float* zb[], float* const w[], int nb) {
    const float* Aj[4]; const float* Bj[4]; float* Cj[4]; float al[4];
    for (int s = 0; s < NS_ITERS; s++) {
        for (int j = 0; j < nb; j++) {
            Aj[j] = z[j]; Bj[j] = y[j]; Cj[j] = w[j]; al[j] = -0.5f;
        }
        phase_gemm(nb, Aj, Bj, Cj, al, 1.5f, 1);
        gridsync();
        for (int j = 0; j < nb; j++) {
            Aj[2*j]   = y[j]; Bj[2*j]   = w[j]; Cj[2*j]   = yb[j]; al[2*j]   = 1.f;
            Aj[2*j+1] = w[j]; Bj[2*j+1] = z[j]; Cj[2*j+1] = zb[j]; al[2*j+1] = 1.f;
        }
        phase_gemm(2 * nb, Aj, Bj, Cj, al, 0.f, 1);
        gridsync();
        for (int j = 0; j < nb; j++) {
            float* t = y[j]; y[j] = yb[j]; yb[j] = t;
            t = z[j]; z[j] = zb[j]; zb[j] = t;
        }
    }
}

// ---------------- persistent barycenter kernel ----------------
__global__ __launch_bounds__(256, 1) void persist_k() {
    float* Yp[2]; float* Zp[2]; float* Ybp[2]; float* Zbp[2]; float* Wp[2];
    const float* Aj[4]; const float* Bj[4]; float* Cj[4]; float al[4];

    ew_copy(g_mat[SIGB], g_mat[COVC]);
    gridsync();

    for (int it = 0; it < BARY_ITERS; it++) {
        if (blockIdx.x == 0) trace_prep(g_mat[SIGB], 0, 0);
        gridsync();
        ew_nsinit(g_mat[BYA], g_mat[BZA], g_mat[SIGB], __ldcg(&g_scal[1]));
        gridsync();
        Yp[0] = g_mat[BYA]; Zp[0] = g_mat[BZA];
        Ybp[0] = g_mat[BYB]; Zbp[0] = g_mat[BZB]; Wp[0] = g_mat[BW0];
        ns_run(Yp, Zp, Ybp, Zbp, Wp, 1);
        float* y = Yp[0]; float* z = Zp[0];

        // P_j = Y @ cov_j (full)
        Aj[0] = y; Bj[0] = g_mat[COVC]; Cj[0] = g_mat[BP0]; al[0] = 1.f;
        Aj[1] = y; Bj[1] = g_mat[COVS]; Cj[1] = g_mat[BP1]; al[1] = 1.f;
        phase_gemm(2, Aj, Bj, Cj, al, 0.f, 0);
        gridsync();
        // M_j = c * (P_j @ Y) (sym)
        float csig = __ldcg(&g_scal[0]);
        Aj[0] = g_mat[BP0]; Bj[0] = y; Cj[0] = g_mat[BM0]; al[0] = csig;
        Aj[1] = g_mat[BP1]; Bj[1] = y; Cj[1] = g_mat[BM1]; al[1] = csig;
        phase_gemm(2, Aj, Bj, Cj, al, 0.f, 1);
        gridsync();

        if (blockIdx.x < 2) trace_prep(g_mat[BM0 + blockIdx.x], 4 + 4 * blockIdx.x, 1);
        gridsync();
        ew_nsinit(g_mat[YJ0A], g_mat[ZJ0A], g_mat[BM0], __ldcg(&g_scal[5]));
        ew_nsinit(g_mat[YJ1A], g_mat[ZJ1A], g_mat[BM1], __ldcg(&g_scal[9]));
        gridsync();
        Yp[0] = g_mat[YJ0A]; Zp[0] = g_mat[ZJ0A];
        Ybp[0] = g_mat[YJ0B]; Zbp[0] = g_mat[ZJ0B]; Wp[0] = g_mat[WJ0];
        Yp[1] = g_mat[YJ1A]; Zp[1] = g_mat[ZJ1A];
        Ybp[1] = g_mat[YJ1B]; Zbp[1] = g_mat[ZJ1B]; Wp[1] = g_mat[WJ1];
        ns_run(Yp, Zp, Ybp, Zbp, Wp, 2);

        // R_j = Z @ Ym_j (full)
        Aj[0] = z; Bj[0] = Yp[0]; Cj[0] = g_mat[BR0]; al[0] = 1.f;
        Aj[1] = z; Bj[1] = Yp[1]; Cj[1] = g_mat[BR1]; al[1] = 1.f;
        phase_gemm(2, Aj, Bj, Cj, al, 0.f, 0);
        gridsync();
        // T_j = (0.5 * sqrt(c_j) / c) * (R_j @ Z) (sym)
        Aj[0] = g_mat[BR0]; Bj[0] = z; Cj[0] = g_mat[BT0]; al[0] = 0.5f * __ldcg(&g_scal[6]);
        Aj[1] = g_mat[BR1]; Bj[1] = z; Cj[1] = g_mat[BT1]; al[1] = 0.5f * __ldcg(&g_scal[10]);
        phase_gemm(2, Aj, Bj, Cj, al, 0.f, 1);
        gridsync();
        ew_add(g_mat[SIGB], g_mat[BT0], g_mat[BT1]);
        gridsync();
    }

    // ---- final transform M = Sc^-1/2 (Sc^1/2 Sigma Sc^1/2)^1/2 Sc^-1/2 ----
    if (blockIdx.x == 0) trace_prep(g_mat[COVC], 0, 0);
    gridsync();
    ew_nsinit(g_mat[BYA], g_mat[BZA], g_mat[COVC], __ldcg(&g_scal[1]));
    gridsync();
    Yp[0] = g_mat[BYA]; Zp[0] = g_mat[BZA];
    Ybp[0] = g_mat[BYB]; Zbp[0] = g_mat[BZB]; Wp[0] = g_mat[BW0];
    ns_run(Yp, Zp, Ybp, Zbp, Wp, 1);
    float* y = Yp[0]; float* z = Zp[0];

    Aj[0] = y; Bj[0] = g_mat[SIGB]; Cj[0] = g_mat[BP0]; al[0] = 1.f;
    phase_gemm(1, Aj, Bj, Cj, al, 0.f, 0);
    gridsync();
    Aj[0] = g_mat[BP0]; Bj[0] = y; Cj[0] = g_mat[BM0]; al[0] = __ldcg(&g_scal[0]);
    phase_gemm(1, Aj, Bj, Cj, al, 0.f, 1);
    gridsync();
    if (blockIdx.x == 0) trace_prep(g_mat[BM0], 4, 1);
    gridsync();
    ew_nsinit(g_mat[YJ0A], g_mat[ZJ0A], g_mat[BM0], __ldcg(&g_scal[5]));
    gridsync();
    Yp[0] = g_mat[YJ0A]; Zp[0] = g_mat[ZJ0A];
    Ybp[0] = g_mat[YJ0B]; Zbp[0] = g_mat[ZJ0B]; Wp[0] = g_mat[WJ0];
    ns_run(Yp, Zp, Ybp, Zbp, Wp, 1);

    Aj[0] = z; Bj[0] = Yp[0]; Cj[0] = g_mat[BR0]; al[0] = 1.f;
    phase_gemm(1, Aj, Bj, Cj, al, 0.f, 0);
    gridsync();
    Aj[0] = g_mat[BR0]; Bj[0] = z; Cj[0] = g_mat[BT0]; al[0] = __ldcg(&g_scal[6]);
    phase_gemm(1, Aj, Bj, Cj, al, 0.f, 1);
}

// ---------------- column means ----------------
__global__ void colsum1_k(const float* __restrict__ x) {
    int cta = blockIdx.x, t = threadIdx.x;
    const float* base = x + (size_t)cta * 256 * D;
    float s0 = 0.f, s1 = 0.f;
    for (int r = 0; r < 256; r++) {
        s0 += base[(size_t)r * D + t];
        s1 += base[(size_t)r * D + t + 256];
    }
    g_meanpart[cta][t] = s0;
    g_meanpart[cta][t + 256] = s1;
}

__global__ void colsum2_k(int which) {
    int t = threadIdx.x;
    float s = 0.f;
    for (int i = 0; i < 256; i++) s += g_meanpart[i][t];
    g_mean[which][t] = s * (1.0f / NROWS);
}

__global__ void mub_k() {
    int t = threadIdx.x;
    g_mean[2][t] = 0.5f * (g_mean[0][t] + g_mean[1][t]);
}

// ---------------- X^T X partials via mma (upper tile triangle) ----------
__global__ __launch_bounds__(256) void xtx_mma_k(const float* __restrict__ x) {
    if (blockIdx.y > blockIdx.x) return;
    extern __shared__ char sm_[];
    unsigned short* Ah = (unsigned short*)sm_;
    unsigned short* Al = Ah + 64 * PK;
    unsigned short* Bh = Al + 64 * PK;
    unsigned short* Bl = Bh + 64 * PK;
    float* Cs = (float*)sm_;
    int tid = threadIdx.x, wid = tid >> 5;
    int wm = (wid >> 2) * 32, wn = (wid & 3) * 16;
    int m0 = blockIdx.y * 64, n0 = blockIdx.x * 64;
    size_t r0 = (size_t)blockIdx.z * CHUNK;
    float c[2][2][4] = {};
    for (int k0 = 0; k0 < CHUNK; k0 += KC) {
        __syncthreads();
        stage_cols(Ah, Al, x, r0 + k0, m0);
        stage_cols(Bh, Bl, x, r0 + k0, n0);
        __syncthreads();
        mma_chunk(c, Ah, Al, Bh, Bl, wm, wn);
    }
    __syncthreads();
    frags_to_Cs(c, Cs, wm, wn);
    __syncthreads();
    float* Cp = g_covpart[blockIdx.z];
    int r = tid >> 2;
    #pragma unroll
    for (int q = 0; q < 4; q++) {
        int cc = (tid & 3) * 4 + q * 16;
        float4 v = *(float4*)&Cs[r * PC + cc];
        *(float4*)&Cp[(m0 + r) * D + n0 + cc] = v;
    }
}

__global__ void covfin_k(int covIdx, int meanIdx) {
    int idx = blockIdx.x * 256 + threadIdx.x;
    int m = idx >> 9, n = idx & 511;
    int ms = m, ns = n;
    if ((m >> 6) > (n >> 6)) { ms = n; ns = m; }
    float s = 0.f;
    #pragma unroll 8
    for (int p = 0; p < SPLITS; p++) s += g_covpart[p][ms * D + ns];
    float v = (s - (float)NROWS * g_mean[meanIdx][m] * g_mean[meanIdx][n])
              * (1.0f / (NROWS - 1));
    g_mat[covIdx][idx] = v;
}

// ---------------- output GEMM: out = (x - mu_c) @ M^T + mu_b -------------
__global__ __launch_bounds__(256) void outgemm_mma_k(const float* __restrict__ x,
                                                     float* __restrict__ out) {
    extern __shared__ char sm_[];
    unsigned short* Ah = (unsigned short*)sm_;
    unsigned short* Al = Ah + 64 * PK;
    unsigned short* Bh = Al + 64 * PK;
    unsigned short* Bl = Bh + 64 * PK;
    float* Cs = (float*)sm_;
    int tid = threadIdx.x, wid = tid >> 5;
    int wm = (wid >> 2) * 32, wn = (wid & 3) * 16;
    size_t m0 = (size_t)blockIdx.y * 64;
    int n0 = blockIdx.x * 64;
    float c[2][2][4] = {};
    for (int k0 = 0; k0 < D; k0 += KC) {
        __syncthreads();
        stage_rows_sub(Ah, Al, x, m0, k0, g_mean[0]);
        stage_rows(Bh, Bl, g_mat[BT0], (size_t)n0, k0);  // M symmetric
        __syncthreads();
        mma_chunk(c, Ah, Al, Bh, Bl, wm, wn);
    }
    __syncthreads();
    frags_to_Cs(c, Cs, wm, wn);
    __syncthreads();
    int r = tid >> 2;
    #pragma unroll
    for (int q = 0; q < 4; q++) {
        int cc = (tid & 3) * 4 + q * 16;
        float4 v = *(float4*)&Cs[r * PC + cc];
        float4 mb = *(const float4*)&g_mean[2][n0 + cc];
        v.x += mb.x; v.y += mb.y; v.z += mb.z; v.w += mb.w;
        *(float4*)&out[(m0 + (size_t)r) * D + n0 + cc] = v;
    }
}

// ---------------- host orchestration ----------------
extern "C" void kernel_launch(void* const* d_in, const int* in_sizes, int n_in,
                              void* d_out, int out_size) {
    const float* content = (const float*)d_in[0];
    const float* style   = (const float*)d_in[1];
    float* out = (float*)d_out;

    colsum1_k<<<256, 256>>>(content);
    colsum2_k<<<1, D>>>(0);
    colsum1_k<<<256, 256>>>(style);
    colsum2_k<<<1, D>>>(1);
    mub_k<<<1, D>>>();

    xtx_mma_k<<<dim3(8, 8, SPLITS), 256, SMEM_SZ>>>(content);
    covfin_k<<<MATN / 256, 256>>>(COVC, 0);
    xtx_mma_k<<<dim3(8, 8, SPLITS), 256, SMEM_SZ>>>(style);
    covfin_k<<<MATN / 256, 256>>>(COVS, 1);

    persist_k<<<NCTA, 256, SMEM_SZ>>>();

    outgemm_mma_k<<<dim3(8, 1024), 256, SMEM_SZ>>>(content, out);

    (void)in_sizes; (void)n_in; (void)out_size;
}

// round 5
// speedup vs baseline: 5.1771x; 1.2814x over previous
#include <cuda_runtime.h>
#include <cuda_bf16.h>
#include <math.h>

#define D 512
#define NROWS 65536
#define MATN (D*D)
#define NS_ITERS 5
#define BARY_ITERS 16
#define SPLITS 32
#define CHUNK (NROWS/SPLITS)
#define NCTA 144
#define KC 64
#define PK 72
#define PC 68
#define PLANE (64*PK)
#define BUFHW (4*PLANE)
#define SMEM_DYN (2*BUFHW*2)   // 73,728 B: two 4-plane bf16 staging buffers

// ---------------- matrix buffer ids ----------------
enum {
  COVC=0, COVS, SIGB, BYA, BZA, BYB, BZB, BW0,
  BP0, BP1, BM0, BM1,
  YJ0A, YJ1A, ZJ0A, ZJ1A, YJ0B, YJ1B, ZJ0B, ZJ1B, WJ0, WJ1,
  BR0, BT0, NBUF
};

__device__ float g_mat[NBUF][MATN];
__device__ __nv_bfloat16 g_h[NBUF][MATN];
__device__ __nv_bfloat16 g_l[NBUF][MATN];
__device__ float g_covpart[SPLITS][MATN];
__device__ float g_meanpart[256][D];
__device__ float g_mean[3][D];
__device__ float g_scal[16];
__device__ __nv_bfloat16 g_xh[(size_t)NROWS * D];   // centered input, hi
__device__ __nv_bfloat16 g_xl[(size_t)NROWS * D];   // centered input, lo

// ---------------- grid-wide barrier ----------------
__device__ unsigned g_bar_cnt;
__device__ volatile unsigned g_bar_gen;

__device__ __forceinline__ void gridsync() {
    __syncthreads();
    if (threadIdx.x == 0) {
        __threadfence();
        unsigned gen = g_bar_gen;
        if (atomicAdd(&g_bar_cnt, 1u) == NCTA - 1u) {
            g_bar_cnt = 0u;
            __threadfence();
            g_bar_gen = gen + 1u;
        } else {
            while (g_bar_gen == gen) { }
        }
        __threadfence();
    }
    __syncthreads();
}

// ---------------- low-level helpers ----------------
__device__ __forceinline__ unsigned sm32(const void* p) {
    return (unsigned)__cvta_generic_to_shared(p);
}
__device__ __forceinline__ void cpa16(void* dst, const void* src) {
    asm volatile("cp.async.cg.shared.global [%0], [%1], 16;"
                 :: "r"(sm32(dst)), "l"(src));
}
__device__ __forceinline__ void cpa_commit() { asm volatile("cp.async.commit_group;"); }
template <int N>
__device__ __forceinline__ void cpa_wait() {
    asm volatile("cp.async.wait_group %0;" :: "n"(N));
}

__device__ __forceinline__ void ldsm4(unsigned r[4], const unsigned short* p) {
    asm volatile("ldmatrix.sync.aligned.m8n8.x4.shared.b16 {%0,%1,%2,%3}, [%4];"
                 : "=r"(r[0]), "=r"(r[1]), "=r"(r[2]), "=r"(r[3]) : "r"(sm32(p)));
}
__device__ __forceinline__ void ldsm4t(unsigned r[4], const unsigned short* p) {
    asm volatile("ldmatrix.sync.aligned.m8n8.x4.trans.shared.b16 {%0,%1,%2,%3}, [%4];"
                 : "=r"(r[0]), "=r"(r[1]), "=r"(r[2]), "=r"(r[3]) : "r"(sm32(p)));
}

__device__ __forceinline__ void mma16816(float c[4], const unsigned a[4],
                                         unsigned b0, unsigned b1) {
    asm volatile(
        "mma.sync.aligned.m16n8k16.row.col.f32.bf16.bf16.f32 "
        "{%0,%1,%2,%3}, {%4,%5,%6,%7}, {%8,%9}, {%0,%1,%2,%3};\n"
        : "+f"(c[0]), "+f"(c[1]), "+f"(c[2]), "+f"(c[3])
        : "r"(a[0]), "r"(a[1]), "r"(a[2]), "r"(a[3]), "r"(b0), "r"(b1));
}

__device__ __forceinline__ void split2(float x0, float x1, unsigned &h, unsigned &l) {
    __nv_bfloat162 hh = __floats2bfloat162_rn(x0, x1);
    float r0 = x0 - __low2float(hh);
    float r1 = x1 - __high2float(hh);
    __nv_bfloat162 ll = __floats2bfloat162_rn(r0, r1);
    h = *reinterpret_cast<unsigned*>(&hh);
    l = *reinterpret_cast<unsigned*>(&ll);
}
__device__ __forceinline__ void split1(float x, unsigned short &h, unsigned short &l) {
    __nv_bfloat16 hb = __float2bfloat16_rn(x);
    float r = x - __bfloat162float(hb);
    __nv_bfloat16 lb = __float2bfloat16_rn(r);
    h = *reinterpret_cast<unsigned short*>(&hb);
    l = *reinterpret_cast<unsigned short*>(&lb);
}

// ---------------- staging: 4 planes (Ah,Al,Bh,Bl), 64x64 bf16 each ------
__device__ __forceinline__ void stage_hl(unsigned short* sbuf,
    const __nv_bfloat16* AH, const __nv_bfloat16* AL,
    const __nv_bfloat16* BH, const __nv_bfloat16* BL,
    size_t aR, int aC, size_t bR, int bC)
{
    int t = threadIdx.x;
    int plane = t >> 6, row = t & 63;
    const __nv_bfloat16* base = (plane == 0) ? AH : (plane == 1) ? AL
                               : (plane == 2) ? BH : BL;
    size_t r = ((plane < 2) ? aR : bR) + row;
    int c0 = (plane < 2) ? aC : bC;
    const __nv_bfloat16* src = base + r * D + c0;
    unsigned short* dst = sbuf + plane * PLANE + row * PK;
    #pragma unroll
    for (int i = 0; i < 8; i++) cpa16(dst + i * 8, src + i * 8);
}

// ---------------- mma over one staged chunk ----------------
__device__ __forceinline__ void mma_planes(float c[2][2][4],
                                           const unsigned short* sbuf,
                                           int wm, int wn, int trans) {
    const unsigned short* Ah = sbuf;
    const unsigned short* Al = sbuf + PLANE;
    const unsigned short* Bh = sbuf + 2 * PLANE;
    const unsigned short* Bl = sbuf + 3 * PLANE;
    int l = threadIdx.x & 31;
    #pragma unroll
    for (int kb = 0; kb < KC; kb += 16) {
        unsigned ah0[4], ah1[4], al0[4], al1[4], bh[4], bl[4];
        if (!trans) {
            int ar = (l & 7) + ((l & 8) ? 8 : 0);
            int ac = kb + ((l & 16) ? 8 : 0);
            ldsm4(ah0, Ah + (wm + ar) * PK + ac);
            ldsm4(ah1, Ah + (wm + 16 + ar) * PK + ac);
            ldsm4(al0, Al + (wm + ar) * PK + ac);
            ldsm4(al1, Al + (wm + 16 + ar) * PK + ac);
            int br = wn + (l & 7) + ((l & 16) ? 8 : 0);
            int bc = kb + ((l & 8) ? 8 : 0);
            ldsm4(bh, Bh + br * PK + bc);
            ldsm4(bl, Bl + br * PK + bc);
        } else {
            int tr = kb + (l & 7) + ((l & 16) ? 8 : 0);
            int ac = wm + ((l & 8) ? 8 : 0);
            ldsm4t(ah0, Ah + tr * PK + ac);
            ldsm4t(ah1, Ah + tr * PK + ac + 16);
            ldsm4t(al0, Al + tr * PK + ac);
            ldsm4t(al1, Al + tr * PK + ac + 16);
            int br = kb + (l & 7) + ((l & 8) ? 8 : 0);
            int bc = wn + ((l & 16) ? 8 : 0);
            ldsm4t(bh, Bh + br * PK + bc);
            ldsm4t(bl, Bl + br * PK + bc);
        }
        mma16816(c[0][0], ah0, bh[0], bh[1]);
        mma16816(c[0][1], ah0, bh[2], bh[3]);
        mma16816(c[1][0], ah1, bh[0], bh[1]);
        mma16816(c[1][1], ah1, bh[2], bh[3]);
        mma16816(c[0][0], ah0, bl[0], bl[1]);
        mma16816(c[0][1], ah0, bl[2], bl[3]);
        mma16816(c[1][0], ah1, bl[0], bl[1]);
        mma16816(c[1][1], ah1, bl[2], bl[3]);
        mma16816(c[0][0], al0, bh[0], bh[1]);
        mma16816(c[0][1], al0, bh[2], bh[3]);
        mma16816(c[1][0], al1, bh[0], bh[1]);
        mma16816(c[1][1], al1, bh[2], bh[3]);
    }
}

__device__ __forceinline__ void frags_to_Cs(float c[2][2][4], float* Cs, int wm, int wn) {
    int l = threadIdx.x & 31;
    int rr = l >> 2, cc2 = (l & 3) * 2;
    #pragma unroll
    for (int mf = 0; mf < 2; mf++)
        #pragma unroll
        for (int nf = 0; nf < 2; nf++) {
            int r = wm + mf * 16 + rr, cc = wn + nf * 8 + cc2;
            *(float2*)&Cs[r * PC + cc]       = make_float2(c[mf][nf][0], c[mf][nf][1]);
            *(float2*)&Cs[(r + 8) * PC + cc] = make_float2(c[mf][nf][2], c[mf][nf][3]);
        }
}

// ---------------- pipelined 64x64 tile GEMM, K=512, prefab bf16 ---------
__device__ __noinline__ void tile_gemm_hl(
    const __nv_bfloat16* AH, const __nv_bfloat16* AL,
    const __nv_bfloat16* BH, const __nv_bfloat16* BL,
    float* C, __nv_bfloat16* CH, __nv_bfloat16* CL,
    int m0, int n0, float alpha, float betaI, int mirror)
{
    extern __shared__ unsigned short sm_u[];
    unsigned short* buf0 = sm_u;
    unsigned short* buf1 = sm_u + BUFHW;
    float* Cs = (float*)sm_u;
    int tid = threadIdx.x, wid = tid >> 5;
    int wm = (wid >> 2) * 32, wn = (wid & 3) * 16;
    float c[2][2][4] = {};
    stage_hl(buf0, AH, AL, BH, BL, (size_t)m0, 0, (size_t)n0, 0);
    cpa_commit();
    #pragma unroll 1
    for (int kc = 0; kc < 8; kc++) {
        unsigned short* cur = (kc & 1) ? buf1 : buf0;
        unsigned short* nxt = (kc & 1) ? buf0 : buf1;
        if (kc < 7) {
            stage_hl(nxt, AH, AL, BH, BL, (size_t)m0, (kc + 1) * KC,
                     (size_t)n0, (kc + 1) * KC);
            cpa_commit();
            cpa_wait<1>();
        } else {
            cpa_wait<0>();
        }
        __syncthreads();
        mma_planes(c, cur, wm, wn, 0);
        __syncthreads();
    }
    frags_to_Cs(c, Cs, wm, wn);
    __syncthreads();
    int r = tid >> 2;
    #pragma unroll
    for (int q = 0; q < 4; q++) {
        int cc = (tid & 3) * 4 + q * 16;
        float4 v = *(float4*)&Cs[r * PC + cc];
        int m = m0 + r, n = n0 + cc;
        float o[4] = {v.x * alpha, v.y * alpha, v.z * alpha, v.w * alpha};
        if (betaI != 0.f) {
            #pragma unroll
            for (int j = 0; j < 4; j++) if (m == n + j) o[j] += betaI;
        }
        *(float4*)&C[(size_t)m * D + n] = make_float4(o[0], o[1], o[2], o[3]);
        if (CH) {
            unsigned h0, l0, h1, l1;
            split2(o[0], o[1], h0, l0);
            split2(o[2], o[3], h1, l1);
            *(unsigned*)&CH[(size_t)m * D + n]     = h0;
            *(unsigned*)&CH[(size_t)m * D + n + 2] = h1;
            *(unsigned*)&CL[(size_t)m * D + n]     = l0;
            *(unsigned*)&CL[(size_t)m * D + n + 2] = l1;
        }
        if (mirror) {
            #pragma unroll
            for (int j = 0; j < 4; j++) {
                C[(size_t)(n + j) * D + m] = o[j];
                if (CH) {
                    unsigned short hh, ll;
                    split1(o[j], hh, ll);
                    *(unsigned short*)&CH[(size_t)(n + j) * D + m] = hh;
                    *(unsigned short*)&CL[(size_t)(n + j) * D + m] = ll;
                }
            }
        }
    }
}

// ---------------- phase runner (buffer ids) ----------------
__device__ __noinline__ void phase_gemm(int nj, const int* A, const int* B,
                                        const int* Cid, const float* al,
                                        float betaI, int sym, int hl) {
    int tpj = sym ? 36 : 64;
    int total = nj * tpj;
    for (int t = blockIdx.x; t < total; t += NCTA) {
        int j = t / tpj, tt = t - j * tpj;
        int mt, nt;
        if (sym) {
            int m = 0, r = tt;
            while (r >= 8 - m) { r -= 8 - m; m++; }
            mt = m; nt = m + r;
        } else { mt = tt >> 3; nt = tt & 7; }
        tile_gemm_hl(g_h[A[j]], g_l[A[j]], g_h[B[j]], g_l[B[j]],
                     g_mat[Cid[j]], hl ? g_h[Cid[j]] : ((__nv_bfloat16*)0),
                     hl ? g_l[Cid[j]] : ((__nv_bfloat16*)0),
                     mt * 64, nt * 64, al[j], betaI, sym && (mt != nt));
    }
}

// ---------------- small device helpers ----------------
__device__ __noinline__ void trace_prep(const float* __restrict__ A, int base,
                                        int withAlpha) {
    __shared__ float red[256];
    int t = threadIdx.x;
    red[t] = __ldcg(&A[(size_t)t * (D + 1)]) + __ldcg(&A[(size_t)(t + 256) * (D + 1)]);
    __syncthreads();
    for (int off = 128; off > 0; off >>= 1) {
        if (t < off) red[t] += red[t + off];
        __syncthreads();
    }
    if (t == 0) {
        float c = red[0] * (1.25f / 512.0f);
        g_scal[base] = c;
        g_scal[base + 1] = 1.0f / c;
        if (withAlpha) g_scal[base + 2] = sqrtf(c) / g_scal[0];
    }
}

__device__ __forceinline__ void ew_copy(float* dst, const float* src) {
    for (int i = blockIdx.x * 256 + threadIdx.x; i < MATN / 4; i += NCTA * 256)
        ((float4*)dst)[i] = __ldcg((const float4*)src + i);
}

__device__ __forceinline__ void ew_nsinit(int Yid, int Zid, const float* S, float invc) {
    float* Y = g_mat[Yid]; float* Z = g_mat[Zid];
    __nv_bfloat16 *Yh = g_h[Yid], *Yl = g_l[Yid], *Zh = g_h[Zid], *Zl = g_l[Zid];
    for (int i = blockIdx.x * 256 + threadIdx.x; i < MATN / 2; i += NCTA * 256) {
        int e = 2 * i;
        float a = __ldcg(&S[e]) * invc, b = __ldcg(&S[e + 1]) * invc;
        Y[e] = a; Y[e + 1] = b;
        unsigned h, l;
        split2(a, b, h, l);
        *(unsigned*)&Yh[e] = h; *(unsigned*)&Yl[e] = l;
        int m = e >> 9, n = e & 511;
        float z0 = (m == n) ? 1.f : 0.f, z1 = (m == n + 1) ? 1.f : 0.f;
        Z[e] = z0; Z[e + 1] = z1;
        split2(z0, z1, h, l);
        *(unsigned*)&Zh[e] = h; *(unsigned*)&Zl[e] = 0u;
    }
}

// V = a0*R0 + a1*R1 (fp32 + h/l)
__device__ __forceinline__ void ew_V(int Vid, const float* R0, const float* R1,
                                     float a0, float a1) {
    float* V = g_mat[Vid];
    __nv_bfloat16 *Vh = g_h[Vid], *Vl = g_l[Vid];
    for (int i = blockIdx.x * 256 + threadIdx.x; i < MATN / 2; i += NCTA * 256) {
        int e = 2 * i;
        float v0 = a0 * __ldcg(&R0[e]) + a1 * __ldcg(&R1[e]);
        float v1 = a0 * __ldcg(&R0[e + 1]) + a1 * __ldcg(&R1[e + 1]);
        V[e] = v0; V[e + 1] = v1;
        unsigned h, l;
        split2(v0, v1, h, l);
        *(unsigned*)&Vh[e] = h; *(unsigned*)&Vl[e] = l;
    }
}

// coupled Newton-Schulz for nb symmetric matrices (buffer ids)
__device__ __noinline__ void ns_run(int* y, int* z, int* yb, int* zb,
                                    const int* w, int nb) {
    int A[4], B[4], C[4]; float al[4];
    for (int s = 0; s < NS_ITERS; s++) {
        for (int j = 0; j < nb; j++) {
            A[j] = z[j]; B[j] = y[j]; C[j] = w[j]; al[j] = -0.5f;
        }
        phase_gemm(nb, A, B, C, al, 1.5f, 1, 1);
        gridsync();
        for (int j = 0; j < nb; j++) {
            A[2*j]   = y[j]; B[2*j]   = w[j]; C[2*j]   = yb[j]; al[2*j]   = 1.f;
            A[2*j+1] = w[j]; B[2*j+1] = z[j]; C[2*j+1] = zb[j]; al[2*j+1] = 1.f;
        }
        phase_gemm(2 * nb, A, B, C, al, 0.f, 1, 1);
        gridsync();
        for (int j = 0; j < nb; j++) {
            int t = y[j]; y[j] = yb[j]; yb[j] = t;
            t = z[j]; z[j] = zb[j]; zb[j] = t;
        }
    }
}

// ---------------- persistent barycenter kernel ----------------
__global__ __launch_bounds__(256, 1) void persist_k() {
    int y[2], z[2], yb[2], zb[2], w[2];
    int A[4], B[4], C[4]; float al[4];

    ew_copy(g_mat[SIGB], g_mat[COVC]);
    gridsync();

    for (int it = 0; it < BARY_ITERS; it++) {
        if (blockIdx.x == 0) trace_prep(g_mat[SIGB], 0, 0);
        gridsync();
        ew_nsinit(BYA, BZA, g_mat[SIGB], __ldcg(&g_scal[1]));
        gridsync();
        y[0] = BYA; z[0] = BZA; yb[0] = BYB; zb[0] = BZB; w[0] = BW0;
        ns_run(y, z, yb, zb, w, 1);
        int ys = y[0], zs = z[0];

        // P_j = Y @ cov_j (full)
        A[0] = ys; B[0] = COVC; C[0] = BP0; al[0] = 1.f;
        A[1] = ys; B[1] = COVS; C[1] = BP1; al[1] = 1.f;
        phase_gemm(2, A, B, C, al, 0.f, 0, 1);
        gridsync();
        // M_j = c * (P_j @ Y) (sym)
        float csig = __ldcg(&g_scal[0]);
        A[0] = BP0; B[0] = ys; C[0] = BM0; al[0] = csig;
        A[1] = BP1; B[1] = ys; C[1] = BM1; al[1] = csig;
        phase_gemm(2, A, B, C, al, 0.f, 1, 0);
        gridsync();

        if (blockIdx.x < 2) trace_prep(g_mat[BM0 + blockIdx.x], 4 + 4 * blockIdx.x, 1);
        gridsync();
        ew_nsinit(YJ0A, ZJ0A, g_mat[BM0], __ldcg(&g_scal[5]));
        ew_nsinit(YJ1A, ZJ1A, g_mat[BM1], __ldcg(&g_scal[9]));
        gridsync();
        y[0] = YJ0A; z[0] = ZJ0A; yb[0] = YJ0B; zb[0] = ZJ0B; w[0] = WJ0;
        y[1] = YJ1A; z[1] = ZJ1A; yb[1] = YJ1B; zb[1] = ZJ1B; w[1] = WJ1;
        ns_run(y, z, yb, zb, w, 2);

        // V = 0.5*(a0*Ym0 + a1*Ym1), a_j = sqrt(c_j)/c   (Sigma' = Z V Z)
        ew_V(BW0, g_mat[y[0]], g_mat[y[1]],
             0.5f * __ldcg(&g_scal[6]), 0.5f * __ldcg(&g_scal[10]));
        gridsync();
        // R = Z @ V (full)
        A[0] = zs; B[0] = BW0; C[0] = BR0; al[0] = 1.f;
        phase_gemm(1, A, B, C, al, 0.f, 0, 1);
        gridsync();
        // Sigma = R @ Z (sym)
        A[0] = BR0; B[0] = zs; C[0] = SIGB; al[0] = 1.f;
        phase_gemm(1, A, B, C, al, 0.f, 1, 1);
        gridsync();
    }

    // ---- final transform M = Sc^-1/2 (Sc^1/2 Sigma Sc^1/2)^1/2 Sc^-1/2 ----
    if (blockIdx.x == 0) trace_prep(g_mat[COVC], 0, 0);
    gridsync();
    ew_nsinit(BYA, BZA, g_mat[COVC], __ldcg(&g_scal[1]));
    gridsync();
    y[0] = BYA; z[0] = BZA; yb[0] = BYB; zb[0] = BZB; w[0] = BW0;
    ns_run(y, z, yb, zb, w, 1);
    int ys = y[0], zs = z[0];

    A[0] = ys; B[0] = SIGB; C[0] = BP0; al[0] = 1.f;
    phase_gemm(1, A, B, C, al, 0.f, 0, 1);
    gridsync();
    A[0] = BP0; B[0] = ys; C[0] = BM0; al[0] = __ldcg(&g_scal[0]);
    phase_gemm(1, A, B, C, al, 0.f, 1, 0);
    gridsync();
    if (blockIdx.x == 0) trace_prep(g_mat[BM0], 4, 1);
    gridsync();
    ew_nsinit(YJ0A, ZJ0A, g_mat[BM0], __ldcg(&g_scal[5]));
    gridsync();
    y[0] = YJ0A; z[0] = ZJ0A; yb[0] = YJ0B; zb[0] = ZJ0B; w[0] = WJ0;
    ns_run(y, z, yb, zb, w, 1);

    A[0] = zs; B[0] = y[0]; C[0] = BR0; al[0] = 1.f;
    phase_gemm(1, A, B, C, al, 0.f, 0, 1);
    gridsync();
    A[0] = BR0; B[0] = zs; C[0] = BT0; al[0] = __ldcg(&g_scal[6]);
    phase_gemm(1, A, B, C, al, 0.f, 1, 1);
}

// ---------------- column means ----------------
__global__ void colsum1_k(const float* __restrict__ x) {
    int cta = blockIdx.x, t = threadIdx.x;
    const float* base = x + (size_t)cta * 256 * D;
    float s0 = 0.f, s1 = 0.f;
    for (int r = 0; r < 256; r++) {
        s0 += base[(size_t)r * D + t];
        s1 += base[(size_t)r * D + t + 256];
    }
    g_meanpart[cta][t] = s0;
    g_meanpart[cta][t + 256] = s1;
}

__global__ void colsum2_k(int which) {
    int t = threadIdx.x;
    float s = 0.f;
    for (int i = 0; i < 256; i++) s += g_meanpart[i][t];
    g_mean[which][t] = s * (1.0f / NROWS);
}

__global__ void mub_k() {
    int t = threadIdx.x;
    g_mean[2][t] = 0.5f * (g_mean[0][t] + g_mean[1][t]);
}

// ---------------- center + split input: Xc = x - mu ----------------
__global__ __launch_bounds__(256) void center_k(const float* __restrict__ x,
                                                int meanIdx) {
    size_t i = (size_t)blockIdx.x * 256 + threadIdx.x;   // float4 index
    float4 v = *((const float4*)x + i);
    int col = (int)((i * 4) & 511);
    float4 mu = *(const float4*)&g_mean[meanIdx][col];
    unsigned h0, l0, h1, l1;
    split2(v.x - mu.x, v.y - mu.y, h0, l0);
    split2(v.z - mu.z, v.w - mu.w, h1, l1);
    *(unsigned*)&g_xh[i * 4]     = h0;
    *(unsigned*)&g_xh[i * 4 + 2] = h1;
    *(unsigned*)&g_xl[i * 4]     = l0;
    *(unsigned*)&g_xl[i * 4 + 2] = l1;
}

// ---------------- Xc^T Xc partials (K-major staging, trans ldmatrix) ----
__global__ __launch_bounds__(256) void xtx_k(int dummy) {
    if (blockIdx.y > blockIdx.x) return;
    extern __shared__ unsigned short sm_u[];
    unsigned short* buf0 = sm_u;
    unsigned short* buf1 = sm_u + BUFHW;
    float* Cs = (float*)sm_u;
    int tid = threadIdx.x, wid = tid >> 5;
    int wm = (wid >> 2) * 32, wn = (wid & 3) * 16;
    int m0 = blockIdx.y * 64, n0 = blockIdx.x * 64;
    size_t r0 = (size_t)blockIdx.z * CHUNK;
    const int NCH = CHUNK / KC;   // 32
    float c[2][2][4] = {};
    stage_hl(buf0, g_xh, g_xl, g_xh, g_xl, r0, m0, r0, n0);
    cpa_commit();
    #pragma unroll 1
    for (int kc = 0; kc < NCH; kc++) {
        unsigned short* cur = (kc & 1) ? buf1 : buf0;
        unsigned short* nxt = (kc & 1) ? buf0 : buf1;
        if (kc < NCH - 1) {
            stage_hl(nxt, g_xh, g_xl, g_xh, g_xl,
                     r0 + (kc + 1) * KC, m0, r0 + (kc + 1) * KC, n0);
            cpa_commit();
            cpa_wait<1>();
        } else {
            cpa_wait<0>();
        }
        __syncthreads();
        mma_planes(c, cur, wm, wn, 1);
        __syncthreads();
    }
    frags_to_Cs(c, Cs, wm, wn);
    __syncthreads();
    float* Cp = g_covpart[blockIdx.z];
    int r = tid >> 2;
    #pragma unroll
    for (int q = 0; q < 4; q++) {
        int cc = (tid & 3) * 4 + q * 16;
        float4 v = *(float4*)&Cs[r * PC + cc];
        *(float4*)&Cp[(m0 + r) * D + n0 + cc] = v;
    }
}

__global__ void covfin_k(int covIdx) {
    int idx = blockIdx.x * 256 + threadIdx.x;
    int m = idx >> 9, n = idx & 511;
    int ms = m, ns = n;
    if ((m >> 6) > (n >> 6)) { ms = n; ns = m; }
    float s = 0.f;
    #pragma unroll 8
    for (int p = 0; p < SPLITS; p++) s += g_covpart[p][ms * D + ns];
    float v = s * (1.0f / (NROWS - 1));
    g_mat[covIdx][idx] = v;
    unsigned short h, l;
    split1(v, h, l);
    *(unsigned short*)&g_h[covIdx][idx] = h;
    *(unsigned short*)&g_l[covIdx][idx] = l;
}

// ---------------- output GEMM: out = Xc @ M + mu_b  (M symmetric) -------
__global__ __launch_bounds__(256) void outgemm_k(float* __restrict__ out) {
    extern __shared__ unsigned short sm_u[];
    unsigned short* buf0 = sm_u;
    unsigned short* buf1 = sm_u + BUFHW;
    float* Cs = (float*)sm_u;
    int tid = threadIdx.x, wid = tid >> 5;
    int wm = (wid >> 2) * 32, wn = (wid & 3) * 16;
    size_t m0 = (size_t)blockIdx.y * 64;
    int n0 = blockIdx.x * 64;
    float c[2][2][4] = {};
    stage_hl(buf0, g_xh, g_xl, g_h[BT0], g_l[BT0], m0, 0, (size_t)n0, 0);
    cpa_commit();
    #pragma unroll 1
    for (int kc = 0; kc < 8; kc++) {
        unsigned short* cur = (kc & 1) ? buf1 : buf0;
        unsigned short* nxt = (kc & 1) ? buf0 : buf1;
        if (kc < 7) {
            stage_hl(nxt, g_xh, g_xl, g_h[BT0], g_l[BT0],
                     m0, (kc + 1) * KC, (size_t)n0, (kc + 1) * KC);
            cpa_commit();
            cpa_wait<1>();
        } else {
            cpa_wait<0>();
        }
        __syncthreads();
        mma_planes(c, cur, wm, wn, 0);
        __syncthreads();
    }
    frags_to_Cs(c, Cs, wm, wn);
    __syncthreads();
    int r = tid >> 2;
    #pragma unroll
    for (int q = 0; q < 4; q++) {
        int cc = (tid & 3) * 4 + q * 16;
        float4 v = *(float4*)&Cs[r * PC + cc];
        float4 mb = *(const float4*)&g_mean[2][n0 + cc];
        v.x += mb.x; v.y += mb.y; v.z += mb.z; v.w += mb.w;
        *(float4*)&out[(m0 + (size_t)r) * D + n0 + cc] = v;
    }
}

// ---------------- host orchestration ----------------
extern "C" void kernel_launch(void* const* d_in, const int* in_sizes, int n_in,
                              void* d_out, int out_size) {
    const float* content = (const float*)d_in[0];
    const float* style   = (const float*)d_in[1];
    float* out = (float*)d_out;

    cudaFuncSetAttribute(persist_k, cudaFuncAttributeMaxDynamicSharedMemorySize, SMEM_DYN);
    cudaFuncSetAttribute(xtx_k, cudaFuncAttributeMaxDynamicSharedMemorySize, SMEM_DYN);
    cudaFuncSetAttribute(outgemm_k, cudaFuncAttributeMaxDynamicSharedMemorySize, SMEM_DYN);

    // means
    colsum1_k<<<256, 256>>>(content);
    colsum2_k<<<1, D>>>(0);
    colsum1_k<<<256, 256>>>(style);
    colsum2_k<<<1, D>>>(1);
    mub_k<<<1, D>>>();

    // style first (Xc buffer reused), then content (left in place for outgemm)
    center_k<<<NROWS * D / 4 / 256, 256>>>(style, 1);
    xtx_k<<<dim3(8, 8, SPLITS), 256, SMEM_DYN>>>(0);
    covfin_k<<<MATN / 256, 256>>>(COVS);

    center_k<<<NROWS * D / 4 / 256, 256>>>(content, 0);
    xtx_k<<<dim3(8, 8, SPLITS), 256, SMEM_DYN>>>(0);
    covfin_k<<<MATN / 256, 256>>>(COVC);

    persist_k<<<NCTA, 256, SMEM_DYN>>>();

    outgemm_k<<<dim3(8, 1024), 256, SMEM_DYN>>>(out);

    (void)in_sizes; (void)n_in; (void)out_size;
}

// round 6
// speedup vs baseline: 10.1942x; 1.9691x over previous
#include <cuda_runtime.h>
#include <cuda_bf16.h>
#include <math.h>

#define D 512
#define NROWS 65536
#define MATN (D*D)
#define NS_REST 3            // total NS iterations = 1 (analytic) + NS_REST
#define BARY_ITERS 8
#define SPLITS 32
#define CHUNK (NROWS/SPLITS)
#define NCTA 148
#define KC 64
#define PK 72
#define PC 68
#define PLANE (64*PK)
#define BUFHW (4*PLANE)
#define SMEM_DYN (2*BUFHW*2)   // 73,728 B

// ---------------- matrix buffer ids ----------------
enum {
  COVC=0, COVS, SIGB, BYA, BZA, BYB, BZB, BW0,
  BP0, BP1, BM0, BM1,
  YJ0A, YJ1A, ZJ0A, ZJ1A, YJ0B, YJ1B, ZJ0B, ZJ1B, WJ0, WJ1,
  BR0, BT0, NBUF
};

__device__ float g_mat[NBUF][MATN];
__device__ __nv_bfloat16 g_h[NBUF][MATN];
__device__ __nv_bfloat16 g_l[NBUF][MATN];
__device__ float g_covpart[2*SPLITS][MATN];
__device__ float g_meanpart[512][D];
__device__ float g_mean[3][D];
__device__ float g_tr[5][8];     // trace partials: 0=Sigma, 1=M0, 2=M1, 4=COVC
__device__ __nv_bfloat16 g_xch[(size_t)NROWS * D];  // centered content hi
__device__ __nv_bfloat16 g_xcl[(size_t)NROWS * D];  // centered content lo
__device__ __nv_bfloat16 g_xsh[(size_t)NROWS * D];  // centered style hi
__device__ __nv_bfloat16 g_xsl[(size_t)NROWS * D];  // centered style lo

// ---------------- grid-wide barrier ----------------
__device__ unsigned g_bar_cnt;
__device__ volatile unsigned g_bar_gen;

__device__ __forceinline__ void gridsync() {
    __syncthreads();
    if (threadIdx.x == 0) {
        __threadfence();
        unsigned gen = g_bar_gen;
        if (atomicAdd(&g_bar_cnt, 1u) == NCTA - 1u) {
            g_bar_cnt = 0u;
            __threadfence();
            g_bar_gen = gen + 1u;
        } else {
            while (g_bar_gen == gen) { }
        }
        __threadfence();
    }
    __syncthreads();
}

// ---------------- low-level helpers ----------------
__device__ __forceinline__ unsigned sm32(const void* p) {
    return (unsigned)__cvta_generic_to_shared(p);
}
__device__ __forceinline__ void cpa16(void* dst, const void* src) {
    asm volatile("cp.async.cg.shared.global [%0], [%1], 16;"
                 :: "r"(sm32(dst)), "l"(src));
}
__device__ __forceinline__ void cpa_commit() { asm volatile("cp.async.commit_group;"); }
template <int N>
__device__ __forceinline__ void cpa_wait() {
    asm volatile("cp.async.wait_group %0;" :: "n"(N));
}
__device__ __forceinline__ void ldsm4(unsigned r[4], const unsigned short* p) {
    asm volatile("ldmatrix.sync.aligned.m8n8.x4.shared.b16 {%0,%1,%2,%3}, [%4];"
                 : "=r"(r[0]), "=r"(r[1]), "=r"(r[2]), "=r"(r[3]) : "r"(sm32(p)));
}
__device__ __forceinline__ void ldsm4t(unsigned r[4], const unsigned short* p) {
    asm volatile("ldmatrix.sync.aligned.m8n8.x4.trans.shared.b16 {%0,%1,%2,%3}, [%4];"
                 : "=r"(r[0]), "=r"(r[1]), "=r"(r[2]), "=r"(r[3]) : "r"(sm32(p)));
}
__device__ __forceinline__ void mma16816(float c[4], const unsigned a[4],
                                         unsigned b0, unsigned b1) {
    asm volatile(
        "mma.sync.aligned.m16n8k16.row.col.f32.bf16.bf16.f32 "
        "{%0,%1,%2,%3}, {%4,%5,%6,%7}, {%8,%9}, {%0,%1,%2,%3};\n"
        : "+f"(c[0]), "+f"(c[1]), "+f"(c[2]), "+f"(c[3])
        : "r"(a[0]), "r"(a[1]), "r"(a[2]), "r"(a[3]), "r"(b0), "r"(b1));
}
__device__ __forceinline__ void split2(float x0, float x1, unsigned &h, unsigned &l) {
    __nv_bfloat162 hh = __floats2bfloat162_rn(x0, x1);
    float r0 = x0 - __low2float(hh);
    float r1 = x1 - __high2float(hh);
    __nv_bfloat162 ll = __floats2bfloat162_rn(r0, r1);
    h = *reinterpret_cast<unsigned*>(&hh);
    l = *reinterpret_cast<unsigned*>(&ll);
}
__device__ __forceinline__ void split1(float x, unsigned short &h, unsigned short &l) {
    __nv_bfloat16 hb = __float2bfloat16_rn(x);
    float r = x - __bfloat162float(hb);
    __nv_bfloat16 lb = __float2bfloat16_rn(r);
    h = *reinterpret_cast<unsigned short*>(&hb);
    l = *reinterpret_cast<unsigned short*>(&lb);
}

__device__ __forceinline__ float get_c(int slot) {
    float s = 0.f;
    #pragma unroll
    for (int i = 0; i < 8; i++) s += __ldcg(&g_tr[slot][i]);
    return s * (1.25f / 512.0f);
}

// ---------------- staging ----------------
__device__ __forceinline__ void stage_hl(unsigned short* sbuf,
    const __nv_bfloat16* AH, const __nv_bfloat16* AL,
    const __nv_bfloat16* BH, const __nv_bfloat16* BL,
    size_t aR, int aC, size_t bR, int bC)
{
    int t = threadIdx.x;
    int plane = t >> 6, row = t & 63;
    const __nv_bfloat16* base = (plane == 0) ? AH : (plane == 1) ? AL
                               : (plane == 2) ? BH : BL;
    size_t r = ((plane < 2) ? aR : bR) + row;
    int c0 = (plane < 2) ? aC : bC;
    const __nv_bfloat16* src = base + r * D + c0;
    unsigned short* dst = sbuf + plane * PLANE + row * PK;
    #pragma unroll
    for (int i = 0; i < 8; i++) cpa16(dst + i * 8, src + i * 8);
}

// ---------------- mma over one staged chunk ----------------
__device__ __forceinline__ void mma_planes(float c[2][2][4],
                                           const unsigned short* sbuf,
                                           int wm, int wn, int trans) {
    const unsigned short* Ah = sbuf;
    const unsigned short* Al = sbuf + PLANE;
    const unsigned short* Bh = sbuf + 2 * PLANE;
    const unsigned short* Bl = sbuf + 3 * PLANE;
    int l = threadIdx.x & 31;
    #pragma unroll
    for (int kb = 0; kb < KC; kb += 16) {
        unsigned ah0[4], ah1[4], al0[4], al1[4], bh[4], bl[4];
        if (!trans) {
            int ar = (l & 7) + ((l & 8) ? 8 : 0);
            int ac = kb + ((l & 16) ? 8 : 0);
            ldsm4(ah0, Ah + (wm + ar) * PK + ac);
            ldsm4(ah1, Ah + (wm + 16 + ar) * PK + ac);
            ldsm4(al0, Al + (wm + ar) * PK + ac);
            ldsm4(al1, Al + (wm + 16 + ar) * PK + ac);
            int br = wn + (l & 7) + ((l & 16) ? 8 : 0);
            int bc = kb + ((l & 8) ? 8 : 0);
            ldsm4(bh, Bh + br * PK + bc);
            ldsm4(bl, Bl + br * PK + bc);
        } else {
            int tr = kb + (l & 7) + ((l & 16) ? 8 : 0);
            int ac = wm + ((l & 8) ? 8 : 0);
            ldsm4t(ah0, Ah + tr * PK + ac);
            ldsm4t(ah1, Ah + tr * PK + ac + 16);
            ldsm4t(al0, Al + tr * PK + ac);
            ldsm4t(al1, Al + tr * PK + ac + 16);
            int br = kb + (l & 7) + ((l & 8) ? 8 : 0);
            int bc = wn + ((l & 16) ? 8 : 0);
            ldsm4t(bh, Bh + br * PK + bc);
            ldsm4t(bl, Bl + br * PK + bc);
        }
        mma16816(c[0][0], ah0, bh[0], bh[1]);
        mma16816(c[0][1], ah0, bh[2], bh[3]);
        mma16816(c[1][0], ah1, bh[0], bh[1]);
        mma16816(c[1][1], ah1, bh[2], bh[3]);
        mma16816(c[0][0], ah0, bl[0], bl[1]);
        mma16816(c[0][1], ah0, bl[2], bl[3]);
        mma16816(c[1][0], ah1, bl[0], bl[1]);
        mma16816(c[1][1], ah1, bl[2], bl[3]);
        mma16816(c[0][0], al0, bh[0], bh[1]);
        mma16816(c[0][1], al0, bh[2], bh[3]);
        mma16816(c[1][0], al1, bh[0], bh[1]);
        mma16816(c[1][1], al1, bh[2], bh[3]);
    }
}

__device__ __forceinline__ void frags_to_Cs(float c[2][2][4], float* Cs, int wm, int wn) {
    int l = threadIdx.x & 31;
    int rr = l >> 2, cc2 = (l & 3) * 2;
    #pragma unroll
    for (int mf = 0; mf < 2; mf++)
        #pragma unroll
        for (int nf = 0; nf < 2; nf++) {
            int r = wm + mf * 16 + rr, cc = wn + nf * 8 + cc2;
            *(float2*)&Cs[r * PC + cc]       = make_float2(c[mf][nf][0], c[mf][nf][1]);
            *(float2*)&Cs[(r + 8) * PC + cc] = make_float2(c[mf][nf][2], c[mf][nf][3]);
        }
}

// full K=512 pipelined mma into accumulators + Cs
__device__ __forceinline__ void run_tile(float c[2][2][4],
    const __nv_bfloat16* AH, const __nv_bfloat16* AL,
    const __nv_bfloat16* BH, const __nv_bfloat16* BL,
    int m0, int n0, unsigned short* sm_u)
{
    unsigned short* buf0 = sm_u;
    unsigned short* buf1 = sm_u + BUFHW;
    int wid = threadIdx.x >> 5;
    int wm = (wid >> 2) * 32, wn = (wid & 3) * 16;
    stage_hl(buf0, AH, AL, BH, BL, (size_t)m0, 0, (size_t)n0, 0);
    cpa_commit();
    #pragma unroll 1
    for (int kc = 0; kc < 8; kc++) {
        unsigned short* cur = (kc & 1) ? buf1 : buf0;
        unsigned short* nxt = (kc & 1) ? buf0 : buf1;
        if (kc < 7) {
            stage_hl(nxt, AH, AL, BH, BL, (size_t)m0, (kc + 1) * KC,
                     (size_t)n0, (kc + 1) * KC);
            cpa_commit();
            cpa_wait<1>();
        } else {
            cpa_wait<0>();
        }
        __syncthreads();
        mma_planes(c, cur, wm, wn, 0);
        __syncthreads();
    }
    frags_to_Cs(c, (float*)sm_u, wm, wn);
    __syncthreads();
}

// ---------------- generic tile GEMM with h/l + trace epilogue -----------
__device__ __noinline__ void tile_gemm(int Aid, int Bid, int Cid,
                                       int m0, int n0, float alpha, float betaI,
                                       int mirror, int trSlot)
{
    extern __shared__ unsigned short sm_u[];
    float* Cs = (float*)sm_u;
    int tid = threadIdx.x;
    float c[2][2][4] = {};
    run_tile(c, g_h[Aid], g_l[Aid], g_h[Bid], g_l[Bid], m0, n0, sm_u);
    float* C = g_mat[Cid];
    __nv_bfloat16* CH = g_h[Cid];
    __nv_bfloat16* CL = g_l[Cid];
    int r = tid >> 2;
    float dsum = 0.f;
    #pragma unroll
    for (int q = 0; q < 4; q++) {
        int cc = (tid & 3) * 4 + q * 16;
        float4 v = *(float4*)&Cs[r * PC + cc];
        int m = m0 + r, n = n0 + cc;
        float o[4] = {v.x * alpha, v.y * alpha, v.z * alpha, v.w * alpha};
        #pragma unroll
        for (int j = 0; j < 4; j++) {
            if (m == n + j) { o[j] += betaI; dsum += o[j]; }
        }
        *(float4*)&C[(size_t)m * D + n] = make_float4(o[0], o[1], o[2], o[3]);
        unsigned h0, l0, h1, l1;
        split2(o[0], o[1], h0, l0);
        split2(o[2], o[3], h1, l1);
        *(unsigned*)&CH[(size_t)m * D + n]     = h0;
        *(unsigned*)&CH[(size_t)m * D + n + 2] = h1;
        *(unsigned*)&CL[(size_t)m * D + n]     = l0;
        *(unsigned*)&CL[(size_t)m * D + n + 2] = l1;
        if (mirror) {
            #pragma unroll
            for (int j = 0; j < 4; j++) {
                C[(size_t)(n + j) * D + m] = o[j];
                unsigned short hh, ll;
                split1(o[j], hh, ll);
                *(unsigned short*)&CH[(size_t)(n + j) * D + m] = hh;
                *(unsigned short*)&CL[(size_t)(n + j) * D + m] = ll;
            }
        }
    }
    if (trSlot >= 0) {
        __syncthreads();
        float* red = (float*)sm_u;
        red[tid] = dsum;
        __syncthreads();
        for (int off = 128; off > 0; off >>= 1) {
            if (tid < off) red[tid] += red[tid + off];
            __syncthreads();
        }
        if (tid == 0) g_tr[trSlot][m0 >> 6] = red[0];
    }
}

// ---------------- analytic NS iteration 1: Y1 = 1.5A - 0.5A^2, Z1 = 1.5I-0.5A
__device__ __noinline__ void tile_yz1(int Sid, int Yid, int Zid, float cNorm,
                                      int m0, int n0, int mirror)
{
    extern __shared__ unsigned short sm_u[];
    float* Cs = (float*)sm_u;
    int tid = threadIdx.x;
    float c[2][2][4] = {};
    run_tile(c, g_h[Sid], g_l[Sid], g_h[Sid], g_l[Sid], m0, n0, sm_u);
    float ic = 1.0f / cNorm;
    float a1 = 1.5f * ic, a2 = 0.5f * ic * ic, a3 = 0.5f * ic;
    const float* S = g_mat[Sid];
    float* Y = g_mat[Yid]; __nv_bfloat16 *Yh = g_h[Yid], *Yl = g_l[Yid];
    float* Z = g_mat[Zid]; __nv_bfloat16 *Zh = g_h[Zid], *Zl = g_l[Zid];
    int r = tid >> 2;
    #pragma unroll
    for (int q = 0; q < 4; q++) {
        int cc = (tid & 3) * 4 + q * 16;
        int m = m0 + r, n = n0 + cc;
        float4 g = *(float4*)&Cs[r * PC + cc];
        float4 s = __ldcg((const float4*)&S[(size_t)m * D + n]);
        float yv[4] = {s.x * a1 - g.x * a2, s.y * a1 - g.y * a2,
                       s.z * a1 - g.z * a2, s.w * a1 - g.w * a2};
        float sv[4] = {s.x, s.y, s.z, s.w};
        float zv[4];
        #pragma unroll
        for (int j = 0; j < 4; j++)
            zv[j] = ((m == n + j) ? 1.5f : 0.f) - sv[j] * a3;
        *(float4*)&Y[(size_t)m * D + n] = make_float4(yv[0], yv[1], yv[2], yv[3]);
        *(float4*)&Z[(size_t)m * D + n] = make_float4(zv[0], zv[1], zv[2], zv[3]);
        unsigned h0, l0, h1, l1;
        split2(yv[0], yv[1], h0, l0); split2(yv[2], yv[3], h1, l1);
        *(unsigned*)&Yh[(size_t)m * D + n] = h0; *(unsigned*)&Yh[(size_t)m * D + n + 2] = h1;
        *(unsigned*)&Yl[(size_t)m * D + n] = l0; *(unsigned*)&Yl[(size_t)m * D + n + 2] = l1;
        split2(zv[0], zv[1], h0, l0); split2(zv[2], zv[3], h1, l1);
        *(unsigned*)&Zh[(size_t)m * D + n] = h0; *(unsigned*)&Zh[(size_t)m * D + n + 2] = h1;
        *(unsigned*)&Zl[(size_t)m * D + n] = l0; *(unsigned*)&Zl[(size_t)m * D + n + 2] = l1;
        if (mirror) {
            #pragma unroll
            for (int j = 0; j < 4; j++) {
                Y[(size_t)(n + j) * D + m] = yv[j];
                Z[(size_t)(n + j) * D + m] = zv[j];
                unsigned short hh, ll;
                split1(yv[j], hh, ll);
                *(unsigned short*)&Yh[(size_t)(n + j) * D + m] = hh;
                *(unsigned short*)&Yl[(size_t)(n + j) * D + m] = ll;
                split1(zv[j], hh, ll);
                *(unsigned short*)&Zh[(size_t)(n + j) * D + m] = hh;
                *(unsigned short*)&Zl[(size_t)(n + j) * D + m] = ll;
            }
        }
    }
}

// ---------------- phase runners ----------------
__device__ __forceinline__ void sym_decode(int tt, int &mt, int &nt) {
    int m = 0, r = tt;
    while (r >= 8 - m) { r -= 8 - m; m++; }
    mt = m; nt = m + r;
}

__device__ __noinline__ void phase_gemm(int nj, const int* A, const int* B,
                                        const int* Cid, const float* al,
                                        float betaI, int sym, int tr0) {
    int tpj = sym ? 36 : 64;
    int total = nj * tpj;
    for (int t = blockIdx.x; t < total; t += NCTA) {
        int j = t / tpj, tt = t - j * tpj;
        int mt, nt;
        if (sym) sym_decode(tt, mt, nt);
        else { mt = tt >> 3; nt = tt & 7; }
        int trSlot = (tr0 >= 0 && mt == nt) ? tr0 + j : -1;
        tile_gemm(A[j], B[j], Cid[j], mt * 64, nt * 64, al[j], betaI,
                  sym && (mt != nt), trSlot);
    }
}

__device__ __noinline__ void phase_yz1(int nb, const int* Sid, const int* Yid,
                                       const int* Zid, const float* cs) {
    int total = nb * 36;
    for (int t = blockIdx.x; t < total; t += NCTA) {
        int j = t / 36, tt = t - j * 36;
        int mt, nt;
        sym_decode(tt, mt, nt);
        tile_yz1(Sid[j], Yid[j], Zid[j], cs[j], mt * 64, nt * 64, mt != nt);
    }
}

// ---------------- small device helpers ----------------
__device__ __noinline__ void trace_prep_covc() {
    __shared__ float red[256];
    int t = threadIdx.x;
    red[t] = __ldcg(&g_mat[COVC][(size_t)t * (D + 1)])
           + __ldcg(&g_mat[COVC][(size_t)(t + 256) * (D + 1)]);
    __syncthreads();
    for (int off = 128; off > 0; off >>= 1) {
        if (t < off) red[t] += red[t + off];
        __syncthreads();
    }
    if (t == 0) {
        g_tr[0][0] = red[0]; g_tr[4][0] = red[0];
        for (int i = 1; i < 8; i++) { g_tr[0][i] = 0.f; g_tr[4][i] = 0.f; }
    }
}

// V = a0*R0 + a1*R1 (fp32 + h/l)
__device__ __forceinline__ void ew_V(int Vid, const float* R0, const float* R1,
                                     float a0, float a1) {
    float* V = g_mat[Vid];
    __nv_bfloat16 *Vh = g_h[Vid], *Vl = g_l[Vid];
    for (int i = blockIdx.x * 256 + threadIdx.x; i < MATN / 2; i += NCTA * 256) {
        int e = 2 * i;
        float v0 = a0 * __ldcg(&R0[e]) + a1 * __ldcg(&R1[e]);
        float v1 = a0 * __ldcg(&R0[e + 1]) + a1 * __ldcg(&R1[e + 1]);
        V[e] = v0; V[e + 1] = v1;
        unsigned h, l;
        split2(v0, v1, h, l);
        *(unsigned*)&Vh[e] = h; *(unsigned*)&Vl[e] = l;
    }
}

// NS iterations 2..: phase1 W=1.5I-0.5ZY; phase2 Y'=YW, Z'=WZ
__device__ __noinline__ void ns_rest(int* y, int* z, int* yb, int* zb,
                                     const int* w, int nb) {
    int A[4], B[4], C[4]; float al[4];
    for (int s = 0; s < NS_REST; s++) {
        for (int j = 0; j < nb; j++) {
            A[j] = z[j]; B[j] = y[j]; C[j] = w[j]; al[j] = -0.5f;
        }
        phase_gemm(nb, A, B, C, al, 1.5f, 1, -1);
        gridsync();
        for (int j = 0; j < nb; j++) {
            A[2*j]   = y[j]; B[2*j]   = w[j]; C[2*j]   = yb[j]; al[2*j]   = 1.f;
            A[2*j+1] = w[j]; B[2*j+1] = z[j]; C[2*j+1] = zb[j]; al[2*j+1] = 1.f;
        }
        phase_gemm(2 * nb, A, B, C, al, 0.f, 1, -1);
        gridsync();
        for (int j = 0; j < nb; j++) {
            int t = y[j]; y[j] = yb[j]; yb[j] = t;
            t = z[j]; z[j] = zb[j]; zb[j] = t;
        }
    }
}

// ---------------- persistent barycenter kernel ----------------
__global__ __launch_bounds__(256, 1) void persist_k() {
    int A[4], B[4], C[4]; float al[4];
    int S2[2], Y2[2], Z2[2]; float cs2[2];

    if (blockIdx.x == 0) trace_prep_covc();
    gridsync();

    for (int it = 0; it < BARY_ITERS; it++) {
        int Sid = (it == 0) ? COVC : SIGB;
        float c = get_c(0);
        // merged NS iteration 1 for Sigma
        S2[0] = Sid; Y2[0] = BYA; Z2[0] = BZA; cs2[0] = c;
        phase_yz1(1, S2, Y2, Z2, cs2);
        gridsync();
        int y1[1] = {BYA}, z1[1] = {BZA}, yb1[1] = {BYB}, zb1[1] = {BZB};
        int w1[1] = {BW0};
        ns_rest(y1, z1, yb1, zb1, w1, 1);
        int ys = y1[0], zs = z1[0];

        // P_j = Y @ cov_j (full)
        A[0] = ys; B[0] = COVC; C[0] = BP0; al[0] = 1.f;
        A[1] = ys; B[1] = COVS; C[1] = BP1; al[1] = 1.f;
        phase_gemm(2, A, B, C, al, 0.f, 0, -1);
        gridsync();
        // M_j = c * (P_j @ Y) (sym, traces -> slots 1,2)
        A[0] = BP0; B[0] = ys; C[0] = BM0; al[0] = c;
        A[1] = BP1; B[1] = ys; C[1] = BM1; al[1] = c;
        phase_gemm(2, A, B, C, al, 0.f, 1, 1);
        gridsync();

        float c0 = get_c(1), c1 = get_c(2);
        // merged NS iteration 1 for middles
        S2[0] = BM0; Y2[0] = YJ0A; Z2[0] = ZJ0A; cs2[0] = c0;
        S2[1] = BM1; Y2[1] = YJ1A; Z2[1] = ZJ1A; cs2[1] = c1;
        phase_yz1(2, S2, Y2, Z2, cs2);
        gridsync();
        int y2[2] = {YJ0A, YJ1A}, z2[2] = {ZJ0A, ZJ1A};
        int yb2[2] = {YJ0B, YJ1B}, zb2[2] = {ZJ0B, ZJ1B}, w2[2] = {WJ0, WJ1};
        ns_rest(y2, z2, yb2, zb2, w2, 2);

        // V = 0.5*(sqrt(c0)*Ym0 + sqrt(c1)*Ym1)/c
        ew_V(BW0, g_mat[y2[0]], g_mat[y2[1]],
             0.5f * sqrtf(c0) / c, 0.5f * sqrtf(c1) / c);
        gridsync();
        // R = Z @ V (full)
        A[0] = zs; B[0] = BW0; C[0] = BR0; al[0] = 1.f;
        phase_gemm(1, A, B, C, al, 0.f, 0, -1);
        gridsync();
        // Sigma = R @ Z (sym, trace -> slot 0)
        A[0] = BR0; B[0] = zs; C[0] = SIGB; al[0] = 1.f;
        phase_gemm(1, A, B, C, al, 0.f, 1, 0);
        gridsync();
    }

    // ---- final transform M = Sc^-1/2 (Sc^1/2 Sigma Sc^1/2)^1/2 Sc^-1/2 ----
    float cc = get_c(4);
    S2[0] = COVC; Y2[0] = BYA; Z2[0] = BZA; cs2[0] = cc;
    phase_yz1(1, S2, Y2, Z2, cs2);
    gridsync();
    int y1[1] = {BYA}, z1[1] = {BZA}, yb1[1] = {BYB}, zb1[1] = {BZB};
    int w1[1] = {BW0};
    ns_rest(y1, z1, yb1, zb1, w1, 1);
    int ys = y1[0], zs = z1[0];

    A[0] = ys; B[0] = SIGB; C[0] = BP0; al[0] = 1.f;
    phase_gemm(1, A, B, C, al, 0.f, 0, -1);
    gridsync();
    A[0] = BP0; B[0] = ys; C[0] = BM0; al[0] = cc;
    phase_gemm(1, A, B, C, al, 0.f, 1, 1);
    gridsync();
    float cm = get_c(1);
    S2[0] = BM0; Y2[0] = YJ0A; Z2[0] = ZJ0A; cs2[0] = cm;
    phase_yz1(1, S2, Y2, Z2, cs2);
    gridsync();
    int ym1[1] = {YJ0A}, zm1[1] = {ZJ0A}, ymb[1] = {YJ0B}, zmb[1] = {ZJ0B};
    int wm1[1] = {WJ0};
    ns_rest(ym1, zm1, ymb, zmb, wm1, 1);

    A[0] = zs; B[0] = ym1[0]; C[0] = BR0; al[0] = 1.f;
    phase_gemm(1, A, B, C, al, 0.f, 0, -1);
    gridsync();
    A[0] = BR0; B[0] = zs; C[0] = BT0; al[0] = sqrtf(cm) / cc;
    phase_gemm(1, A, B, C, al, 0.f, 1, -1);
}

// ---------------- pre-kernels ----------------
__global__ void colsum1_k(const float* __restrict__ content,
                          const float* __restrict__ style) {
    int cta = blockIdx.x, t = threadIdx.x;
    const float* x = (cta < 256) ? content : style;
    const float* base = x + (size_t)(cta & 255) * 256 * D;
    float s0 = 0.f, s1 = 0.f;
    for (int r = 0; r < 256; r++) {
        s0 += base[(size_t)r * D + t];
        s1 += base[(size_t)r * D + t + 256];
    }
    g_meanpart[cta][t] = s0;
    g_meanpart[cta][t + 256] = s1;
}

__global__ void colsum2_k() {
    int t = threadIdx.x;
    float sc = 0.f, ss = 0.f;
    for (int i = 0; i < 256; i++) {
        sc += g_meanpart[i][t];
        ss += g_meanpart[256 + i][t];
    }
    sc *= (1.0f / NROWS);
    ss *= (1.0f / NROWS);
    g_mean[0][t] = sc;
    g_mean[1][t] = ss;
    g_mean[2][t] = 0.5f * (sc + ss);
}

__global__ __launch_bounds__(256) void center_k(const float* __restrict__ content,
                                                const float* __restrict__ style) {
    int which = blockIdx.y;
    const float* x = which ? style : content;
    __nv_bfloat16* XH = which ? g_xsh : g_xch;
    __nv_bfloat16* XL = which ? g_xsl : g_xcl;
    size_t i = (size_t)blockIdx.x * 256 + threadIdx.x;   // float4 index
    float4 v = *((const float4*)x + i);
    int col = (int)((i * 4) & 511);
    float4 mu = *(const float4*)&g_mean[which][col];
    unsigned h0, l0, h1, l1;
    split2(v.x - mu.x, v.y - mu.y, h0, l0);
    split2(v.z - mu.z, v.w - mu.w, h1, l1);
    *(unsigned*)&XH[i * 4]     = h0;
    *(unsigned*)&XH[i * 4 + 2] = h1;
    *(unsigned*)&XL[i * 4]     = l0;
    *(unsigned*)&XL[i * 4 + 2] = l1;
}

// ---------------- Xc^T Xc partials (K-major, trans ldmatrix) ------------
__global__ __launch_bounds__(256) void xtx_k() {
    if (blockIdx.y > blockIdx.x) return;
    extern __shared__ unsigned short sm_u[];
    unsigned short* buf0 = sm_u;
    unsigned short* buf1 = sm_u + BUFHW;
    float* Cs = (float*)sm_u;
    int z = blockIdx.z;
    const __nv_bfloat16* XH = (z < 32) ? g_xch : g_xsh;
    const __nv_bfloat16* XL = (z < 32) ? g_xcl : g_xsl;
    int tid = threadIdx.x, wid = tid >> 5;
    int wm = (wid >> 2) * 32, wn = (wid & 3) * 16;
    int m0 = blockIdx.y * 64, n0 = blockIdx.x * 64;
    size_t r0 = (size_t)(z & 31) * CHUNK;
    const int NCH = CHUNK / KC;   // 32
    float c[2][2][4] = {};
    stage_hl(buf0, XH, XL, XH, XL, r0, m0, r0, n0);
    cpa_commit();
    #pragma unroll 1
    for (int kc = 0; kc < NCH; kc++) {
        unsigned short* cur = (kc & 1) ? buf1 : buf0;
        unsigned short* nxt = (kc & 1) ? buf0 : buf1;
        if (kc < NCH - 1) {
            stage_hl(nxt, XH, XL, XH, XL,
                     r0 + (kc + 1) * KC, m0, r0 + (kc + 1) * KC, n0);
            cpa_commit();
            cpa_wait<1>();
        } else {
            cpa_wait<0>();
        }
        __syncthreads();
        mma_planes(c, cur, wm, wn, 1);
        __syncthreads();
    }
    frags_to_Cs(c, Cs, wm, wn);
    __syncthreads();
    float* Cp = g_covpart[z];
    int r = tid >> 2;
    #pragma unroll
    for (int q = 0; q < 4; q++) {
        int cc = (tid & 3) * 4 + q * 16;
        float4 v = *(float4*)&Cs[r * PC + cc];
        *(float4*)&Cp[(m0 + r) * D + n0 + cc] = v;
    }
}

__global__ void covfin_k() {
    int gidx = blockIdx.x * 256 + threadIdx.x;
    int which = gidx >= MATN;
    int idx = gidx & (MATN - 1);
    int base = which ? 32 : 0;
    int cov = which ? COVS : COVC;
    int m = idx >> 9, n = idx & 511;
    int ms = m, ns = n;
    if ((m >> 6) > (n >> 6)) { ms = n; ns = m; }
    float s = 0.f;
    #pragma unroll 8
    for (int p = 0; p < SPLITS; p++) s += g_covpart[base + p][ms * D + ns];
    float v = s * (1.0f / (NROWS - 1));
    g_mat[cov][idx] = v;
    unsigned short h, l;
    split1(v, h, l);
    *(unsigned short*)&g_h[cov][idx] = h;
    *(unsigned short*)&g_l[cov][idx] = l;
}

// ---------------- output GEMM: out = Xc @ M + mu_b  (M symmetric) -------
__global__ __launch_bounds__(256) void outgemm_k(float* __restrict__ out) {
    extern __shared__ unsigned short sm_u[];
    unsigned short* buf0 = sm_u;
    unsigned short* buf1 = sm_u + BUFHW;
    float* Cs = (float*)sm_u;
    int tid = threadIdx.x, wid = tid >> 5;
    int wm = (wid >> 2) * 32, wn = (wid & 3) * 16;
    size_t m0 = (size_t)blockIdx.y * 64;
    int n0 = blockIdx.x * 64;
    float c[2][2][4] = {};
    stage_hl(buf0, g_xch, g_xcl, g_h[BT0], g_l[BT0], m0, 0, (size_t)n0, 0);
    cpa_commit();
    #pragma unroll 1
    for (int kc = 0; kc < 8; kc++) {
        unsigned short* cur = (kc & 1) ? buf1 : buf0;
        unsigned short* nxt = (kc & 1) ? buf0 : buf1;
        if (kc < 7) {
            stage_hl(nxt, g_xch, g_xcl, g_h[BT0], g_l[BT0],
                     m0, (kc + 1) * KC, (size_t)n0, (kc + 1) * KC);
            cpa_commit();
            cpa_wait<1>();
        } else {
            cpa_wait<0>();
        }
        __syncthreads();
        mma_planes(c, cur, wm, wn, 0);
        __syncthreads();
    }
    frags_to_Cs(c, Cs, wm, wn);
    __syncthreads();
    int r = tid >> 2;
    #pragma unroll
    for (int q = 0; q < 4; q++) {
        int cc = (tid & 3) * 4 + q * 16;
        float4 v = *(float4*)&Cs[r * PC + cc];
        float4 mb = *(const float4*)&g_mean[2][n0 + cc];
        v.x += mb.x; v.y += mb.y; v.z += mb.z; v.w += mb.w;
        *(float4*)&out[(m0 + (size_t)r) * D + n0 + cc] = v;
    }
}

// ---------------- host orchestration (7 graph nodes) ----------------
extern "C" void kernel_launch(void* const* d_in, const int* in_sizes, int n_in,
                              void* d_out, int out_size) {
    const float* content = (const float*)d_in[0];
    const float* style   = (const float*)d_in[1];
    float* out = (float*)d_out;

    cudaFuncSetAttribute(persist_k, cudaFuncAttributeMaxDynamicSharedMemorySize, SMEM_DYN);
    cudaFuncSetAttribute(xtx_k, cudaFuncAttributeMaxDynamicSharedMemorySize, SMEM_DYN);
    cudaFuncSetAttribute(outgemm_k, cudaFuncAttributeMaxDynamicSharedMemorySize, SMEM_DYN);

    colsum1_k<<<512, 256>>>(content, style);                       // 0
    colsum2_k<<<1, D>>>();                                         // 1
    center_k<<<dim3(NROWS * D / 4 / 256, 2), 256>>>(content, style); // 2
    xtx_k<<<dim3(8, 8, 64), 256, SMEM_DYN>>>();                    // 3
    covfin_k<<<2 * MATN / 256, 256>>>();                           // 4
    persist_k<<<NCTA, 256, SMEM_DYN>>>();                          // 5  <- ncu -s 5
    outgemm_k<<<dim3(8, 1024), 256, SMEM_DYN>>>(out);              // 6

    (void)in_sizes; (void)n_in; (void)out_size;
}

// round 7
// speedup vs baseline: 11.7253x; 1.1502x over previous
#include <cuda_runtime.h>
#include <cuda_bf16.h>
#include <math.h>

#define D 512
#define NROWS 65536
#define MATN (D*D)
#define NS_REST 2            // total NS iterations = 1 (analytic) + NS_REST
#define BARY_ITERS 8
#define SPLITS 32
#define CHUNK (NROWS/SPLITS)
#define NCTA 148
#define KC 64
#define PK 72
#define PC 68
#define PLANE (64*PK)
#define BUFHW (4*PLANE)
#define SMEM_DYN (2*BUFHW*2)   // 73,728 B

// ---------------- matrix buffer ids ----------------
enum {
  COVC=0, COVS, SIGB, BYA, BZA, BYB, BZB, BW0,
  BP0, BP1, BM0, BM1,
  YJ0A, YJ1A, ZJ0A, ZJ1A, YJ0B, YJ1B, ZJ0B, ZJ1B, WJ0, WJ1,
  BR0, BT0, NBUF
};

__device__ float g_mat[NBUF][MATN];
__device__ __nv_bfloat16 g_h[NBUF][MATN];
__device__ __nv_bfloat16 g_l[NBUF][MATN];
__device__ float g_covpart[2*SPLITS][MATN];
__device__ float g_meanpart[512][D];
__device__ float g_mean[3][D];
__device__ float g_tr[5][8];     // trace partials: 0=Sigma, 1=M0, 2=M1, 4=COVC
__device__ __nv_bfloat16 g_xch[(size_t)NROWS * D];
__device__ __nv_bfloat16 g_xcl[(size_t)NROWS * D];
__device__ __nv_bfloat16 g_xsh[(size_t)NROWS * D];
__device__ __nv_bfloat16 g_xsl[(size_t)NROWS * D];

// ---------------- grid-wide barrier (low-contention) ----------------
__device__ unsigned g_bar_cnt;
__device__ unsigned g_bar_gen;

__device__ __forceinline__ unsigned ldcg_u32(const unsigned* p) {
    unsigned v;
    asm volatile("ld.global.cg.u32 %0, [%1];" : "=r"(v) : "l"(p) : "memory");
    return v;
}

__device__ __forceinline__ void gridsync() {
    __syncthreads();
    if (threadIdx.x == 0) {
        __threadfence();
        unsigned gen = ldcg_u32(&g_bar_gen);
        if (atomicAdd(&g_bar_cnt, 1u) == NCTA - 1u) {
            g_bar_cnt = 0u;
            __threadfence();
            atomicExch(&g_bar_gen, gen + 1u);
        } else {
            unsigned ns = 64;
            while (ldcg_u32(&g_bar_gen) == gen) {
                __nanosleep(ns);
                if (ns < 1024) ns <<= 1;
            }
        }
        __threadfence();
    }
    __syncthreads();
}

// ---------------- low-level helpers ----------------
__device__ __forceinline__ unsigned sm32(const void* p) {
    return (unsigned)__cvta_generic_to_shared(p);
}
__device__ __forceinline__ void cpa16(void* dst, const void* src) {
    asm volatile("cp.async.cg.shared.global [%0], [%1], 16;"
                 :: "r"(sm32(dst)), "l"(src));
}
__device__ __forceinline__ void cpa_commit() { asm volatile("cp.async.commit_group;"); }
template <int N>
__device__ __forceinline__ void cpa_wait() {
    asm volatile("cp.async.wait_group %0;" :: "n"(N));
}
__device__ __forceinline__ void ldsm4(unsigned r[4], const unsigned short* p) {
    asm volatile("ldmatrix.sync.aligned.m8n8.x4.shared.b16 {%0,%1,%2,%3}, [%4];"
                 : "=r"(r[0]), "=r"(r[1]), "=r"(r[2]), "=r"(r[3]) : "r"(sm32(p)));
}
__device__ __forceinline__ void ldsm4t(unsigned r[4], const unsigned short* p) {
    asm volatile("ldmatrix.sync.aligned.m8n8.x4.trans.shared.b16 {%0,%1,%2,%3}, [%4];"
                 : "=r"(r[0]), "=r"(r[1]), "=r"(r[2]), "=r"(r[3]) : "r"(sm32(p)));
}
__device__ __forceinline__ void mma16816(float c[4], const unsigned a[4],
                                         unsigned b0, unsigned b1) {
    asm volatile(
        "mma.sync.aligned.m16n8k16.row.col.f32.bf16.bf16.f32 "
        "{%0,%1,%2,%3}, {%4,%5,%6,%7}, {%8,%9}, {%0,%1,%2,%3};\n"
        : "+f"(c[0]), "+f"(c[1]), "+f"(c[2]), "+f"(c[3])
        : "r"(a[0]), "r"(a[1]), "r"(a[2]), "r"(a[3]), "r"(b0), "r"(b1));
}
__device__ __forceinline__ void split2(float x0, float x1, unsigned &h, unsigned &l) {
    __nv_bfloat162 hh = __floats2bfloat162_rn(x0, x1);
    float r0 = x0 - __low2float(hh);
    float r1 = x1 - __high2float(hh);
    __nv_bfloat162 ll = __floats2bfloat162_rn(r0, r1);
    h = *reinterpret_cast<unsigned*>(&hh);
    l = *reinterpret_cast<unsigned*>(&ll);
}
__device__ __forceinline__ void split1(float x, unsigned short &h, unsigned short &l) {
    __nv_bfloat16 hb = __float2bfloat16_rn(x);
    float r = x - __bfloat162float(hb);
    __nv_bfloat16 lb = __float2bfloat16_rn(r);
    h = *reinterpret_cast<unsigned short*>(&hb);
    l = *reinterpret_cast<unsigned short*>(&lb);
}

__device__ __forceinline__ float get_c(int slot) {
    float s = 0.f;
    #pragma unroll
    for (int i = 0; i < 8; i++) s += __ldcg(&g_tr[slot][i]);
    return s * (1.0f / 512.0f);   // c = mean eigenvalue: spectrum/c in ~[0.8,1.2]
}

// ---------------- staging ----------------
__device__ __forceinline__ void stage_hl(unsigned short* sbuf,
    const __nv_bfloat16* AH, const __nv_bfloat16* AL,
    const __nv_bfloat16* BH, const __nv_bfloat16* BL,
    size_t aR, int aC, size_t bR, int bC)
{
    int t = threadIdx.x;
    int plane = t >> 6, row = t & 63;
    const __nv_bfloat16* base = (plane == 0) ? AH : (plane == 1) ? AL
                               : (plane == 2) ? BH : BL;
    size_t r = ((plane < 2) ? aR : bR) + row;
    int c0 = (plane < 2) ? aC : bC;
    const __nv_bfloat16* src = base + r * D + c0;
    unsigned short* dst = sbuf + plane * PLANE + row * PK;
    #pragma unroll
    for (int i = 0; i < 8; i++) cpa16(dst + i * 8, src + i * 8);
}

// ---------------- mma over one staged chunk ----------------
__device__ __forceinline__ void mma_planes(float c[2][2][4],
                                           const unsigned short* sbuf,
                                           int wm, int wn, int trans) {
    const unsigned short* Ah = sbuf;
    const unsigned short* Al = sbuf + PLANE;
    const unsigned short* Bh = sbuf + 2 * PLANE;
    const unsigned short* Bl = sbuf + 3 * PLANE;
    int l = threadIdx.x & 31;
    #pragma unroll
    for (int kb = 0; kb < KC; kb += 16) {
        unsigned ah0[4], ah1[4], al0[4], al1[4], bh[4], bl[4];
        if (!trans) {
            int ar = (l & 7) + ((l & 8) ? 8 : 0);
            int ac = kb + ((l & 16) ? 8 : 0);
            ldsm4(ah0, Ah + (wm + ar) * PK + ac);
            ldsm4(ah1, Ah + (wm + 16 + ar) * PK + ac);
            ldsm4(al0, Al + (wm + ar) * PK + ac);
            ldsm4(al1, Al + (wm + 16 + ar) * PK + ac);
            int br = wn + (l & 7) + ((l & 16) ? 8 : 0);
            int bc = kb + ((l & 8) ? 8 : 0);
            ldsm4(bh, Bh + br * PK + bc);
            ldsm4(bl, Bl + br * PK + bc);
        } else {
            int tr = kb + (l & 7) + ((l & 16) ? 8 : 0);
            int ac = wm + ((l & 8) ? 8 : 0);
            ldsm4t(ah0, Ah + tr * PK + ac);
            ldsm4t(ah1, Ah + tr * PK + ac + 16);
            ldsm4t(al0, Al + tr * PK + ac);
            ldsm4t(al1, Al + tr * PK + ac + 16);
            int br = kb + (l & 7) + ((l & 8) ? 8 : 0);
            int bc = wn + ((l & 16) ? 8 : 0);
            ldsm4t(bh, Bh + br * PK + bc);
            ldsm4t(bl, Bl + br * PK + bc);
        }
        mma16816(c[0][0], ah0, bh[0], bh[1]);
        mma16816(c[0][1], ah0, bh[2], bh[3]);
        mma16816(c[1][0], ah1, bh[0], bh[1]);
        mma16816(c[1][1], ah1, bh[2], bh[3]);
        mma16816(c[0][0], ah0, bl[0], bl[1]);
        mma16816(c[0][1], ah0, bl[2], bl[3]);
        mma16816(c[1][0], ah1, bl[0], bl[1]);
        mma16816(c[1][1], ah1, bl[2], bl[3]);
        mma16816(c[0][0], al0, bh[0], bh[1]);
        mma16816(c[0][1], al0, bh[2], bh[3]);
        mma16816(c[1][0], al1, bh[0], bh[1]);
        mma16816(c[1][1], al1, bh[2], bh[3]);
    }
}

__device__ __forceinline__ void frags_to_Cs(float c[2][2][4], float* Cs, int wm, int wn) {
    int l = threadIdx.x & 31;
    int rr = l >> 2, cc2 = (l & 3) * 2;
    #pragma unroll
    for (int mf = 0; mf < 2; mf++)
        #pragma unroll
        for (int nf = 0; nf < 2; nf++) {
            int r = wm + mf * 16 + rr, cc = wn + nf * 8 + cc2;
            *(float2*)&Cs[r * PC + cc]       = make_float2(c[mf][nf][0], c[mf][nf][1]);
            *(float2*)&Cs[(r + 8) * PC + cc] = make_float2(c[mf][nf][2], c[mf][nf][3]);
        }
}

// full K=512 pipelined mma into Cs
__device__ __forceinline__ void run_tile(float c[2][2][4],
    const __nv_bfloat16* AH, const __nv_bfloat16* AL,
    const __nv_bfloat16* BH, const __nv_bfloat16* BL,
    int m0, int n0, unsigned short* sm_u)
{
    unsigned short* buf0 = sm_u;
    unsigned short* buf1 = sm_u + BUFHW;
    int wid = threadIdx.x >> 5;
    int wm = (wid >> 2) * 32, wn = (wid & 3) * 16;
    stage_hl(buf0, AH, AL, BH, BL, (size_t)m0, 0, (size_t)n0, 0);
    cpa_commit();
    #pragma unroll 1
    for (int kc = 0; kc < 8; kc++) {
        unsigned short* cur = (kc & 1) ? buf1 : buf0;
        unsigned short* nxt = (kc & 1) ? buf0 : buf1;
        if (kc < 7) {
            stage_hl(nxt, AH, AL, BH, BL, (size_t)m0, (kc + 1) * KC,
                     (size_t)n0, (kc + 1) * KC);
            cpa_commit();
            cpa_wait<1>();
        } else {
            cpa_wait<0>();
        }
        __syncthreads();
        mma_planes(c, cur, wm, wn, 0);
        __syncthreads();
    }
    frags_to_Cs(c, (float*)sm_u, wm, wn);
    __syncthreads();
}

// ---------------- generic tile GEMM with h/l + trace epilogue -----------
__device__ __noinline__ void tile_gemm(int Aid, int Bid, int Cid,
                                       int m0, int n0, float alpha, float betaI,
                                       int mirror, int trSlot)
{
    extern __shared__ unsigned short sm_u[];
    float* Cs = (float*)sm_u;
    int tid = threadIdx.x;
    float c[2][2][4] = {};
    run_tile(c, g_h[Aid], g_l[Aid], g_h[Bid], g_l[Bid], m0, n0, sm_u);
    float* C = g_mat[Cid];
    __nv_bfloat16* CH = g_h[Cid];
    __nv_bfloat16* CL = g_l[Cid];
    int r = tid >> 2;
    float dsum = 0.f;
    #pragma unroll
    for (int q = 0; q < 4; q++) {
        int cc = (tid & 3) * 4 + q * 16;
        float4 v = *(float4*)&Cs[r * PC + cc];
        int m = m0 + r, n = n0 + cc;
        float o[4] = {v.x * alpha, v.y * alpha, v.z * alpha, v.w * alpha};
        #pragma unroll
        for (int j = 0; j < 4; j++) {
            if (m == n + j) { o[j] += betaI; dsum += o[j]; }
        }
        *(float4*)&C[(size_t)m * D + n] = make_float4(o[0], o[1], o[2], o[3]);
        unsigned h0, l0, h1, l1;
        split2(o[0], o[1], h0, l0);
        split2(o[2], o[3], h1, l1);
        *(unsigned*)&CH[(size_t)m * D + n]     = h0;
        *(unsigned*)&CH[(size_t)m * D + n + 2] = h1;
        *(unsigned*)&CL[(size_t)m * D + n]     = l0;
        *(unsigned*)&CL[(size_t)m * D + n + 2] = l1;
    }
    if (mirror) {
        // transposed tile read from Cs -> coalesced row writes at (n0.., m0..)
        #pragma unroll
        for (int q = 0; q < 4; q++) {
            int cc = (tid & 3) * 4 + q * 16;
            float o[4];
            #pragma unroll
            for (int j = 0; j < 4; j++)
                o[j] = alpha * Cs[(cc + j) * PC + r];
            int row = n0 + r, col = m0 + cc;
            *(float4*)&C[(size_t)row * D + col] = make_float4(o[0], o[1], o[2], o[3]);
            unsigned h0, l0, h1, l1;
            split2(o[0], o[1], h0, l0);
            split2(o[2], o[3], h1, l1);
            *(unsigned*)&CH[(size_t)row * D + col]     = h0;
            *(unsigned*)&CH[(size_t)row * D + col + 2] = h1;
            *(unsigned*)&CL[(size_t)row * D + col]     = l0;
            *(unsigned*)&CL[(size_t)row * D + col + 2] = l1;
        }
    }
    if (trSlot >= 0) {
        __syncthreads();
        float* red = (float*)sm_u;
        red[tid] = dsum;
        __syncthreads();
        for (int off = 128; off > 0; off >>= 1) {
            if (tid < off) red[tid] += red[tid + off];
            __syncthreads();
        }
        if (tid == 0) g_tr[trSlot][m0 >> 6] = red[0];
    }
}

// ---------------- analytic NS iteration 1: Y1 = 1.5A-0.5A^2, Z1 = 1.5I-0.5A
__device__ __noinline__ void tile_yz1(int Sid, int Yid, int Zid, float cNorm,
                                      int m0, int n0, int mirror)
{
    extern __shared__ unsigned short sm_u[];
    float* Cs = (float*)sm_u;
    int tid = threadIdx.x;
    float c[2][2][4] = {};
    run_tile(c, g_h[Sid], g_l[Sid], g_h[Sid], g_l[Sid], m0, n0, sm_u);
    float ic = 1.0f / cNorm;
    float a1 = 1.5f * ic, a2 = 0.5f * ic * ic, a3 = 0.5f * ic;
    const float* S = g_mat[Sid];
    float* Y = g_mat[Yid]; __nv_bfloat16 *Yh = g_h[Yid], *Yl = g_l[Yid];
    float* Z = g_mat[Zid]; __nv_bfloat16 *Zh = g_h[Zid], *Zl = g_l[Zid];
    int r = tid >> 2;
    #pragma unroll
    for (int q = 0; q < 4; q++) {
        int cc = (tid & 3) * 4 + q * 16;
        int m = m0 + r, n = n0 + cc;
        float4 g = *(float4*)&Cs[r * PC + cc];
        float4 s = __ldcg((const float4*)&S[(size_t)m * D + n]);
        float yv[4] = {s.x * a1 - g.x * a2, s.y * a1 - g.y * a2,
                       s.z * a1 - g.z * a2, s.w * a1 - g.w * a2};
        float sv[4] = {s.x, s.y, s.z, s.w};
        float zv[4];
        #pragma unroll
        for (int j = 0; j < 4; j++)
            zv[j] = ((m == n + j) ? 1.5f : 0.f) - sv[j] * a3;
        *(float4*)&Y[(size_t)m * D + n] = make_float4(yv[0], yv[1], yv[2], yv[3]);
        *(float4*)&Z[(size_t)m * D + n] = make_float4(zv[0], zv[1], zv[2], zv[3]);
        unsigned h0, l0, h1, l1;
        split2(yv[0], yv[1], h0, l0); split2(yv[2], yv[3], h1, l1);
        *(unsigned*)&Yh[(size_t)m * D + n] = h0; *(unsigned*)&Yh[(size_t)m * D + n + 2] = h1;
        *(unsigned*)&Yl[(size_t)m * D + n] = l0; *(unsigned*)&Yl[(size_t)m * D + n + 2] = l1;
        split2(zv[0], zv[1], h0, l0); split2(zv[2], zv[3], h1, l1);
        *(unsigned*)&Zh[(size_t)m * D + n] = h0; *(unsigned*)&Zh[(size_t)m * D + n + 2] = h1;
        *(unsigned*)&Zl[(size_t)m * D + n] = l0; *(unsigned*)&Zl[(size_t)m * D + n + 2] = l1;
    }
    if (mirror) {
        // off-diagonal tile: no identity terms. A^2 symmetric -> Cs transposed.
        #pragma unroll
        for (int q = 0; q < 4; q++) {
            int cc = (tid & 3) * 4 + q * 16;
            int row = n0 + r, col = m0 + cc;
            float4 s = __ldcg((const float4*)&S[(size_t)row * D + col]);
            float g0 = Cs[(cc + 0) * PC + r], g1 = Cs[(cc + 1) * PC + r];
            float g2 = Cs[(cc + 2) * PC + r], g3 = Cs[(cc + 3) * PC + r];
            float yv[4] = {s.x * a1 - g0 * a2, s.y * a1 - g1 * a2,
                           s.z * a1 - g2 * a2, s.w * a1 - g3 * a2};
            float zv[4] = {-s.x * a3, -s.y * a3, -s.z * a3, -s.w * a3};
            *(float4*)&Y[(size_t)row * D + col] = make_float4(yv[0], yv[1], yv[2], yv[3]);
            *(float4*)&Z[(size_t)row * D + col] = make_float4(zv[0], zv[1], zv[2], zv[3]);
            unsigned h0, l0, h1, l1;
            split2(yv[0], yv[1], h0, l0); split2(yv[2], yv[3], h1, l1);
            *(unsigned*)&Yh[(size_t)row * D + col] = h0; *(unsigned*)&Yh[(size_t)row * D + col + 2] = h1;
            *(unsigned*)&Yl[(size_t)row * D + col] = l0; *(unsigned*)&Yl[(size_t)row * D + col + 2] = l1;
            split2(zv[0], zv[1], h0, l0); split2(zv[2], zv[3], h1, l1);
            *(unsigned*)&Zh[(size_t)row * D + col] = h0; *(unsigned*)&Zh[(size_t)row * D + col + 2] = h1;
            *(unsigned*)&Zl[(size_t)row * D + col] = l0; *(unsigned*)&Zl[(size_t)row * D + col + 2] = l1;
        }
    }
}

// ---------------- phase runners ----------------
__device__ __forceinline__ void sym_decode(int tt, int &mt, int &nt) {
    int m = 0, r = tt;
    while (r >= 8 - m) { r -= 8 - m; m++; }
    mt = m; nt = m + r;
}

__device__ __noinline__ void phase_gemm(int nj, const int* A, const int* B,
                                        const int* Cid, const float* al,
                                        float betaI, int sym, int tr0) {
    int tpj = sym ? 36 : 64;
    int total = nj * tpj;
    for (int t = blockIdx.x; t < total; t += NCTA) {
        int j = t / tpj, tt = t - j * tpj;
        int mt, nt;
        if (sym) sym_decode(tt, mt, nt);
        else { mt = tt >> 3; nt = tt & 7; }
        int trSlot = (tr0 >= 0 && mt == nt) ? tr0 + j : -1;
        tile_gemm(A[j], B[j], Cid[j], mt * 64, nt * 64, al[j], betaI,
                  sym && (mt != nt), trSlot);
    }
}

__device__ __noinline__ void phase_yz1(int nb, const int* Sid, const int* Yid,
                                       const int* Zid, const float* cs) {
    int total = nb * 36;
    for (int t = blockIdx.x; t < total; t += NCTA) {
        int j = t / 36, tt = t - j * 36;
        int mt, nt;
        sym_decode(tt, mt, nt);
        tile_yz1(Sid[j], Yid[j], Zid[j], cs[j], mt * 64, nt * 64, mt != nt);
    }
}

// ---------------- small device helpers ----------------
__device__ __noinline__ void trace_prep_covc() {
    __shared__ float red[256];
    int t = threadIdx.x;
    red[t] = __ldcg(&g_mat[COVC][(size_t)t * (D + 1)])
           + __ldcg(&g_mat[COVC][(size_t)(t + 256) * (D + 1)]);
    __syncthreads();
    for (int off = 128; off > 0; off >>= 1) {
        if (t < off) red[t] += red[t + off];
        __syncthreads();
    }
    if (t == 0) {
        g_tr[0][0] = red[0]; g_tr[4][0] = red[0];
        for (int i = 1; i < 8; i++) { g_tr[0][i] = 0.f; g_tr[4][i] = 0.f; }
    }
}

// V = a0*R0 + a1*R1 (fp32 + h/l)
__device__ __forceinline__ void ew_V(int Vid, const float* R0, const float* R1,
                                     float a0, float a1) {
    float* V = g_mat[Vid];
    __nv_bfloat16 *Vh = g_h[Vid], *Vl = g_l[Vid];
    for (int i = blockIdx.x * 256 + threadIdx.x; i < MATN / 2; i += NCTA * 256) {
        int e = 2 * i;
        float v0 = a0 * __ldcg(&R0[e]) + a1 * __ldcg(&R1[e]);
        float v1 = a0 * __ldcg(&R0[e + 1]) + a1 * __ldcg(&R1[e + 1]);
        V[e] = v0; V[e + 1] = v1;
        unsigned h, l;
        split2(v0, v1, h, l);
        *(unsigned*)&Vh[e] = h; *(unsigned*)&Vl[e] = l;
    }
}

// NS iterations 2..: phase1 W=1.5I-0.5ZY; phase2 Y'=YW, Z'=WZ
__device__ __noinline__ void ns_rest(int* y, int* z, int* yb, int* zb,
                                     const int* w, int nb) {
    int A[4], B[4], C[4]; float al[4];
    for (int s = 0; s < NS_REST; s++) {
        for (int j = 0; j < nb; j++) {
            A[j] = z[j]; B[j] = y[j]; C[j] = w[j]; al[j] = -0.5f;
        }
        phase_gemm(nb, A, B, C, al, 1.5f, 1, -1);
        gridsync();
        for (int j = 0; j < nb; j++) {
            A[2*j]   = y[j]; B[2*j]   = w[j]; C[2*j]   = yb[j]; al[2*j]   = 1.f;
            A[2*j+1] = w[j]; B[2*j+1] = z[j]; C[2*j+1] = zb[j]; al[2*j+1] = 1.f;
        }
        phase_gemm(2 * nb, A, B, C, al, 0.f, 1, -1);
        gridsync();
        for (int j = 0; j < nb; j++) {
            int t = y[j]; y[j] = yb[j]; yb[j] = t;
            t = z[j]; z[j] = zb[j]; zb[j] = t;
        }
    }
}

// ---------------- persistent barycenter kernel ----------------
__global__ __launch_bounds__(256, 1) void persist_k() {
    int A[4], B[4], C[4]; float al[4];
    int S2[2], Y2[2], Z2[2]; float cs2[2];

    if (blockIdx.x == 0) trace_prep_covc();
    gridsync();

    for (int it = 0; it < BARY_ITERS; it++) {
        int Sid = (it == 0) ? COVC : SIGB;
        float c = get_c(0);
        S2[0] = Sid; Y2[0] = BYA; Z2[0] = BZA; cs2[0] = c;
        phase_yz1(1, S2, Y2, Z2, cs2);
        gridsync();
        int y1[1] = {BYA}, z1[1] = {BZA}, yb1[1] = {BYB}, zb1[1] = {BZB};
        int w1[1] = {BW0};
        ns_rest(y1, z1, yb1, zb1, w1, 1);
        int ys = y1[0], zs = z1[0];

        // P_j = Y @ cov_j (full)
        A[0] = ys; B[0] = COVC; C[0] = BP0; al[0] = 1.f;
        A[1] = ys; B[1] = COVS; C[1] = BP1; al[1] = 1.f;
        phase_gemm(2, A, B, C, al, 0.f, 0, -1);
        gridsync();
        // M_j = c * (P_j @ Y) (sym, traces -> slots 1,2)
        A[0] = BP0; B[0] = ys; C[0] = BM0; al[0] = c;
        A[1] = BP1; B[1] = ys; C[1] = BM1; al[1] = c;
        phase_gemm(2, A, B, C, al, 0.f, 1, 1);
        gridsync();

        float c0 = get_c(1), c1 = get_c(2);
        S2[0] = BM0; Y2[0] = YJ0A; Z2[0] = ZJ0A; cs2[0] = c0;
        S2[1] = BM1; Y2[1] = YJ1A; Z2[1] = ZJ1A; cs2[1] = c1;
        phase_yz1(2, S2, Y2, Z2, cs2);
        gridsync();
        int y2[2] = {YJ0A, YJ1A}, z2[2] = {ZJ0A, ZJ1A};
        int yb2[2] = {YJ0B, YJ1B}, zb2[2] = {ZJ0B, ZJ1B}, w2[2] = {WJ0, WJ1};
        ns_rest(y2, z2, yb2, zb2, w2, 2);

        // V = 0.5*(sqrt(c0)*Ym0 + sqrt(c1)*Ym1)/c
        ew_V(BW0, g_mat[y2[0]], g_mat[y2[1]],
             0.5f * sqrtf(c0) / c, 0.5f * sqrtf(c1) / c);
        gridsync();
        // R = Z @ V (full)
        A[0] = zs; B[0] = BW0; C[0] = BR0; al[0] = 1.f;
        phase_gemm(1, A, B, C, al, 0.f, 0, -1);
        gridsync();
        // Sigma = R @ Z (sym, trace -> slot 0)
        A[0] = BR0; B[0] = zs; C[0] = SIGB; al[0] = 1.f;
        phase_gemm(1, A, B, C, al, 0.f, 1, 0);
        gridsync();
    }

    // ---- final transform M = Sc^-1/2 (Sc^1/2 Sigma Sc^1/2)^1/2 Sc^-1/2 ----
    float cc = get_c(4);
    S2[0] = COVC; Y2[0] = BYA; Z2[0] = BZA; cs2[0] = cc;
    phase_yz1(1, S2, Y2, Z2, cs2);
    gridsync();
    int y1[1] = {BYA}, z1[1] = {BZA}, yb1[1] = {BYB}, zb1[1] = {BZB};
    int w1[1] = {BW0};
    ns_rest(y1, z1, yb1, zb1, w1, 1);
    int ys = y1[0], zs = z1[0];

    A[0] = ys; B[0] = SIGB; C[0] = BP0; al[0] = 1.f;
    phase_gemm(1, A, B, C, al, 0.f, 0, -1);
    gridsync();
    A[0] = BP0; B[0] = ys; C[0] = BM0; al[0] = cc;
    phase_gemm(1, A, B, C, al, 0.f, 1, 1);
    gridsync();
    float cm = get_c(1);
    S2[0] = BM0; Y2[0] = YJ0A; Z2[0] = ZJ0A; cs2[0] = cm;
    phase_yz1(1, S2, Y2, Z2, cs2);
    gridsync();
    int ym1[1] = {YJ0A}, zm1[1] = {ZJ0A}, ymb[1] = {YJ0B}, zmb[1] = {ZJ0B};
    int wm1[1] = {WJ0};
    ns_rest(ym1, zm1, ymb, zmb, wm1, 1);

    A[0] = zs; B[0] = ym1[0]; C[0] = BR0; al[0] = 1.f;
    phase_gemm(1, A, B, C, al, 0.f, 0, -1);
    gridsync();
    A[0] = BR0; B[0] = zs; C[0] = BT0; al[0] = sqrtf(cm) / cc;
    phase_gemm(1, A, B, C, al, 0.f, 1, -1);
}

// ---------------- pre-kernels ----------------
__global__ void colsum1_k(const float* __restrict__ content,
                          const float* __restrict__ style) {
    int cta = blockIdx.x, t = threadIdx.x;
    const float* x = (cta < 256) ? content : style;
    const float* base = x + (size_t)(cta & 255) * 256 * D;
    float s0 = 0.f, s1 = 0.f;
    for (int r = 0; r < 256; r++) {
        s0 += base[(size_t)r * D + t];
        s1 += base[(size_t)r * D + t + 256];
    }
    g_meanpart[cta][t] = s0;
    g_meanpart[cta][t + 256] = s1;
}

__global__ void colsum2_k() {
    int t = threadIdx.x;
    float sc = 0.f, ss = 0.f;
    for (int i = 0; i < 256; i++) {
        sc += g_meanpart[i][t];
        ss += g_meanpart[256 + i][t];
    }
    sc *= (1.0f / NROWS);
    ss *= (1.0f / NROWS);
    g_mean[0][t] = sc;
    g_mean[1][t] = ss;
    g_mean[2][t] = 0.5f * (sc + ss);
}

__global__ __launch_bounds__(256) void center_k(const float* __restrict__ content,
                                                const float* __restrict__ style) {
    int which = blockIdx.y;
    const float* x = which ? style : content;
    __nv_bfloat16* XH = which ? g_xsh : g_xch;
    __nv_bfloat16* XL = which ? g_xsl : g_xcl;
    size_t i = (size_t)blockIdx.x * 256 + threadIdx.x;
    float4 v = *((const float4*)x + i);
    int col = (int)((i * 4) & 511);
    float4 mu = *(const float4*)&g_mean[which][col];
    unsigned h0, l0, h1, l1;
    split2(v.x - mu.x, v.y - mu.y, h0, l0);
    split2(v.z - mu.z, v.w - mu.w, h1, l1);
    *(unsigned*)&XH[i * 4]     = h0;
    *(unsigned*)&XH[i * 4 + 2] = h1;
    *(unsigned*)&XL[i * 4]     = l0;
    *(unsigned*)&XL[i * 4 + 2] = l1;
}

// ---------------- Xc^T Xc partials (K-major, trans ldmatrix) ------------
__global__ __launch_bounds__(256) void xtx_k() {
    if (blockIdx.y > blockIdx.x) return;
    extern __shared__ unsigned short sm_u[];
    unsigned short* buf0 = sm_u;
    unsigned short* buf1 = sm_u + BUFHW;
    float* Cs = (float*)sm_u;
    int z = blockIdx.z;
    const __nv_bfloat16* XH = (z < 32) ? g_xch : g_xsh;
    const __nv_bfloat16* XL = (z < 32) ? g_xcl : g_xsl;
    int tid = threadIdx.x, wid = tid >> 5;
    int wm = (wid >> 2) * 32, wn = (wid & 3) * 16;
    int m0 = blockIdx.y * 64, n0 = blockIdx.x * 64;
    size_t r0 = (size_t)(z & 31) * CHUNK;
    const int NCH = CHUNK / KC;
    float c[2][2][4] = {};
    stage_hl(buf0, XH, XL, XH, XL, r0, m0, r0, n0);
    cpa_commit();
    #pragma unroll 1
    for (int kc = 0; kc < NCH; kc++) {
        unsigned short* cur = (kc & 1) ? buf1 : buf0;
        unsigned short* nxt = (kc & 1) ? buf0 : buf1;
        if (kc < NCH - 1) {
            stage_hl(nxt, XH, XL, XH, XL,
                     r0 + (kc + 1) * KC, m0, r0 + (kc + 1) * KC, n0);
            cpa_commit();
            cpa_wait<1>();
        } else {
            cpa_wait<0>();
        }
        __syncthreads();
        mma_planes(c, cur, wm, wn, 1);
        __syncthreads();
    }
    frags_to_Cs(c, Cs, wm, wn);
    __syncthreads();
    float* Cp = g_covpart[z];
    int r = tid >> 2;
    #pragma unroll
    for (int q = 0; q < 4; q++) {
        int cc = (tid & 3) * 4 + q * 16;
        float4 v = *(float4*)&Cs[r * PC + cc];
        *(float4*)&Cp[(m0 + r) * D + n0 + cc] = v;
    }
}

__global__ void covfin_k() {
    int gidx = blockIdx.x * 256 + threadIdx.x;
    int which = gidx >= MATN;
    int idx = gidx & (MATN - 1);
    int base = which ? 32 : 0;
    int cov = which ? COVS : COVC;
    int m = idx >> 9, n = idx & 511;
    int ms = m, ns = n;
    if ((m >> 6) > (n >> 6)) { ms = n; ns = m; }
    float s = 0.f;
    #pragma unroll 8
    for (int p = 0; p < SPLITS; p++) s += g_covpart[base + p][ms * D + ns];
    float v = s * (1.0f / (NROWS - 1));
    g_mat[cov][idx] = v;
    unsigned short h, l;
    split1(v, h, l);
    *(unsigned short*)&g_h[cov][idx] = h;
    *(unsigned short*)&g_l[cov][idx] = l;
}

// ---------------- output GEMM: out = Xc @ M + mu_b ----------------------
__global__ __launch_bounds__(256) void outgemm_k(float* __restrict__ out) {
    extern __shared__ unsigned short sm_u[];
    unsigned short* buf0 = sm_u;
    unsigned short* buf1 = sm_u + BUFHW;
    float* Cs = (float*)sm_u;
    int tid = threadIdx.x, wid = tid >> 5;
    int wm = (wid >> 2) * 32, wn = (wid & 3) * 16;
    size_t m0 = (size_t)blockIdx.y * 64;
    int n0 = blockIdx.x * 64;
    float c[2][2][4] = {};
    stage_hl(buf0, g_xch, g_xcl, g_h[BT0], g_l[BT0], m0, 0, (size_t)n0, 0);
    cpa_commit();
    #pragma unroll 1
    for (int kc = 0; kc < 8; kc++) {
        unsigned short* cur = (kc & 1) ? buf1 : buf0;
        unsigned short* nxt = (kc & 1) ? buf0 : buf1;
        if (kc < 7) {
            stage_hl(nxt, g_xch, g_xcl, g_h[BT0], g_l[BT0],
                     m0, (kc + 1) * KC, (size_t)n0, (kc + 1) * KC);
            cpa_commit();
            cpa_wait<1>();
        } else {
            cpa_wait<0>();
        }
        __syncthreads();
        mma_planes(c, cur, wm, wn, 0);
        __syncthreads();
    }
    frags_to_Cs(c, Cs, wm, wn);
    __syncthreads();
    int r = tid >> 2;
    #pragma unroll
    for (int q = 0; q < 4; q++) {
        int cc = (tid & 3) * 4 + q * 16;
        float4 v = *(float4*)&Cs[r * PC + cc];
        float4 mb = *(const float4*)&g_mean[2][n0 + cc];
        v.x += mb.x; v.y += mb.y; v.z += mb.z; v.w += mb.w;
        *(float4*)&out[(m0 + (size_t)r) * D + n0 + cc] = v;
    }
}

// ---------------- host orchestration ----------------
extern "C" void kernel_launch(void* const* d_in, const int* in_sizes, int n_in,
                              void* d_out, int out_size) {
    const float* content = (const float*)d_in[0];
    const float* style   = (const float*)d_in[1];
    float* out = (float*)d_out;

    cudaFuncSetAttribute(persist_k, cudaFuncAttributeMaxDynamicSharedMemorySize, SMEM_DYN);
    cudaFuncSetAttribute(xtx_k, cudaFuncAttributeMaxDynamicSharedMemorySize, SMEM_DYN);
    cudaFuncSetAttribute(outgemm_k, cudaFuncAttributeMaxDynamicSharedMemorySize, SMEM_DYN);

    colsum1_k<<<512, 256>>>(content, style);                         // 0
    colsum2_k<<<1, D>>>();                                           // 1
    center_k<<<dim3(NROWS * D / 4 / 256, 2), 256>>>(content, style); // 2
    xtx_k<<<dim3(8, 8, 64), 256, SMEM_DYN>>>();                      // 3
    covfin_k<<<2 * MATN / 256, 256>>>();                             // 4
    persist_k<<<NCTA, 256, SMEM_DYN>>>();                            // 5
    outgemm_k<<<dim3(8, 1024), 256, SMEM_DYN>>>(out);                // 6

    (void)in_sizes; (void)n_in; (void)out_size;
}

// round 8
// speedup vs baseline: 20.6523x; 1.7613x over previous
#include <cuda_runtime.h>
#include <cuda_bf16.h>
#include <math.h>

#define D 512
#define NROWS 65536
#define MATN (D*D)
#define NS_REST 2            // total NS iterations = 1 (analytic) + NS_REST
#define BARY_ITERS 8
#define SPLITS 32
#define CHUNK (NROWS/SPLITS)
#define NCTA 148
#define KC 64
#define PC 68
#define TILEB 8192           // bytes per 64x64 bf16 tile (swizzled)
#define BUFSZ 32768          // 4 planes x 8KB
#define SMEM_DYN 65536       // two buffers

// ---------------- matrix buffer ids ----------------
enum {
  COVC=0, COVS, SIGB, BYA, BZA, BYB, BZB, BW0,
  BP0, BP1, BM0, BM1,
  YJ0A, YJ1A, ZJ0A, ZJ1A, YJ0B, YJ1B, ZJ0B, ZJ1B, WJ0, WJ1,
  BR0, BT0, NBUF
};

__device__ float g_mat[NBUF][MATN];
// h/l planes stored TILED: tile (m>>6, n>>6) = 8KB contiguous, SW128-swizzled inside
__device__ __nv_bfloat16 g_h[NBUF][MATN];
__device__ __nv_bfloat16 g_l[NBUF][MATN];
__device__ float g_covpart[2*SPLITS][MATN];
__device__ float g_meanpart[512][D];
__device__ float g_mean[3][D];
__device__ float g_tr[5][8];
__device__ __nv_bfloat16 g_xch[(size_t)NROWS * D];   // tiled+swizzled
__device__ __nv_bfloat16 g_xcl[(size_t)NROWS * D];
__device__ __nv_bfloat16 g_xsh[(size_t)NROWS * D];
__device__ __nv_bfloat16 g_xsl[(size_t)NROWS * D];

// ---------------- grid-wide barrier (low-contention) ----------------
__device__ unsigned g_bar_cnt;
__device__ unsigned g_bar_gen;

__device__ __forceinline__ unsigned ldcg_u32(const unsigned* p) {
    unsigned v;
    asm volatile("ld.global.cg.u32 %0, [%1];" : "=r"(v) : "l"(p) : "memory");
    return v;
}

__device__ __forceinline__ void gridsync() {
    __syncthreads();
    if (threadIdx.x == 0) {
        __threadfence();
        unsigned gen = ldcg_u32(&g_bar_gen);
        if (atomicAdd(&g_bar_cnt, 1u) == NCTA - 1u) {
            g_bar_cnt = 0u;
            __threadfence();
            atomicExch(&g_bar_gen, gen + 1u);
        } else {
            unsigned ns = 64;
            while (ldcg_u32(&g_bar_gen) == gen) {
                __nanosleep(ns);
                if (ns < 1024) ns <<= 1;
            }
        }
        __threadfence();
    }
    __syncthreads();
}

// ---------------- low-level helpers ----------------
__device__ __forceinline__ unsigned sm32(const void* p) {
    return (unsigned)__cvta_generic_to_shared(p);
}
__device__ __forceinline__ void mbar_init(unsigned a) {
    asm volatile("mbarrier.init.shared.b64 [%0], 1;" :: "r"(a) : "memory");
}
__device__ __forceinline__ void mbar_expect(unsigned a, unsigned bytes) {
    asm volatile("mbarrier.arrive.expect_tx.shared.b64 _, [%0], %1;"
                 :: "r"(a), "r"(bytes) : "memory");
}
__device__ __forceinline__ void bulk8k(unsigned sdst, const void* gsrc, unsigned mbar) {
    asm volatile("cp.async.bulk.shared::cta.global.mbarrier::complete_tx::bytes "
                 "[%0], [%1], 8192, [%2];"
                 :: "r"(sdst), "l"(gsrc), "r"(mbar) : "memory");
}
__device__ __forceinline__ void mbar_wait(unsigned mbar, unsigned parity) {
    asm volatile(
        "{\n\t.reg .pred P;\n\t"
        "MWL_%=:\n\t"
        "mbarrier.try_wait.parity.acquire.cta.shared::cta.b64 P, [%0], %1;\n\t"
        "@!P bra MWL_%=;\n\t}"
        :: "r"(mbar), "r"(parity) : "memory");
}
__device__ __forceinline__ void ldsm4(unsigned r[4], const unsigned short* p) {
    asm volatile("ldmatrix.sync.aligned.m8n8.x4.shared.b16 {%0,%1,%2,%3}, [%4];"
                 : "=r"(r[0]), "=r"(r[1]), "=r"(r[2]), "=r"(r[3]) : "r"(sm32(p)));
}
__device__ __forceinline__ void ldsm4t(unsigned r[4], const unsigned short* p) {
    asm volatile("ldmatrix.sync.aligned.m8n8.x4.trans.shared.b16 {%0,%1,%2,%3}, [%4];"
                 : "=r"(r[0]), "=r"(r[1]), "=r"(r[2]), "=r"(r[3]) : "r"(sm32(p)));
}
__device__ __forceinline__ void mma16816(float c[4], const unsigned a[4],
                                         unsigned b0, unsigned b1) {
    asm volatile(
        "mma.sync.aligned.m16n8k16.row.col.f32.bf16.bf16.f32 "
        "{%0,%1,%2,%3}, {%4,%5,%6,%7}, {%8,%9}, {%0,%1,%2,%3};\n"
        : "+f"(c[0]), "+f"(c[1]), "+f"(c[2]), "+f"(c[3])
        : "r"(a[0]), "r"(a[1]), "r"(a[2]), "r"(a[3]), "r"(b0), "r"(b1));
}
__device__ __forceinline__ void split2(float x0, float x1, unsigned &h, unsigned &l) {
    __nv_bfloat162 hh = __floats2bfloat162_rn(x0, x1);
    float r0 = x0 - __low2float(hh);
    float r1 = x1 - __high2float(hh);
    __nv_bfloat162 ll = __floats2bfloat162_rn(r0, r1);
    h = *reinterpret_cast<unsigned*>(&hh);
    l = *reinterpret_cast<unsigned*>(&ll);
}
__device__ __forceinline__ void split1(float x, unsigned short &h, unsigned short &l) {
    __nv_bfloat16 hb = __float2bfloat16_rn(x);
    float r = x - __bfloat162float(hb);
    __nv_bfloat16 lb = __float2bfloat16_rn(r);
    h = *reinterpret_cast<unsigned short*>(&hb);
    l = *reinterpret_cast<unsigned short*>(&lb);
}

__device__ __forceinline__ float get_c(int slot) {
    float s = 0.f;
    #pragma unroll
    for (int i = 0; i < 8; i++) s += __ldcg(&g_tr[slot][i]);
    return s * (1.0f / 512.0f);
}

// tiled+swizzled byte offset for element (m, n) in an h/l plane (8 col-tiles)
__device__ __forceinline__ size_t thl_off(int m, int n) {
    unsigned tile = (((unsigned)m >> 6) << 3) + ((unsigned)n >> 6);
    unsigned off = (((unsigned)m & 63u) << 7) | (((unsigned)n & 63u) << 1);
    off ^= (off >> 3) & 0x70;
    return ((size_t)tile << 13) + off;
}

// write 4 consecutive elements (n%4==0) to h/l planes
__device__ __forceinline__ void store_hl(__nv_bfloat16* H, __nv_bfloat16* L,
                                         int m, int n,
                                         float o0, float o1, float o2, float o3) {
    size_t t = thl_off(m, n);
    unsigned h0, l0, h1, l1;
    split2(o0, o1, h0, l0);
    split2(o2, o3, h1, l1);
    *(unsigned*)((char*)H + t)     = h0;
    *(unsigned*)((char*)H + t + 4) = h1;
    *(unsigned*)((char*)L + t)     = l0;
    *(unsigned*)((char*)L + t + 4) = l1;
}

// swizzled smem address inside a staged plane
__device__ __forceinline__ const unsigned short* swp(const char* sbuf, int plane,
                                                     int r, int c) {
    unsigned off = (((unsigned)r) << 7) + (((unsigned)c) << 1);
    off ^= (off >> 3) & 0x70;
    return (const unsigned short*)(sbuf + plane * TILEB + off);
}

// ---------------- pipeline state ----------------
struct Pipe {
    unsigned mb0, mb1;
    unsigned par;       // bit0 = buf0 parity, bit1 = buf1 parity
    char* sm;
};

__device__ __forceinline__ void stage_tiles(Pipe& pp, int buf,
    const __nv_bfloat16* AH, const __nv_bfloat16* AL,
    const __nv_bfloat16* BH, const __nv_bfloat16* BL,
    int aT, int bT)
{
    if (threadIdx.x == 0) {
        unsigned mbar = buf ? pp.mb1 : pp.mb0;
        mbar_expect(mbar, (unsigned)BUFSZ);
        unsigned d = sm32(pp.sm + buf * BUFSZ);
        bulk8k(d,             (const char*)AH + (size_t)aT * TILEB, mbar);
        bulk8k(d + TILEB,     (const char*)AL + (size_t)aT * TILEB, mbar);
        bulk8k(d + 2 * TILEB, (const char*)BH + (size_t)bT * TILEB, mbar);
        bulk8k(d + 3 * TILEB, (const char*)BL + (size_t)bT * TILEB, mbar);
    }
}

// ---------------- mma over one staged chunk ----------------
__device__ __forceinline__ void mma_planes(float c[2][2][4], const char* sbuf,
                                           int wm, int wn, int trans) {
    int l = threadIdx.x & 31;
    #pragma unroll
    for (int kb = 0; kb < KC; kb += 16) {
        unsigned ah0[4], ah1[4], al0[4], al1[4], bh[4], bl[4];
        if (!trans) {
            int ar = (l & 7) + ((l & 8) ? 8 : 0);
            int ac = kb + ((l & 16) ? 8 : 0);
            ldsm4(ah0, swp(sbuf, 0, wm + ar, ac));
            ldsm4(ah1, swp(sbuf, 0, wm + 16 + ar, ac));
            ldsm4(al0, swp(sbuf, 1, wm + ar, ac));
            ldsm4(al1, swp(sbuf, 1, wm + 16 + ar, ac));
            int br = wn + (l & 7) + ((l & 16) ? 8 : 0);
            int bc = kb + ((l & 8) ? 8 : 0);
            ldsm4(bh, swp(sbuf, 2, br, bc));
            ldsm4(bl, swp(sbuf, 3, br, bc));
        } else {
            int tr = kb + (l & 7) + ((l & 16) ? 8 : 0);
            int ac = wm + ((l & 8) ? 8 : 0);
            ldsm4t(ah0, swp(sbuf, 0, tr, ac));
            ldsm4t(ah1, swp(sbuf, 0, tr, ac + 16));
            ldsm4t(al0, swp(sbuf, 1, tr, ac));
            ldsm4t(al1, swp(sbuf, 1, tr, ac + 16));
            int br = kb + (l & 7) + ((l & 8) ? 8 : 0);
            int bc = wn + ((l & 16) ? 8 : 0);
            ldsm4t(bh, swp(sbuf, 2, br, bc));
            ldsm4t(bl, swp(sbuf, 3, br, bc));
        }
        mma16816(c[0][0], ah0, bh[0], bh[1]);
        mma16816(c[0][1], ah0, bh[2], bh[3]);
        mma16816(c[1][0], ah1, bh[0], bh[1]);
        mma16816(c[1][1], ah1, bh[2], bh[3]);
        mma16816(c[0][0], ah0, bl[0], bl[1]);
        mma16816(c[0][1], ah0, bl[2], bl[3]);
        mma16816(c[1][0], ah1, bl[0], bl[1]);
        mma16816(c[1][1], ah1, bl[2], bl[3]);
        mma16816(c[0][0], al0, bh[0], bh[1]);
        mma16816(c[0][1], al0, bh[2], bh[3]);
        mma16816(c[1][0], al1, bh[0], bh[1]);
        mma16816(c[1][1], al1, bh[2], bh[3]);
    }
}

__device__ __forceinline__ void frags_to_Cs(float c[2][2][4], float* Cs, int wm, int wn) {
    int l = threadIdx.x & 31;
    int rr = l >> 2, cc2 = (l & 3) * 2;
    #pragma unroll
    for (int mf = 0; mf < 2; mf++)
        #pragma unroll
        for (int nf = 0; nf < 2; nf++) {
            int r = wm + mf * 16 + rr, cc = wn + nf * 8 + cc2;
            *(float2*)&Cs[r * PC + cc]       = make_float2(c[mf][nf][0], c[mf][nf][1]);
            *(float2*)&Cs[(r + 8) * PC + cc] = make_float2(c[mf][nf][2], c[mf][nf][3]);
        }
}

// pipelined tile: nch chunks of 64, tiles at (aBase + kc*aStr), (bBase + kc*bStr)
__device__ __forceinline__ void run_tile(float c[2][2][4],
    const __nv_bfloat16* AH, const __nv_bfloat16* AL,
    const __nv_bfloat16* BH, const __nv_bfloat16* BL,
    int aBase, int aStr, int bBase, int bStr, int nch, int trans, Pipe& pp)
{
    int wid = threadIdx.x >> 5;
    int wm = (wid >> 2) * 32, wn = (wid & 3) * 16;
    stage_tiles(pp, 0, AH, AL, BH, BL, aBase, bBase);
    #pragma unroll 1
    for (int kc = 0; kc < nch; kc++) {
        int cur = kc & 1;
        if (kc < nch - 1)
            stage_tiles(pp, cur ^ 1, AH, AL, BH, BL,
                        aBase + (kc + 1) * aStr, bBase + (kc + 1) * bStr);
        unsigned mbar = cur ? pp.mb1 : pp.mb0;
        mbar_wait(mbar, (pp.par >> cur) & 1u);
        pp.par ^= 1u << cur;
        mma_planes(c, pp.sm + cur * BUFSZ, wm, wn, trans);
        __syncthreads();
    }
    frags_to_Cs(c, (float*)pp.sm, wm, wn);
    __syncthreads();
}

// ---------------- generic tile GEMM with h/l + trace epilogue -----------
__device__ __noinline__ void tile_gemm(int Aid, int Bid, int Cid,
                                       int m0, int n0, float alpha, float betaI,
                                       int mirror, int trSlot, Pipe& pp)
{
    float* Cs = (float*)pp.sm;
    int tid = threadIdx.x;
    float c[2][2][4] = {};
    run_tile(c, g_h[Aid], g_l[Aid], g_h[Bid], g_l[Bid],
             (m0 >> 6) * 8, 1, (n0 >> 6) * 8, 1, 8, 0, pp);
    float* C = g_mat[Cid];
    __nv_bfloat16* CH = g_h[Cid];
    __nv_bfloat16* CL = g_l[Cid];
    int r = tid >> 2;
    float dsum = 0.f;
    #pragma unroll
    for (int q = 0; q < 4; q++) {
        int cc = (tid & 3) * 4 + q * 16;
        float4 v = *(float4*)&Cs[r * PC + cc];
        int m = m0 + r, n = n0 + cc;
        float o[4] = {v.x * alpha, v.y * alpha, v.z * alpha, v.w * alpha};
        #pragma unroll
        for (int j = 0; j < 4; j++) {
            if (m == n + j) { o[j] += betaI; dsum += o[j]; }
        }
        *(float4*)&C[(size_t)m * D + n] = make_float4(o[0], o[1], o[2], o[3]);
        store_hl(CH, CL, m, n, o[0], o[1], o[2], o[3]);
    }
    if (mirror) {
        #pragma unroll
        for (int q = 0; q < 4; q++) {
            int cc = (tid & 3) * 4 + q * 16;
            float o[4];
            #pragma unroll
            for (int j = 0; j < 4; j++)
                o[j] = alpha * Cs[(cc + j) * PC + r];
            int row = n0 + r, col = m0 + cc;
            *(float4*)&C[(size_t)row * D + col] = make_float4(o[0], o[1], o[2], o[3]);
            store_hl(CH, CL, row, col, o[0], o[1], o[2], o[3]);
        }
    }
    if (trSlot >= 0) {
        __syncthreads();
        float* red = (float*)pp.sm;
        red[tid] = dsum;
        __syncthreads();
        for (int off = 128; off > 0; off >>= 1) {
            if (tid < off) red[tid] += red[tid + off];
            __syncthreads();
        }
        if (tid == 0) g_tr[trSlot][m0 >> 6] = red[0];
    }
    __syncthreads();   // protect Cs before next tile restages buf0
}

// ---------------- analytic NS iteration 1: Y1=1.5A-0.5A^2, Z1=1.5I-0.5A --
__device__ __noinline__ void tile_yz1(int Sid, int Yid, int Zid, float cNorm,
                                      int m0, int n0, int mirror, Pipe& pp)
{
    float* Cs = (float*)pp.sm;
    int tid = threadIdx.x;
    float c[2][2][4] = {};
    run_tile(c, g_h[Sid], g_l[Sid], g_h[Sid], g_l[Sid],
             (m0 >> 6) * 8, 1, (n0 >> 6) * 8, 1, 8, 0, pp);
    float ic = 1.0f / cNorm;
    float a1 = 1.5f * ic, a2 = 0.5f * ic * ic, a3 = 0.5f * ic;
    const float* S = g_mat[Sid];
    float* Y = g_mat[Yid]; __nv_bfloat16 *Yh = g_h[Yid], *Yl = g_l[Yid];
    float* Z = g_mat[Zid]; __nv_bfloat16 *Zh = g_h[Zid], *Zl = g_l[Zid];
    int r = tid >> 2;
    #pragma unroll
    for (int q = 0; q < 4; q++) {
        int cc = (tid & 3) * 4 + q * 16;
        int m = m0 + r, n = n0 + cc;
        float4 g = *(float4*)&Cs[r * PC + cc];
        float4 s = __ldcg((const float4*)&S[(size_t)m * D + n]);
        float yv[4] = {s.x * a1 - g.x * a2, s.y * a1 - g.y * a2,
                       s.z * a1 - g.z * a2, s.w * a1 - g.w * a2};
        float sv[4] = {s.x, s.y, s.z, s.w};
        float zv[4];
        #pragma unroll
        for (int j = 0; j < 4; j++)
            zv[j] = ((m == n + j) ? 1.5f : 0.f) - sv[j] * a3;
        *(float4*)&Y[(size_t)m * D + n] = make_float4(yv[0], yv[1], yv[2], yv[3]);
        *(float4*)&Z[(size_t)m * D + n] = make_float4(zv[0], zv[1], zv[2], zv[3]);
        store_hl(Yh, Yl, m, n, yv[0], yv[1], yv[2], yv[3]);
        store_hl(Zh, Zl, m, n, zv[0], zv[1], zv[2], zv[3]);
    }
    if (mirror) {
        #pragma unroll
        for (int q = 0; q < 4; q++) {
            int cc = (tid & 3) * 4 + q * 16;
            int row = n0 + r, col = m0 + cc;
            float4 s = __ldcg((const float4*)&S[(size_t)row * D + col]);
            float g0 = Cs[(cc + 0) * PC + r], g1 = Cs[(cc + 1) * PC + r];
            float g2 = Cs[(cc + 2) * PC + r], g3 = Cs[(cc + 3) * PC + r];
            float yv[4] = {s.x * a1 - g0 * a2, s.y * a1 - g1 * a2,
                           s.z * a1 - g2 * a2, s.w * a1 - g3 * a2};
            float zv[4] = {-s.x * a3, -s.y * a3, -s.z * a3, -s.w * a3};
            *(float4*)&Y[(size_t)row * D + col] = make_float4(yv[0], yv[1], yv[2], yv[3]);
            *(float4*)&Z[(size_t)row * D + col] = make_float4(zv[0], zv[1], zv[2], zv[3]);
            store_hl(Yh, Yl, row, col, yv[0], yv[1], yv[2], yv[3]);
            store_hl(Zh, Zl, row, col, zv[0], zv[1], zv[2], zv[3]);
        }
    }
    __syncthreads();
}

// ---------------- phase runners ----------------
__device__ __forceinline__ void sym_decode(int tt, int &mt, int &nt) {
    int m = 0, r = tt;
    while (r >= 8 - m) { r -= 8 - m; m++; }
    mt = m; nt = m + r;
}

__device__ __noinline__ void phase_gemm(int nj, const int* A, const int* B,
                                        const int* Cid, const float* al,
                                        float betaI, int sym, int tr0, Pipe& pp) {
    int tpj = sym ? 36 : 64;
    int total = nj * tpj;
    for (int t = blockIdx.x; t < total; t += NCTA) {
        int j = t / tpj, tt = t - j * tpj;
        int mt, nt;
        if (sym) sym_decode(tt, mt, nt);
        else { mt = tt >> 3; nt = tt & 7; }
        int trSlot = (tr0 >= 0 && mt == nt) ? tr0 + j : -1;
        tile_gemm(A[j], B[j], Cid[j], mt * 64, nt * 64, al[j], betaI,
                  sym && (mt != nt), trSlot, pp);
    }
}

__device__ __noinline__ void phase_yz1(int nb, const int* Sid, const int* Yid,
                                       const int* Zid, const float* cs, Pipe& pp) {
    int total = nb * 36;
    for (int t = blockIdx.x; t < total; t += NCTA) {
        int j = t / 36, tt = t - j * 36;
        int mt, nt;
        sym_decode(tt, mt, nt);
        tile_yz1(Sid[j], Yid[j], Zid[j], cs[j], mt * 64, nt * 64, mt != nt, pp);
    }
}

// ---------------- small device helpers ----------------
__device__ __noinline__ void trace_prep_covc() {
    __shared__ float red[256];
    int t = threadIdx.x;
    red[t] = __ldcg(&g_mat[COVC][(size_t)t * (D + 1)])
           + __ldcg(&g_mat[COVC][(size_t)(t + 256) * (D + 1)]);
    __syncthreads();
    for (int off = 128; off > 0; off >>= 1) {
        if (t < off) red[t] += red[t + off];
        __syncthreads();
    }
    if (t == 0) {
        g_tr[0][0] = red[0]; g_tr[4][0] = red[0];
        for (int i = 1; i < 8; i++) { g_tr[0][i] = 0.f; g_tr[4][i] = 0.f; }
    }
}

// V = a0*R0 + a1*R1 (fp32 + tiled h/l)
__device__ __forceinline__ void ew_V(int Vid, const float* R0, const float* R1,
                                     float a0, float a1) {
    float* V = g_mat[Vid];
    __nv_bfloat16 *Vh = g_h[Vid], *Vl = g_l[Vid];
    for (int i = blockIdx.x * 256 + threadIdx.x; i < MATN / 4; i += NCTA * 256) {
        int e = 4 * i;
        float4 r0 = __ldcg((const float4*)&R0[e]);
        float4 r1 = __ldcg((const float4*)&R1[e]);
        float v0 = a0 * r0.x + a1 * r1.x;
        float v1 = a0 * r0.y + a1 * r1.y;
        float v2 = a0 * r0.z + a1 * r1.z;
        float v3 = a0 * r0.w + a1 * r1.w;
        *(float4*)&V[e] = make_float4(v0, v1, v2, v3);
        store_hl(Vh, Vl, e >> 9, e & 511, v0, v1, v2, v3);
    }
}

// NS iterations 2..: phase1 W=1.5I-0.5ZY; phase2 Y'=YW, Z'=WZ
__device__ __noinline__ void ns_rest(int* y, int* z, int* yb, int* zb,
                                     const int* w, int nb, Pipe& pp) {
    int A[4], B[4], C[4]; float al[4];
    for (int s = 0; s < NS_REST; s++) {
        for (int j = 0; j < nb; j++) {
            A[j] = z[j]; B[j] = y[j]; C[j] = w[j]; al[j] = -0.5f;
        }
        phase_gemm(nb, A, B, C, al, 1.5f, 1, -1, pp);
        gridsync();
        for (int j = 0; j < nb; j++) {
            A[2*j]   = y[j]; B[2*j]   = w[j]; C[2*j]   = yb[j]; al[2*j]   = 1.f;
            A[2*j+1] = w[j]; B[2*j+1] = z[j]; C[2*j+1] = zb[j]; al[2*j+1] = 1.f;
        }
        phase_gemm(2 * nb, A, B, C, al, 0.f, 1, -1, pp);
        gridsync();
        for (int j = 0; j < nb; j++) {
            int t = y[j]; y[j] = yb[j]; yb[j] = t;
            t = z[j]; z[j] = zb[j]; zb[j] = t;
        }
    }
}

// ---------------- persistent barycenter kernel ----------------
__global__ __launch_bounds__(256, 1) void persist_k() {
    extern __shared__ char sm_c[];
    __shared__ unsigned long long s_mbar[2];
    Pipe pp;
    pp.mb0 = sm32(&s_mbar[0]); pp.mb1 = sm32(&s_mbar[1]);
    pp.par = 0; pp.sm = sm_c;
    if (threadIdx.x == 0) { mbar_init(pp.mb0); mbar_init(pp.mb1); }
    __syncthreads();

    int A[4], B[4], C[4]; float al[4];
    int S2[2], Y2[2], Z2[2]; float cs2[2];

    if (blockIdx.x == 0) trace_prep_covc();
    gridsync();

    for (int it = 0; it < BARY_ITERS; it++) {
        int Sid = (it == 0) ? COVC : SIGB;
        float c = get_c(0);
        S2[0] = Sid; Y2[0] = BYA; Z2[0] = BZA; cs2[0] = c;
        phase_yz1(1, S2, Y2, Z2, cs2, pp);
        gridsync();
        int y1[1] = {BYA}, z1[1] = {BZA}, yb1[1] = {BYB}, zb1[1] = {BZB};
        int w1[1] = {BW0};
        ns_rest(y1, z1, yb1, zb1, w1, 1, pp);
        int ys = y1[0], zs = z1[0];

        A[0] = ys; B[0] = COVC; C[0] = BP0; al[0] = 1.f;
        A[1] = ys; B[1] = COVS; C[1] = BP1; al[1] = 1.f;
        phase_gemm(2, A, B, C, al, 0.f, 0, -1, pp);
        gridsync();
        A[0] = BP0; B[0] = ys; C[0] = BM0; al[0] = c;
        A[1] = BP1; B[1] = ys; C[1] = BM1; al[1] = c;
        phase_gemm(2, A, B, C, al, 0.f, 1, 1, pp);
        gridsync();

        float c0 = get_c(1), c1 = get_c(2);
        S2[0] = BM0; Y2[0] = YJ0A; Z2[0] = ZJ0A; cs2[0] = c0;
        S2[1] = BM1; Y2[1] = YJ1A; Z2[1] = ZJ1A; cs2[1] = c1;
        phase_yz1(2, S2, Y2, Z2, cs2, pp);
        gridsync();
        int y2[2] = {YJ0A, YJ1A}, z2[2] = {ZJ0A, ZJ1A};
        int yb2[2] = {YJ0B, YJ1B}, zb2[2] = {ZJ0B, ZJ1B}, w2[2] = {WJ0, WJ1};
        ns_rest(y2, z2, yb2, zb2, w2, 2, pp);

        ew_V(BW0, g_mat[y2[0]], g_mat[y2[1]],
             0.5f * sqrtf(c0) / c, 0.5f * sqrtf(c1) / c);
        gridsync();
        A[0] = zs; B[0] = BW0; C[0] = BR0; al[0] = 1.f;
        phase_gemm(1, A, B, C, al, 0.f, 0, -1, pp);
        gridsync();
        A[0] = BR0; B[0] = zs; C[0] = SIGB; al[0] = 1.f;
        phase_gemm(1, A, B, C, al, 0.f, 1, 0, pp);
        gridsync();
    }

    // ---- final transform M = Sc^-1/2 (Sc^1/2 Sigma Sc^1/2)^1/2 Sc^-1/2 ----
    float cc = get_c(4);
    S2[0] = COVC; Y2[0] = BYA; Z2[0] = BZA; cs2[0] = cc;
    phase_yz1(1, S2, Y2, Z2, cs2, pp);
    gridsync();
    int y1[1] = {BYA}, z1[1] = {BZA}, yb1[1] = {BYB}, zb1[1] = {BZB};
    int w1[1] = {BW0};
    ns_rest(y1, z1, yb1, zb1, w1, 1, pp);
    int ys = y1[0], zs = z1[0];

    A[0] = ys; B[0] = SIGB; C[0] = BP0; al[0] = 1.f;
    phase_gemm(1, A, B, C, al, 0.f, 0, -1, pp);
    gridsync();
    A[0] = BP0; B[0] = ys; C[0] = BM0; al[0] = cc;
    phase_gemm(1, A, B, C, al, 0.f, 1, 1, pp);
    gridsync();
    float cm = get_c(1);
    S2[0] = BM0; Y2[0] = YJ0A; Z2[0] = ZJ0A; cs2[0] = cm;
    phase_yz1(1, S2, Y2, Z2, cs2, pp);
    gridsync();
    int ym1[1] = {YJ0A}, zm1[1] = {ZJ0A}, ymb[1] = {YJ0B}, zmb[1] = {ZJ0B};
    int wm1[1] = {WJ0};
    ns_rest(ym1, zm1, ymb, zmb, wm1, 1, pp);

    A[0] = zs; B[0] = ym1[0]; C[0] = BR0; al[0] = 1.f;
    phase_gemm(1, A, B, C, al, 0.f, 0, -1, pp);
    gridsync();
    A[0] = BR0; B[0] = zs; C[0] = BT0; al[0] = sqrtf(cm) / cc;
    phase_gemm(1, A, B, C, al, 0.f, 1, -1, pp);
}

// ---------------- pre-kernels ----------------
__global__ void colsum1_k(const float* __restrict__ content,
                          const float* __restrict__ style) {
    int cta = blockIdx.x, t = threadIdx.x;
    const float* x = (cta < 256) ? content : style;
    const float* base = x + (size_t)(cta & 255) * 256 * D;
    float s0 = 0.f, s1 = 0.f;
    for (int r = 0; r < 256; r++) {
        s0 += base[(size_t)r * D + t];
        s1 += base[(size_t)r * D + t + 256];
    }
    g_meanpart[cta][t] = s0;
    g_meanpart[cta][t + 256] = s1;
}

__global__ void colsum2_k() {
    int t = threadIdx.x;
    float sc = 0.f, ss = 0.f;
    for (int i = 0; i < 256; i++) {
        sc += g_meanpart[i][t];
        ss += g_meanpart[256 + i][t];
    }
    sc *= (1.0f / NROWS);
    ss *= (1.0f / NROWS);
    g_mean[0][t] = sc;
    g_mean[1][t] = ss;
    g_mean[2][t] = 0.5f * (sc + ss);
}

__global__ __launch_bounds__(256) void center_k(const float* __restrict__ content,
                                                const float* __restrict__ style) {
    int which = blockIdx.y;
    const float* x = which ? style : content;
    __nv_bfloat16* XH = which ? g_xsh : g_xch;
    __nv_bfloat16* XL = which ? g_xsl : g_xcl;
    size_t i = (size_t)blockIdx.x * 256 + threadIdx.x;   // float4 index
    float4 v = *((const float4*)x + i);
    int r = (int)(i >> 7);
    int col = (int)((i << 2) & 511);
    float4 mu = *(const float4*)&g_mean[which][col];
    store_hl(XH, XL, r, col, v.x - mu.x, v.y - mu.y, v.z - mu.z, v.w - mu.w);
}

// ---------------- Xc^T Xc partials ----------------
__global__ __launch_bounds__(256) void xtx_k() {
    if (blockIdx.y > blockIdx.x) return;
    extern __shared__ char sm_c[];
    __shared__ unsigned long long s_mbar[2];
    Pipe pp;
    pp.mb0 = sm32(&s_mbar[0]); pp.mb1 = sm32(&s_mbar[1]);
    pp.par = 0; pp.sm = sm_c;
    if (threadIdx.x == 0) { mbar_init(pp.mb0); mbar_init(pp.mb1); }
    __syncthreads();

    float* Cs = (float*)sm_c;
    int z = blockIdx.z;
    const __nv_bfloat16* XH = (z < 32) ? g_xch : g_xsh;
    const __nv_bfloat16* XL = (z < 32) ? g_xcl : g_xsl;
    int tid = threadIdx.x;
    int m0 = blockIdx.y * 64, n0 = blockIdx.x * 64;
    int rb0 = (z & 31) * (CHUNK / 64);      // starting sample-block
    float c[2][2][4] = {};
    run_tile(c, XH, XL, XH, XL,
             rb0 * 8 + (m0 >> 6), 8, rb0 * 8 + (n0 >> 6), 8, CHUNK / 64, 1, pp);
    float* Cp = g_covpart[z];
    int r = tid >> 2;
    #pragma unroll
    for (int q = 0; q < 4; q++) {
        int cc = (tid & 3) * 4 + q * 16;
        float4 v = *(float4*)&Cs[r * PC + cc];
        *(float4*)&Cp[(m0 + r) * D + n0 + cc] = v;
    }
}

__global__ void covfin_k() {
    int gidx = blockIdx.x * 256 + threadIdx.x;
    int which = gidx >= MATN;
    int idx = gidx & (MATN - 1);
    int base = which ? 32 : 0;
    int cov = which ? COVS : COVC;
    int m = idx >> 9, n = idx & 511;
    int ms = m, ns = n;
    if ((m >> 6) > (n >> 6)) { ms = n; ns = m; }
    float s = 0.f;
    #pragma unroll 8
    for (int p = 0; p < SPLITS; p++) s += g_covpart[base + p][ms * D + ns];
    float v = s * (1.0f / (NROWS - 1));
    g_mat[cov][idx] = v;
    unsigned short h, l;
    split1(v, h, l);
    size_t t = thl_off(m, n);
    *(unsigned short*)((char*)g_h[cov] + t) = h;
    *(unsigned short*)((char*)g_l[cov] + t) = l;
}

// ---------------- output GEMM: out = Xc @ M + mu_b ----------------------
__global__ __launch_bounds__(256) void outgemm_k(float* __restrict__ out) {
    extern __shared__ char sm_c[];
    __shared__ unsigned long long s_mbar[2];
    Pipe pp;
    pp.mb0 = sm32(&s_mbar[0]); pp.mb1 = sm32(&s_mbar[1]);
    pp.par = 0; pp.sm = sm_c;
    if (threadIdx.x == 0) { mbar_init(pp.mb0); mbar_init(pp.mb1); }
    __syncthreads();

    float* Cs = (float*)sm_c;
    int tid = threadIdx.x;
    size_t m0 = (size_t)blockIdx.y * 64;
    int n0 = blockIdx.x * 64;
    float c[2][2][4] = {};
    run_tile(c, g_xch, g_xcl, g_h[BT0], g_l[BT0],
             (int)(m0 >> 6) * 8, 1, (n0 >> 6) * 8, 1, 8, 0, pp);
    int r = tid >> 2;
    #pragma unroll
    for (int q = 0; q < 4; q++) {
        int cc = (tid & 3) * 4 + q * 16;
        float4 v = *(float4*)&Cs[r * PC + cc];
        float4 mb = *(const float4*)&g_mean[2][n0 + cc];
        v.x += mb.x; v.y += mb.y; v.z += mb.z; v.w += mb.w;
        *(float4*)&out[(m0 + (size_t)r) * D + n0 + cc] = v;
    }
}

// ---------------- host orchestration ----------------
extern "C" void kernel_launch(void* const* d_in, const int* in_sizes, int n_in,
                              void* d_out, int out_size) {
    const float* content = (const float*)d_in[0];
    const float* style   = (const float*)d_in[1];
    float* out = (float*)d_out;

    cudaFuncSetAttribute(persist_k, cudaFuncAttributeMaxDynamicSharedMemorySize, SMEM_DYN);
    cudaFuncSetAttribute(xtx_k, cudaFuncAttributeMaxDynamicSharedMemorySize, SMEM_DYN);
    cudaFuncSetAttribute(outgemm_k, cudaFuncAttributeMaxDynamicSharedMemorySize, SMEM_DYN);

    colsum1_k<<<512, 256>>>(content, style);                         // 0
    colsum2_k<<<1, D>>>();                                           // 1
    center_k<<<dim3(NROWS * D / 4 / 256, 2), 256>>>(content, style); // 2
    xtx_k<<<dim3(8, 8, 64), 256, SMEM_DYN>>>();                      // 3
    covfin_k<<<2 * MATN / 256, 256>>>();                             // 4
    persist_k<<<NCTA, 256, SMEM_DYN>>>();                            // 5
    outgemm_k<<<dim3(8, 1024), 256, SMEM_DYN>>>(out);                // 6

    (void)in_sizes; (void)n_in; (void)out_size;
}

// round 9
// speedup vs baseline: 25.0474x; 1.2128x over previous
#include <cuda_runtime.h>
#include <cuda_bf16.h>
#include <math.h>

#define D 512
#define NROWS 65536
#define MATN (D*D)
#define NS_REST 2            // total NS iterations = 1 (analytic) + NS_REST
#define BARY_ITERS 6
#define SPLITS 32
#define CHUNK (NROWS/SPLITS)
#define NCTA 148
#define KC 64
#define PC 68
#define TILEB 8192           // bytes per 64x64 bf16 tile (swizzled)
#define BUFSZ 32768          // 4 planes x 8KB
#define SMEM_DYN 65536       // two buffers

// ---------------- matrix buffer ids ----------------
enum {
  COVC=0, COVS, SIGB, BYA, BZA, BYB, BZB, BW0,
  BP0, BP1, BM0, BM1,
  YJ0A, YJ1A, ZJ0A, ZJ1A, YJ0B, YJ1B, ZJ0B, ZJ1B, WJ0, WJ1,
  BR0, BT0, NBUF
};

__device__ float g_mat[NBUF][MATN];
// h/l planes stored TILED: tile (m>>6, n>>6) = 8KB contiguous, SW128-swizzled inside
__device__ __nv_bfloat16 g_h[NBUF][MATN];
__device__ __nv_bfloat16 g_l[NBUF][MATN];
__device__ float g_covpart[2*SPLITS][MATN];
__device__ float g_meanpart[512][D];
__device__ float g_mean[3][D];
__device__ float g_tr[5][8];
__device__ __nv_bfloat16 g_xch[(size_t)NROWS * D];   // tiled+swizzled
__device__ __nv_bfloat16 g_xcl[(size_t)NROWS * D];
__device__ __nv_bfloat16 g_xsh[(size_t)NROWS * D];
__device__ __nv_bfloat16 g_xsl[(size_t)NROWS * D];

// ---------------- grid-wide barrier (low-contention) ----------------
__device__ unsigned g_bar_cnt;
__device__ unsigned g_bar_gen;

__device__ __forceinline__ unsigned ldcg_u32(const unsigned* p) {
    unsigned v;
    asm volatile("ld.global.cg.u32 %0, [%1];" : "=r"(v) : "l"(p) : "memory");
    return v;
}

__device__ __forceinline__ void gridsync() {
    __syncthreads();
    if (threadIdx.x == 0) {
        __threadfence();
        unsigned gen = ldcg_u32(&g_bar_gen);
        if (atomicAdd(&g_bar_cnt, 1u) == NCTA - 1u) {
            g_bar_cnt = 0u;
            __threadfence();
            atomicExch(&g_bar_gen, gen + 1u);
        } else {
            unsigned ns = 32;
            while (ldcg_u32(&g_bar_gen) == gen) {
                __nanosleep(ns);
                if (ns < 256) ns <<= 1;
            }
        }
        __threadfence();
    }
    __syncthreads();
}

// ---------------- low-level helpers ----------------
__device__ __forceinline__ unsigned sm32(const void* p) {
    return (unsigned)__cvta_generic_to_shared(p);
}
__device__ __forceinline__ void mbar_init(unsigned a) {
    asm volatile("mbarrier.init.shared.b64 [%0], 1;" :: "r"(a) : "memory");
}
__device__ __forceinline__ void mbar_expect(unsigned a, unsigned bytes) {
    asm volatile("mbarrier.arrive.expect_tx.shared.b64 _, [%0], %1;"
                 :: "r"(a), "r"(bytes) : "memory");
}
__device__ __forceinline__ void bulk8k(unsigned sdst, const void* gsrc, unsigned mbar) {
    asm volatile("cp.async.bulk.shared::cta.global.mbarrier::complete_tx::bytes "
                 "[%0], [%1], 8192, [%2];"
                 :: "r"(sdst), "l"(gsrc), "r"(mbar) : "memory");
}
__device__ __forceinline__ void mbar_wait(unsigned mbar, unsigned parity) {
    asm volatile(
        "{\n\t.reg .pred P;\n\t"
        "MWL_%=:\n\t"
        "mbarrier.try_wait.parity.acquire.cta.shared::cta.b64 P, [%0], %1;\n\t"
        "@!P bra MWL_%=;\n\t}"
        :: "r"(mbar), "r"(parity) : "memory");
}
__device__ __forceinline__ void ldsm4(unsigned r[4], const unsigned short* p) {
    asm volatile("ldmatrix.sync.aligned.m8n8.x4.shared.b16 {%0,%1,%2,%3}, [%4];"
                 : "=r"(r[0]), "=r"(r[1]), "=r"(r[2]), "=r"(r[3]) : "r"(sm32(p)));
}
__device__ __forceinline__ void ldsm4t(unsigned r[4], const unsigned short* p) {
    asm volatile("ldmatrix.sync.aligned.m8n8.x4.trans.shared.b16 {%0,%1,%2,%3}, [%4];"
                 : "=r"(r[0]), "=r"(r[1]), "=r"(r[2]), "=r"(r[3]) : "r"(sm32(p)));
}
__device__ __forceinline__ void mma16816(float c[4], const unsigned a[4],
                                         unsigned b0, unsigned b1) {
    asm volatile(
        "mma.sync.aligned.m16n8k16.row.col.f32.bf16.bf16.f32 "
        "{%0,%1,%2,%3}, {%4,%5,%6,%7}, {%8,%9}, {%0,%1,%2,%3};\n"
        : "+f"(c[0]), "+f"(c[1]), "+f"(c[2]), "+f"(c[3])
        : "r"(a[0]), "r"(a[1]), "r"(a[2]), "r"(a[3]), "r"(b0), "r"(b1));
}
__device__ __forceinline__ void split2(float x0, float x1, unsigned &h, unsigned &l) {
    __nv_bfloat162 hh = __floats2bfloat162_rn(x0, x1);
    float r0 = x0 - __low2float(hh);
    float r1 = x1 - __high2float(hh);
    __nv_bfloat162 ll = __floats2bfloat162_rn(r0, r1);
    h = *reinterpret_cast<unsigned*>(&hh);
    l = *reinterpret_cast<unsigned*>(&ll);
}
__device__ __forceinline__ void split1(float x, unsigned short &h, unsigned short &l) {
    __nv_bfloat16 hb = __float2bfloat16_rn(x);
    float r = x - __bfloat162float(hb);
    __nv_bfloat16 lb = __float2bfloat16_rn(r);
    h = *reinterpret_cast<unsigned short*>(&hb);
    l = *reinterpret_cast<unsigned short*>(&lb);
}

__device__ __forceinline__ float get_c(int slot) {
    float s = 0.f;
    #pragma unroll
    for (int i = 0; i < 8; i++) s += __ldcg(&g_tr[slot][i]);
    return s * (1.0f / 512.0f);
}

// tiled+swizzled byte offset for element (m, n) in an h/l plane (8 col-tiles)
__device__ __forceinline__ size_t thl_off(int m, int n) {
    unsigned tile = (((unsigned)m >> 6) << 3) + ((unsigned)n >> 6);
    unsigned off = (((unsigned)m & 63u) << 7) | (((unsigned)n & 63u) << 1);
    off ^= (off >> 3) & 0x70;
    return ((size_t)tile << 13) + off;
}

// write 4 consecutive elements (n%4==0) to h/l planes
__device__ __forceinline__ void store_hl(__nv_bfloat16* H, __nv_bfloat16* L,
                                         int m, int n,
                                         float o0, float o1, float o2, float o3) {
    size_t t = thl_off(m, n);
    unsigned h0, l0, h1, l1;
    split2(o0, o1, h0, l0);
    split2(o2, o3, h1, l1);
    *(unsigned*)((char*)H + t)     = h0;
    *(unsigned*)((char*)H + t + 4) = h1;
    *(unsigned*)((char*)L + t)     = l0;
    *(unsigned*)((char*)L + t + 4) = l1;
}

// swizzled smem address inside a staged plane
__device__ __forceinline__ const unsigned short* swp(const char* sbuf, int plane,
                                                     int r, int c) {
    unsigned off = (((unsigned)r) << 7) + (((unsigned)c) << 1);
    off ^= (off >> 3) & 0x70;
    return (const unsigned short*)(sbuf + plane * TILEB + off);
}

// ---------------- pipeline state ----------------
struct Pipe {
    unsigned mb0, mb1;
    unsigned par;       // bit0 = buf0 parity, bit1 = buf1 parity
    char* sm;
};

__device__ __forceinline__ void stage_tiles(Pipe& pp, int buf,
    const __nv_bfloat16* AH, const __nv_bfloat16* AL,
    const __nv_bfloat16* BH, const __nv_bfloat16* BL,
    int aT, int bT)
{
    if (threadIdx.x == 0) {
        unsigned mbar = buf ? pp.mb1 : pp.mb0;
        mbar_expect(mbar, (unsigned)BUFSZ);
        unsigned d = sm32(pp.sm + buf * BUFSZ);
        bulk8k(d,             (const char*)AH + (size_t)aT * TILEB, mbar);
        bulk8k(d + TILEB,     (const char*)AL + (size_t)aT * TILEB, mbar);
        bulk8k(d + 2 * TILEB, (const char*)BH + (size_t)bT * TILEB, mbar);
        bulk8k(d + 3 * TILEB, (const char*)BL + (size_t)bT * TILEB, mbar);
    }
}

// ---------------- mma over one staged chunk ----------------
__device__ __forceinline__ void mma_planes(float c[2][2][4], const char* sbuf,
                                           int wm, int wn, int trans) {
    int l = threadIdx.x & 31;
    #pragma unroll
    for (int kb = 0; kb < KC; kb += 16) {
        unsigned ah0[4], ah1[4], al0[4], al1[4], bh[4], bl[4];
        if (!trans) {
            int ar = (l & 7) + ((l & 8) ? 8 : 0);
            int ac = kb + ((l & 16) ? 8 : 0);
            ldsm4(ah0, swp(sbuf, 0, wm + ar, ac));
            ldsm4(ah1, swp(sbuf, 0, wm + 16 + ar, ac));
            ldsm4(al0, swp(sbuf, 1, wm + ar, ac));
            ldsm4(al1, swp(sbuf, 1, wm + 16 + ar, ac));
            int br = wn + (l & 7) + ((l & 16) ? 8 : 0);
            int bc = kb + ((l & 8) ? 8 : 0);
            ldsm4(bh, swp(sbuf, 2, br, bc));
            ldsm4(bl, swp(sbuf, 3, br, bc));
        } else {
            int tr = kb + (l & 7) + ((l & 16) ? 8 : 0);
            int ac = wm + ((l & 8) ? 8 : 0);
            ldsm4t(ah0, swp(sbuf, 0, tr, ac));
            ldsm4t(ah1, swp(sbuf, 0, tr, ac + 16));
            ldsm4t(al0, swp(sbuf, 1, tr, ac));
            ldsm4t(al1, swp(sbuf, 1, tr, ac + 16));
            int br = kb + (l & 7) + ((l & 8) ? 8 : 0);
            int bc = wn + ((l & 16) ? 8 : 0);
            ldsm4t(bh, swp(sbuf, 2, br, bc));
            ldsm4t(bl, swp(sbuf, 3, br, bc));
        }
        mma16816(c[0][0], ah0, bh[0], bh[1]);
        mma16816(c[0][1], ah0, bh[2], bh[3]);
        mma16816(c[1][0], ah1, bh[0], bh[1]);
        mma16816(c[1][1], ah1, bh[2], bh[3]);
        mma16816(c[0][0], ah0, bl[0], bl[1]);
        mma16816(c[0][1], ah0, bl[2], bl[3]);
        mma16816(c[1][0], ah1, bl[0], bl[1]);
        mma16816(c[1][1], ah1, bl[2], bl[3]);
        mma16816(c[0][0], al0, bh[0], bh[1]);
        mma16816(c[0][1], al0, bh[2], bh[3]);
        mma16816(c[1][0], al1, bh[0], bh[1]);
        mma16816(c[1][1], al1, bh[2], bh[3]);
    }
}

__device__ __forceinline__ void frags_to_Cs(float c[2][2][4], float* Cs, int wm, int wn) {
    int l = threadIdx.x & 31;
    int rr = l >> 2, cc2 = (l & 3) * 2;
    #pragma unroll
    for (int mf = 0; mf < 2; mf++)
        #pragma unroll
        for (int nf = 0; nf < 2; nf++) {
            int r = wm + mf * 16 + rr, cc = wn + nf * 8 + cc2;
            *(float2*)&Cs[r * PC + cc]       = make_float2(c[mf][nf][0], c[mf][nf][1]);
            *(float2*)&Cs[(r + 8) * PC + cc] = make_float2(c[mf][nf][2], c[mf][nf][3]);
        }
}

// pipelined mma accumulation (no Cs writeback)
__device__ __forceinline__ void run_tile_acc(float c[2][2][4],
    const __nv_bfloat16* AH, const __nv_bfloat16* AL,
    const __nv_bfloat16* BH, const __nv_bfloat16* BL,
    int aBase, int aStr, int bBase, int bStr, int nch, int trans, Pipe& pp)
{
    int wid = threadIdx.x >> 5;
    int wm = (wid >> 2) * 32, wn = (wid & 3) * 16;
    stage_tiles(pp, 0, AH, AL, BH, BL, aBase, bBase);
    #pragma unroll 1
    for (int kc = 0; kc < nch; kc++) {
        int cur = kc & 1;
        if (kc < nch - 1)
            stage_tiles(pp, cur ^ 1, AH, AL, BH, BL,
                        aBase + (kc + 1) * aStr, bBase + (kc + 1) * bStr);
        unsigned mbar = cur ? pp.mb1 : pp.mb0;
        mbar_wait(mbar, (pp.par >> cur) & 1u);
        pp.par ^= 1u << cur;
        mma_planes(c, pp.sm + cur * BUFSZ, wm, wn, trans);
        __syncthreads();
    }
}

__device__ __forceinline__ void run_tile(float c[2][2][4],
    const __nv_bfloat16* AH, const __nv_bfloat16* AL,
    const __nv_bfloat16* BH, const __nv_bfloat16* BL,
    int aBase, int aStr, int bBase, int bStr, int nch, int trans, Pipe& pp)
{
    run_tile_acc(c, AH, AL, BH, BL, aBase, aStr, bBase, bStr, nch, trans, pp);
    int wid = threadIdx.x >> 5;
    frags_to_Cs(c, (float*)pp.sm, (wid >> 2) * 32, (wid & 3) * 16);
    __syncthreads();
}

// ---------------- generic tile GEMM with h/l + trace epilogue -----------
__device__ __noinline__ void tile_gemm(int Aid, int Bid, int Cid,
                                       int m0, int n0, float alpha, float betaI,
                                       int mirror, int trSlot, Pipe& pp)
{
    float* Cs = (float*)pp.sm;
    int tid = threadIdx.x;
    float c[2][2][4] = {};
    run_tile(c, g_h[Aid], g_l[Aid], g_h[Bid], g_l[Bid],
             (m0 >> 6) * 8, 1, (n0 >> 6) * 8, 1, 8, 0, pp);
    float* C = g_mat[Cid];
    __nv_bfloat16* CH = g_h[Cid];
    __nv_bfloat16* CL = g_l[Cid];
    int r = tid >> 2;
    float dsum = 0.f;
    #pragma unroll
    for (int q = 0; q < 4; q++) {
        int cc = (tid & 3) * 4 + q * 16;
        float4 v = *(float4*)&Cs[r * PC + cc];
        int m = m0 + r, n = n0 + cc;
        float o[4] = {v.x * alpha, v.y * alpha, v.z * alpha, v.w * alpha};
        #pragma unroll
        for (int j = 0; j < 4; j++) {
            if (m == n + j) { o[j] += betaI; dsum += o[j]; }
        }
        *(float4*)&C[(size_t)m * D + n] = make_float4(o[0], o[1], o[2], o[3]);
        store_hl(CH, CL, m, n, o[0], o[1], o[2], o[3]);
    }
    if (mirror) {
        #pragma unroll
        for (int q = 0; q < 4; q++) {
            int cc = (tid & 3) * 4 + q * 16;
            float o[4];
            #pragma unroll
            for (int j = 0; j < 4; j++)
                o[j] = alpha * Cs[(cc + j) * PC + r];
            int row = n0 + r, col = m0 + cc;
            *(float4*)&C[(size_t)row * D + col] = make_float4(o[0], o[1], o[2], o[3]);
            store_hl(CH, CL, row, col, o[0], o[1], o[2], o[3]);
        }
    }
    if (trSlot >= 0) {
        __syncthreads();
        float* red = (float*)pp.sm;
        red[tid] = dsum;
        __syncthreads();
        for (int off = 128; off > 0; off >>= 1) {
            if (tid < off) red[tid] += red[tid + off];
            __syncthreads();
        }
        if (tid == 0) g_tr[trSlot][m0 >> 6] = red[0];
    }
    __syncthreads();
}

// ---------------- fused V tile: V = a0*(Y0@W0) + a1*(Y1@W1) -------------
__device__ __noinline__ void tile_V(int Y0, int W0, int Y1, int W1,
                                    float a0, float a1, int Vid,
                                    int m0, int n0, int mirror, Pipe& pp)
{
    float* Cs = (float*)pp.sm;
    int tid = threadIdx.x;
    float c[2][2][4] = {};
    run_tile_acc(c, g_h[Y0], g_l[Y0], g_h[W0], g_l[W0],
                 (m0 >> 6) * 8, 1, (n0 >> 6) * 8, 1, 8, 0, pp);
    float r01 = a0 / a1;
    #pragma unroll
    for (int i = 0; i < 2; i++)
        #pragma unroll
        for (int j = 0; j < 2; j++)
            #pragma unroll
            for (int k = 0; k < 4; k++)
                c[i][j][k] *= r01;
    run_tile_acc(c, g_h[Y1], g_l[Y1], g_h[W1], g_l[W1],
                 (m0 >> 6) * 8, 1, (n0 >> 6) * 8, 1, 8, 0, pp);
    int wid = tid >> 5;
    frags_to_Cs(c, Cs, (wid >> 2) * 32, (wid & 3) * 16);
    __syncthreads();
    float* C = g_mat[Vid];
    __nv_bfloat16* CH = g_h[Vid];
    __nv_bfloat16* CL = g_l[Vid];
    int r = tid >> 2;
    #pragma unroll
    for (int q = 0; q < 4; q++) {
        int cc = (tid & 3) * 4 + q * 16;
        float4 v = *(float4*)&Cs[r * PC + cc];
        int m = m0 + r, n = n0 + cc;
        float o[4] = {v.x * a1, v.y * a1, v.z * a1, v.w * a1};
        *(float4*)&C[(size_t)m * D + n] = make_float4(o[0], o[1], o[2], o[3]);
        store_hl(CH, CL, m, n, o[0], o[1], o[2], o[3]);
    }
    if (mirror) {
        #pragma unroll
        for (int q = 0; q < 4; q++) {
            int cc = (tid & 3) * 4 + q * 16;
            float o[4];
            #pragma unroll
            for (int j = 0; j < 4; j++)
                o[j] = a1 * Cs[(cc + j) * PC + r];
            int row = n0 + r, col = m0 + cc;
            *(float4*)&C[(size_t)row * D + col] = make_float4(o[0], o[1], o[2], o[3]);
            store_hl(CH, CL, row, col, o[0], o[1], o[2], o[3]);
        }
    }
    __syncthreads();
}

// ---------------- analytic NS iteration 1: Y1=1.5A-0.5A^2, Z1=1.5I-0.5A --
__device__ __noinline__ void tile_yz1(int Sid, int Yid, int Zid, float cNorm,
                                      int m0, int n0, int mirror, Pipe& pp)
{
    float* Cs = (float*)pp.sm;
    int tid = threadIdx.x;
    float c[2][2][4] = {};
    run_tile(c, g_h[Sid], g_l[Sid], g_h[Sid], g_l[Sid],
             (m0 >> 6) * 8, 1, (n0 >> 6) * 8, 1, 8, 0, pp);
    float ic = 1.0f / cNorm;
    float a1 = 1.5f * ic, a2 = 0.5f * ic * ic, a3 = 0.5f * ic;
    const float* S = g_mat[Sid];
    float* Y = g_mat[Yid]; __nv_bfloat16 *Yh = g_h[Yid], *Yl = g_l[Yid];
    float* Z = g_mat[Zid]; __nv_bfloat16 *Zh = g_h[Zid], *Zl = g_l[Zid];
    int r = tid >> 2;
    #pragma unroll
    for (int q = 0; q < 4; q++) {
        int cc = (tid & 3) * 4 + q * 16;
        int m = m0 + r, n = n0 + cc;
        float4 g = *(float4*)&Cs[r * PC + cc];
        float4 s = __ldcg((const float4*)&S[(size_t)m * D + n]);
        float yv[4] = {s.x * a1 - g.x * a2, s.y * a1 - g.y * a2,
                       s.z * a1 - g.z * a2, s.w * a1 - g.w * a2};
        float sv[4] = {s.x, s.y, s.z, s.w};
        float zv[4];
        #pragma unroll
        for (int j = 0; j < 4; j++)
            zv[j] = ((m == n + j) ? 1.5f : 0.f) - sv[j] * a3;
        *(float4*)&Y[(size_t)m * D + n] = make_float4(yv[0], yv[1], yv[2], yv[3]);
        *(float4*)&Z[(size_t)m * D + n] = make_float4(zv[0], zv[1], zv[2], zv[3]);
        store_hl(Yh, Yl, m, n, yv[0], yv[1], yv[2], yv[3]);
        store_hl(Zh, Zl, m, n, zv[0], zv[1], zv[2], zv[3]);
    }
    if (mirror) {
        #pragma unroll
        for (int q = 0; q < 4; q++) {
            int cc = (tid & 3) * 4 + q * 16;
            int row = n0 + r, col = m0 + cc;
            float4 s = __ldcg((const float4*)&S[(size_t)row * D + col]);
            float g0 = Cs[(cc + 0) * PC + r], g1 = Cs[(cc + 1) * PC + r];
            float g2 = Cs[(cc + 2) * PC + r], g3 = Cs[(cc + 3) * PC + r];
            float yv[4] = {s.x * a1 - g0 * a2, s.y * a1 - g1 * a2,
                           s.z * a1 - g2 * a2, s.w * a1 - g3 * a2};
            float zv[4] = {-s.x * a3, -s.y * a3, -s.z * a3, -s.w * a3};
            *(float4*)&Y[(size_t)row * D + col] = make_float4(yv[0], yv[1], yv[2], yv[3]);
            *(float4*)&Z[(size_t)row * D + col] = make_float4(zv[0], zv[1], zv[2], zv[3]);
            store_hl(Yh, Yl, row, col, yv[0], yv[1], yv[2], yv[3]);
            store_hl(Zh, Zl, row, col, zv[0], zv[1], zv[2], zv[3]);
        }
    }
    __syncthreads();
}

// ---------------- phase runners ----------------
__device__ __forceinline__ void sym_decode(int tt, int &mt, int &nt) {
    int m = 0, r = tt;
    while (r >= 8 - m) { r -= 8 - m; m++; }
    mt = m; nt = m + r;
}

__device__ __noinline__ void phase_gemm(int nj, const int* A, const int* B,
                                        const int* Cid, const float* al,
                                        float betaI, int sym, int tr0, Pipe& pp) {
    int tpj = sym ? 36 : 64;
    int total = nj * tpj;
    for (int t = blockIdx.x; t < total; t += NCTA) {
        int j = t / tpj, tt = t - j * tpj;
        int mt, nt;
        if (sym) sym_decode(tt, mt, nt);
        else { mt = tt >> 3; nt = tt & 7; }
        int trSlot = (tr0 >= 0 && mt == nt) ? tr0 + j : -1;
        tile_gemm(A[j], B[j], Cid[j], mt * 64, nt * 64, al[j], betaI,
                  sym && (mt != nt), trSlot, pp);
    }
}

__device__ __noinline__ void phase_yz1(int nb, const int* Sid, const int* Yid,
                                       const int* Zid, const float* cs, Pipe& pp) {
    int total = nb * 36;
    for (int t = blockIdx.x; t < total; t += NCTA) {
        int j = t / 36, tt = t - j * 36;
        int mt, nt;
        sym_decode(tt, mt, nt);
        tile_yz1(Sid[j], Yid[j], Zid[j], cs[j], mt * 64, nt * 64, mt != nt, pp);
    }
}

__device__ __noinline__ void phase_V(int Y0, int W0, int Y1, int W1,
                                     float a0, float a1, int Vid, Pipe& pp) {
    for (int t = blockIdx.x; t < 36; t += NCTA) {
        int mt, nt;
        sym_decode(t, mt, nt);
        tile_V(Y0, W0, Y1, W1, a0, a1, Vid, mt * 64, nt * 64, mt != nt, pp);
    }
}

// ---------------- small device helpers ----------------
__device__ __noinline__ void trace_prep_covc() {
    __shared__ float red[256];
    int t = threadIdx.x;
    red[t] = __ldcg(&g_mat[COVC][(size_t)t * (D + 1)])
           + __ldcg(&g_mat[COVC][(size_t)(t + 256) * (D + 1)]);
    __syncthreads();
    for (int off = 128; off > 0; off >>= 1) {
        if (t < off) red[t] += red[t + off];
        __syncthreads();
    }
    if (t == 0) {
        g_tr[0][0] = red[0]; g_tr[4][0] = red[0];
        for (int i = 1; i < 8; i++) { g_tr[0][i] = 0.f; g_tr[4][i] = 0.f; }
    }
}

// NS full iterations: phase1 W=1.5I-0.5ZY; phase2 Y'=YW, Z'=WZ
__device__ __noinline__ void ns_rest(int* y, int* z, int* yb, int* zb,
                                     const int* w, int nb, Pipe& pp) {
    int A[4], B[4], C[4]; float al[4];
    for (int s = 0; s < NS_REST; s++) {
        for (int j = 0; j < nb; j++) {
            A[j] = z[j]; B[j] = y[j]; C[j] = w[j]; al[j] = -0.5f;
        }
        phase_gemm(nb, A, B, C, al, 1.5f, 1, -1, pp);
        gridsync();
        for (int j = 0; j < nb; j++) {
            A[2*j]   = y[j]; B[2*j]   = w[j]; C[2*j]   = yb[j]; al[2*j]   = 1.f;
            A[2*j+1] = w[j]; B[2*j+1] = z[j]; C[2*j+1] = zb[j]; al[2*j+1] = 1.f;
        }
        phase_gemm(2 * nb, A, B, C, al, 0.f, 1, -1, pp);
        gridsync();
        for (int j = 0; j < nb; j++) {
            int t = y[j]; y[j] = yb[j]; yb[j] = t;
            t = z[j]; z[j] = zb[j]; zb[j] = t;
        }
    }
}

// ---------------- persistent barycenter kernel ----------------
__global__ __launch_bounds__(256, 1) void persist_k() {
    extern __shared__ char sm_c[];
    __shared__ unsigned long long s_mbar[2];
    Pipe pp;
    pp.mb0 = sm32(&s_mbar[0]); pp.mb1 = sm32(&s_mbar[1]);
    pp.par = 0; pp.sm = sm_c;
    if (threadIdx.x == 0) { mbar_init(pp.mb0); mbar_init(pp.mb1); }
    __syncthreads();

    int A[4], B[4], C[4]; float al[4];
    int S2[2], Y2[2], Z2[2]; float cs2[2];

    if (blockIdx.x == 0) trace_prep_covc();
    gridsync();

    for (int it = 0; it < BARY_ITERS; it++) {
        int Sid = (it == 0) ? COVC : SIGB;
        float c = get_c(0);
        S2[0] = Sid; Y2[0] = BYA; Z2[0] = BZA; cs2[0] = c;
        phase_yz1(1, S2, Y2, Z2, cs2, pp);
        gridsync();
        int y1[1] = {BYA}, z1[1] = {BZA}, yb1[1] = {BYB}, zb1[1] = {BZB};
        int w1[1] = {BW0};
        ns_rest(y1, z1, yb1, zb1, w1, 1, pp);
        int ys = y1[0], zs = z1[0];

        A[0] = ys; B[0] = COVC; C[0] = BP0; al[0] = 1.f;
        A[1] = ys; B[1] = COVS; C[1] = BP1; al[1] = 1.f;
        phase_gemm(2, A, B, C, al, 0.f, 0, -1, pp);
        gridsync();
        A[0] = BP0; B[0] = ys; C[0] = BM0; al[0] = c;
        A[1] = BP1; B[1] = ys; C[1] = BM1; al[1] = c;
        phase_gemm(2, A, B, C, al, 0.f, 1, 1, pp);
        gridsync();

        float c0 = get_c(1), c1 = get_c(2);
        S2[0] = BM0; Y2[0] = YJ0A; Z2[0] = ZJ0A; cs2[0] = c0;
        S2[1] = BM1; Y2[1] = YJ1A; Z2[1] = ZJ1A; cs2[1] = c1;
        phase_yz1(2, S2, Y2, Z2, cs2, pp);
        gridsync();

        // middles NS: full iterations except the last, which fuses V
        int y2[2] = {YJ0A, YJ1A}, z2[2] = {ZJ0A, ZJ1A};
        int yb2[2] = {YJ0B, YJ1B}, zb2[2] = {ZJ0B, ZJ1B};
        for (int s = 0; s < NS_REST; s++) {
            A[0] = z2[0]; B[0] = y2[0]; C[0] = WJ0; al[0] = -0.5f;
            A[1] = z2[1]; B[1] = y2[1]; C[1] = WJ1; al[1] = -0.5f;
            phase_gemm(2, A, B, C, al, 1.5f, 1, -1, pp);
            gridsync();
            if (s < NS_REST - 1) {
                A[0] = y2[0]; B[0] = WJ0; C[0] = yb2[0]; al[0] = 1.f;
                A[1] = WJ0; B[1] = z2[0]; C[1] = zb2[0]; al[1] = 1.f;
                A[2] = y2[1]; B[2] = WJ1; C[2] = yb2[1]; al[2] = 1.f;
                A[3] = WJ1; B[3] = z2[1]; C[3] = zb2[1]; al[3] = 1.f;
                phase_gemm(4, A, B, C, al, 0.f, 1, -1, pp);
                gridsync();
                int t = y2[0]; y2[0] = yb2[0]; yb2[0] = t;
                t = z2[0]; z2[0] = zb2[0]; zb2[0] = t;
                t = y2[1]; y2[1] = yb2[1]; yb2[1] = t;
                t = z2[1]; z2[1] = zb2[1]; zb2[1] = t;
            } else {
                // V = a0*(Y0@W0) + a1*(Y1@W1), a_j = 0.5*sqrt(c_j)/c
                phase_V(y2[0], WJ0, y2[1], WJ1,
                        0.5f * sqrtf(c0) / c, 0.5f * sqrtf(c1) / c, BW0, pp);
                gridsync();
            }
        }

        // R = Z @ V (full)
        A[0] = zs; B[0] = BW0; C[0] = BR0; al[0] = 1.f;
        phase_gemm(1, A, B, C, al, 0.f, 0, -1, pp);
        gridsync();
        // Sigma = R @ Z (sym, trace -> slot 0)
        A[0] = BR0; B[0] = zs; C[0] = SIGB; al[0] = 1.f;
        phase_gemm(1, A, B, C, al, 0.f, 1, 0, pp);
        gridsync();
    }

    // ---- final transform M = Sc^-1/2 (Sc^1/2 Sigma Sc^1/2)^1/2 Sc^-1/2 ----
    float cc = get_c(4);
    S2[0] = COVC; Y2[0] = BYA; Z2[0] = BZA; cs2[0] = cc;
    phase_yz1(1, S2, Y2, Z2, cs2, pp);
    gridsync();
    int y1[1] = {BYA}, z1[1] = {BZA}, yb1[1] = {BYB}, zb1[1] = {BZB};
    int w1[1] = {BW0};
    ns_rest(y1, z1, yb1, zb1, w1, 1, pp);
    int ys = y1[0], zs = z1[0];

    A[0] = ys; B[0] = SIGB; C[0] = BP0; al[0] = 1.f;
    phase_gemm(1, A, B, C, al, 0.f, 0, -1, pp);
    gridsync();
    A[0] = BP0; B[0] = ys; C[0] = BM0; al[0] = cc;
    phase_gemm(1, A, B, C, al, 0.f, 1, 1, pp);
    gridsync();
    float cm = get_c(1);
    S2[0] = BM0; Y2[0] = YJ0A; Z2[0] = ZJ0A; cs2[0] = cm;
    phase_yz1(1, S2, Y2, Z2, cs2, pp);
    gridsync();
    // M-root NS: full iterations except last, which is Y-only
    int ym = YJ0A, zm = ZJ0A, ymb = YJ0B, zmb = ZJ0B;
    for (int s = 0; s < NS_REST; s++) {
        A[0] = zm; B[0] = ym; C[0] = WJ0; al[0] = -0.5f;
        phase_gemm(1, A, B, C, al, 1.5f, 1, -1, pp);
        gridsync();
        if (s < NS_REST - 1) {
            A[0] = ym; B[0] = WJ0; C[0] = ymb; al[0] = 1.f;
            A[1] = WJ0; B[1] = zm; C[1] = zmb; al[1] = 1.f;
            phase_gemm(2, A, B, C, al, 0.f, 1, -1, pp);
            gridsync();
            int t = ym; ym = ymb; ymb = t;
            t = zm; zm = zmb; zmb = t;
        } else {
            A[0] = ym; B[0] = WJ0; C[0] = ymb; al[0] = 1.f;
            phase_gemm(1, A, B, C, al, 0.f, 1, -1, pp);
            gridsync();
            ym = ymb;
        }
    }

    A[0] = zs; B[0] = ym; C[0] = BR0; al[0] = 1.f;
    phase_gemm(1, A, B, C, al, 0.f, 0, -1, pp);
    gridsync();
    A[0] = BR0; B[0] = zs; C[0] = BT0; al[0] = sqrtf(cm) / cc;
    phase_gemm(1, A, B, C, al, 0.f, 1, -1, pp);
}

// ---------------- pre-kernels ----------------
__global__ void colsum1_k(const float* __restrict__ content,
                          const float* __restrict__ style) {
    int cta = blockIdx.x, t = threadIdx.x;
    const float* x = (cta < 256) ? content : style;
    const float* base = x + (size_t)(cta & 255) * 256 * D;
    float s0 = 0.f, s1 = 0.f;
    for (int r = 0; r < 256; r++) {
        s0 += base[(size_t)r * D + t];
        s1 += base[(size_t)r * D + t + 256];
    }
    g_meanpart[cta][t] = s0;
    g_meanpart[cta][t + 256] = s1;
}

__global__ void colsum2_k() {
    int t = threadIdx.x;
    float sc = 0.f, ss = 0.f;
    for (int i = 0; i < 256; i++) {
        sc += g_meanpart[i][t];
        ss += g_meanpart[256 + i][t];
    }
    sc *= (1.0f / NROWS);
    ss *= (1.0f / NROWS);
    g_mean[0][t] = sc;
    g_mean[1][t] = ss;
    g_mean[2][t] = 0.5f * (sc + ss);
}

__global__ __launch_bounds__(256) void center_k(const float* __restrict__ content,
                                                const float* __restrict__ style) {
    int which = blockIdx.y;
    const float* x = which ? style : content;
    __nv_bfloat16* XH = which ? g_xsh : g_xch;
    __nv_bfloat16* XL = which ? g_xsl : g_xcl;
    size_t i = (size_t)blockIdx.x * 256 + threadIdx.x;   // float4 index
    float4 v = *((const float4*)x + i);
    int r = (int)(i >> 7);
    int col = (int)((i << 2) & 511);
    float4 mu = *(const float4*)&g_mean[which][col];
    store_hl(XH, XL, r, col, v.x - mu.x, v.y - mu.y, v.z - mu.z, v.w - mu.w);
}

// ---------------- Xc^T Xc partials ----------------
__global__ __launch_bounds__(256) void xtx_k() {
    if (blockIdx.y > blockIdx.x) return;
    extern __shared__ char sm_c[];
    __shared__ unsigned long long s_mbar[2];
    Pipe pp;
    pp.mb0 = sm32(&s_mbar[0]); pp.mb1 = sm32(&s_mbar[1]);
    pp.par = 0; pp.sm = sm_c;
    if (threadIdx.x == 0) { mbar_init(pp.mb0); mbar_init(pp.mb1); }
    __syncthreads();

    float* Cs = (float*)sm_c;
    int z = blockIdx.z;
    const __nv_bfloat16* XH = (z < 32) ? g_xch : g_xsh;
    const __nv_bfloat16* XL = (z < 32) ? g_xcl : g_xsl;
    int tid = threadIdx.x;
    int m0 = blockIdx.y * 64, n0 = blockIdx.x * 64;
    int rb0 = (z & 31) * (CHUNK / 64);
    float c[2][2][4] = {};
    run_tile(c, XH, XL, XH, XL,
             rb0 * 8 + (m0 >> 6), 8, rb0 * 8 + (n0 >> 6), 8, CHUNK / 64, 1, pp);
    float* Cp = g_covpart[z];
    int r = tid >> 2;
    #pragma unroll
    for (int q = 0; q < 4; q++) {
        int cc = (tid & 3) * 4 + q * 16;
        float4 v = *(float4*)&Cs[r * PC + cc];
        *(float4*)&Cp[(m0 + r) * D + n0 + cc] = v;
    }
}

__global__ void covfin_k() {
    int gidx = blockIdx.x * 256 + threadIdx.x;
    int which = gidx >= MATN;
    int idx = gidx & (MATN - 1);
    int base = which ? 32 : 0;
    int cov = which ? COVS : COVC;
    int m = idx >> 9, n = idx & 511;
    int ms = m, ns = n;
    if ((m >> 6) > (n >> 6)) { ms = n; ns = m; }
    float s = 0.f;
    #pragma unroll 8
    for (int p = 0; p < SPLITS; p++) s += g_covpart[base + p][ms * D + ns];
    float v = s * (1.0f / (NROWS - 1));
    g_mat[cov][idx] = v;
    unsigned short h, l;
    split1(v, h, l);
    size_t t = thl_off(m, n);
    *(unsigned short*)((char*)g_h[cov] + t) = h;
    *(unsigned short*)((char*)g_l[cov] + t) = l;
}

// ---------------- output GEMM: out = Xc @ M + mu_b ----------------------
__global__ __launch_bounds__(256) void outgemm_k(float* __restrict__ out) {
    extern __shared__ char sm_c[];
    __shared__ unsigned long long s_mbar[2];
    Pipe pp;
    pp.mb0 = sm32(&s_mbar[0]); pp.mb1 = sm32(&s_mbar[1]);
    pp.par = 0; pp.sm = sm_c;
    if (threadIdx.x == 0) { mbar_init(pp.mb0); mbar_init(pp.mb1); }
    __syncthreads();

    float* Cs = (float*)sm_c;
    int tid = threadIdx.x;
    size_t m0 = (size_t)blockIdx.y * 64;
    int n0 = blockIdx.x * 64;
    float c[2][2][4] = {};
    run_tile(c, g_xch, g_xcl, g_h[BT0], g_l[BT0],
             (int)(m0 >> 6) * 8, 1, (n0 >> 6) * 8, 1, 8, 0, pp);
    int r = tid >> 2;
    #pragma unroll
    for (int q = 0; q < 4; q++) {
        int cc = (tid & 3) * 4 + q * 16;
        float4 v = *(float4*)&Cs[r * PC + cc];
        float4 mb = *(const float4*)&g_mean[2][n0 + cc];
        v.x += mb.x; v.y += mb.y; v.z += mb.z; v.w += mb.w;
        *(float4*)&out[(m0 + (size_t)r) * D + n0 + cc] = v;
    }
}

// ---------------- host orchestration ----------------
extern "C" void kernel_launch(void* const* d_in, const int* in_sizes, int n_in,
                              void* d_out, int out_size) {
    const float* content = (const float*)d_in[0];
    const float* style   = (const float*)d_in[1];
    float* out = (float*)d_out;

    cudaFuncSetAttribute(persist_k, cudaFuncAttributeMaxDynamicSharedMemorySize, SMEM_DYN);
    cudaFuncSetAttribute(xtx_k, cudaFuncAttributeMaxDynamicSharedMemorySize, SMEM_DYN);
    cudaFuncSetAttribute(outgemm_k, cudaFuncAttributeMaxDynamicSharedMemorySize, SMEM_DYN);

    colsum1_k<<<512, 256>>>(content, style);                         // 0
    colsum2_k<<<1, D>>>();                                           // 1
    center_k<<<dim3(NROWS * D / 4 / 256, 2), 256>>>(content, style); // 2
    xtx_k<<<dim3(8, 8, 64), 256, SMEM_DYN>>>();                      // 3
    covfin_k<<<2 * MATN / 256, 256>>>();                             // 4
    persist_k<<<NCTA, 256, SMEM_DYN>>>();                            // 5
    outgemm_k<<<dim3(8, 1024), 256, SMEM_DYN>>>(out);                // 6

    (void)in_sizes; (void)n_in; (void)out_size;
}